// round 7
// baseline (speedup 1.0000x reference)
#include <cuda_runtime.h>
#include <cuda_fp16.h>
#include <math.h>

#define B_ 16
#define C1_ 256
#define C2_ 256
#define H_ 64
#define W_ 64
#define NH_ 8
#define C_ 128
#define HD_ 16
#define HW_ (H_*W_)
#define TOKENS (B_*HW_)

typedef unsigned int u32;

// -------- static scratch -----------
__device__ __half g_xt16  [(size_t)TOKENS*256];
__device__ __half g_cat16 [(size_t)TOKENS*384];
__device__ float  g_y2f   [(size_t)TOKENS*128];
__device__ __half g_fn16  [(size_t)TOKENS*128];
__device__ __half g_qkv16 [(size_t)TOKENS*384];
__device__ float  g_attnp [(size_t)TOKENS*128];
__device__ __half g_attn16[(size_t)TOKENS*128];
__device__ float  g_f2    [(size_t)TOKENS*128];
__device__ __half g_h116  [(size_t)TOKENS*256];
__device__ __half g_w16[65536+49152+16384+32768+32768+98304];

// ---------------------------------------------------------------------------
__device__ __forceinline__ u32 smem_u32(const void* p) {
    u32 a;
    asm("{ .reg .u64 t; cvta.to.shared.u64 t, %1; cvt.u32.u64 %0, t; }"
        : "=r"(a) : "l"(p));
    return a;
}
__device__ __forceinline__ void mma_fp16(float* c, const u32* a, const u32* b) {
    asm volatile(
        "mma.sync.aligned.m16n8k16.row.col.f32.f16.f16.f32 "
        "{%0,%1,%2,%3}, {%4,%5,%6,%7}, {%8,%9}, {%0,%1,%2,%3};"
        : "+f"(c[0]), "+f"(c[1]), "+f"(c[2]), "+f"(c[3])
        : "r"(a[0]), "r"(a[1]), "r"(a[2]), "r"(a[3]), "r"(b[0]), "r"(b[1]));
}
__device__ __forceinline__ void ldm_x4(u32& r0, u32& r1, u32& r2, u32& r3, u32 a) {
    asm volatile("ldmatrix.sync.aligned.m8n8.x4.shared.b16 {%0,%1,%2,%3}, [%4];"
        : "=r"(r0), "=r"(r1), "=r"(r2), "=r"(r3) : "r"(a));
}
__device__ __forceinline__ void ldm_x4t(u32& r0, u32& r1, u32& r2, u32& r3, u32 a) {
    asm volatile("ldmatrix.sync.aligned.m8n8.x4.trans.shared.b16 {%0,%1,%2,%3}, [%4];"
        : "=r"(r0), "=r"(r1), "=r"(r2), "=r"(r3) : "r"(a));
}
__device__ __forceinline__ void cp16(u32 dst, const void* src) {
    asm volatile("cp.async.cg.shared.global [%0], [%1], 16;" :: "r"(dst), "l"(src));
}

// ---------------------------------------------------------------------------
__global__ void convert_w_all(const float* __restrict__ s0, const float* __restrict__ s1,
                              const float* __restrict__ s2, const float* __restrict__ s3,
                              const float* __restrict__ s4, const float* __restrict__ s5,
                              __half* __restrict__ dst) {
    const int sizes[6] = {65536, 49152, 16384, 32768, 32768, 98304};
    const int offs [6] = {0, 65536, 114688, 131072, 163840, 196608};
    int t = blockIdx.y;
    const float* src = t == 0 ? s0 : t == 1 ? s1 : t == 2 ? s2 :
                       t == 3 ? s3 : t == 4 ? s4 : s5;
    int n2 = sizes[t] >> 1;
    int i = blockIdx.x * 256 + threadIdx.x;
    if (i < n2) {
        float2 v = *(const float2*)(src + 2 * i);
        *(__half2*)(dst + offs[t] + 2 * i) = __floats2half2_rn(v.x, v.y);
    }
}

__global__ void transpose_x_kernel(const float* __restrict__ x,
                                   __half* __restrict__ xt) {
    __shared__ float tile[32][33];
    int b  = blockIdx.z;
    int p0 = blockIdx.x * 32;
    int c0 = blockIdx.y * 32;
    const float* xb = x + (size_t)b * C1_ * HW_;
    __half*     xtb = xt + (size_t)b * HW_ * C1_;
#pragma unroll
    for (int i = 0; i < 32; i += 8)
        tile[threadIdx.y + i][threadIdx.x] =
            xb[(size_t)(c0 + threadIdx.y + i) * HW_ + p0 + threadIdx.x];
    __syncthreads();
#pragma unroll
    for (int i = 0; i < 32; i += 8)
        xtb[(size_t)(p0 + threadIdx.y + i) * C1_ + c0 + threadIdx.x] =
            __float2half_rn(tile[threadIdx.x][threadIdx.y + i]);
}

enum { EPI_CV1 = 0, EPI_QKV = 1, EPI_PROJ = 2, EPI_GELU = 3,
       EPI_FFN2 = 4, EPI_NCHW = 5 };

// ---------------------------------------------------------------------------
// gemm128: CTA 128x128, 8 warps (2m x 4n, warp 64x32). For LN-fused GEMMs.
// ---------------------------------------------------------------------------
#define STG128 36864
#define SM128_BYTES (2*STG128)

template <int EPI>
__global__ void __launch_bounds__(256)
gemm128(const __half* __restrict__ A, int lda,
        const __half* __restrict__ Wt, int K,
        void* __restrict__ Cpv, int ldc,
        const float* __restrict__ p0, const float* __restrict__ p1,
        const float* __restrict__ p2, const float* __restrict__ p3,
        const float* __restrict__ Rs, int ldr,
        const float* __restrict__ lng, const float* __restrict__ lnb,
        __half* __restrict__ fnout) {
    extern __shared__ __align__(16) char smem[];
    const u32 sb = smem_u32(smem);
    const int tid = threadIdx.x, wid = tid >> 5, lane = tid & 31;
    const int wm = (wid >> 2) * 64, wn = (wid & 3) * 32;
    const int g = lane >> 2, t2 = lane & 3;
    const int row0 = blockIdx.x * 128, col0 = blockIdx.y * 128;
    const int lrow = tid >> 3, lc8 = tid & 7;

    float acc[4][4][4];
#pragma unroll
    for (int i = 0; i < 4; i++)
#pragma unroll
        for (int j = 0; j < 4; j++)
#pragma unroll
            for (int q = 0; q < 4; q++) acc[i][j][q] = 0.f;

    const int nch = K >> 6;
    auto issue = [&](int c) {
        u32 ab = sb + (c & 1) * STG128;
        u32 bb = ab + 18432;
        const __half* Ag = A  + (size_t)row0 * lda + c * 64;
        const __half* Bg = Wt + (size_t)col0 * K   + c * 64;
#pragma unroll
        for (int i = 0; i < 4; i++) {
            int r = i * 32 + lrow;
            cp16(ab + r * 144 + lc8 * 16, Ag + (size_t)r * lda + lc8 * 8);
            cp16(bb + r * 144 + lc8 * 16, Bg + (size_t)r * K   + lc8 * 8);
        }
    };

    issue(0);
    asm volatile("cp.async.commit_group;");
    for (int c = 0; c < nch; c++) {
        if (c + 1 < nch) {
            issue(c + 1);
            asm volatile("cp.async.commit_group;");
            asm volatile("cp.async.wait_group 1;");
        } else {
            asm volatile("cp.async.wait_group 0;");
        }
        __syncthreads();
        u32 ab = sb + (c & 1) * STG128;
        u32 bb = ab + 18432;
#pragma unroll
        for (int kb = 0; kb < 4; kb++) {
            u32 a[4][4], b[4][2];
#pragma unroll
            for (int mf = 0; mf < 4; mf++) {
                int r = wm + mf * 16 + (lane & 7) + ((lane >> 3) & 1) * 8;
                ldm_x4(a[mf][0], a[mf][1], a[mf][2], a[mf][3],
                       ab + r * 144 + kb * 32 + (lane >> 4) * 16);
            }
#pragma unroll
            for (int np = 0; np < 2; np++) {
                int r = wn + np * 16 + (lane & 7) + ((lane >> 4) & 1) * 8;
                ldm_x4(b[2*np][0], b[2*np][1], b[2*np+1][0], b[2*np+1][1],
                       bb + r * 144 + kb * 32 + ((lane >> 3) & 1) * 16);
            }
#pragma unroll
            for (int mf = 0; mf < 4; mf++)
#pragma unroll
                for (int nf = 0; nf < 4; nf++)
                    mma_fp16(acc[mf][nf], a[mf], b[nf]);
        }
        __syncthreads();
    }

    float* stg = (float*)smem;
    const bool doLN = (EPI != EPI_CV1) || (blockIdx.y == 1);

#pragma unroll
    for (int mf = 0; mf < 4; mf++) {
#pragma unroll
        for (int nf = 0; nf < 4; nf++) {
            int lcol = wn + nf * 8 + t2 * 2;
            int col  = col0 + lcol;
            float e0 = 0.f, e1 = 0.f, f0 = 0.f, f1 = 0.f;
            if constexpr (EPI == EPI_CV1) {
                e0 = p0[col]     * rsqrtf(p3[col]     + 1e-5f);
                e1 = p0[col + 1] * rsqrtf(p3[col + 1] + 1e-5f);
                f0 = p1[col]     - p2[col]     * e0;
                f1 = p1[col + 1] - p2[col + 1] * e1;
            } else if constexpr (EPI == EPI_PROJ) {
                e0 = p0[col]; e1 = p0[col + 1];
                f0 = p1[col]; f1 = p1[col + 1];
            }
#pragma unroll
            for (int h = 0; h < 2; h++) {
                int r   = wm + mf * 16 + g + h * 8;
                int row = row0 + r;
                float v0 = acc[mf][nf][h * 2];
                float v1 = acc[mf][nf][h * 2 + 1];
                if constexpr (EPI == EPI_CV1) {
                    v0 = v0 * e0 + f0; v0 = v0 / (1.f + __expf(-v0));
                    v1 = v1 * e1 + f1; v1 = v1 / (1.f + __expf(-v1));
                    *(__half2*)((__half*)Cpv + (size_t)row * 384 + col) =
                        __floats2half2_rn(v0, v1);
                    if (col0 == 128)
                        *(float2*)(g_y2f + (size_t)row * 128 + lcol) =
                            make_float2(v0, v1);
                } else if constexpr (EPI == EPI_PROJ) {
                    float2 rs = *(const float2*)(Rs + (size_t)row * ldr + col);
                    v0 = rs.x + (v0 + e0) * f0;
                    v1 = rs.y + (v1 + e1) * f1;
                    *(float2*)((float*)Cpv + (size_t)row * ldc + col) =
                        make_float2(v0, v1);
                }
                if (doLN) {
                    stg[r * 129 + lcol]     = v0;
                    stg[r * 129 + lcol + 1] = v1;
                }
            }
        }
    }
    if (doLN) {
        __syncthreads();
#pragma unroll
        for (int rr = 0; rr < 16; rr++) {
            int r = wid * 16 + rr;
            float v[4];
            float s = 0.f;
#pragma unroll
            for (int i = 0; i < 4; i++) {
                v[i] = stg[r * 129 + lane + 32 * i];
                s += v[i];
            }
#pragma unroll
            for (int o = 16; o; o >>= 1) s += __shfl_xor_sync(~0u, s, o);
            float mu = s * (1.f / 128.f);
            float q = 0.f;
#pragma unroll
            for (int i = 0; i < 4; i++) { float d = v[i] - mu; q += d * d; }
#pragma unroll
            for (int o = 16; o; o >>= 1) q += __shfl_xor_sync(~0u, q, o);
            float rsd = rsqrtf(q * (1.f / 128.f) + 1e-5f);
#pragma unroll
            for (int i = 0; i < 4; i++) {
                int cc = lane + 32 * i;
                fnout[(size_t)(row0 + r) * 128 + cc] =
                    __float2half_rn((v[i] - mu) * rsd * lng[cc] + lnb[cc]);
            }
        }
    }
}

// ---------------------------------------------------------------------------
// gemm_ws: weight-stationary GEMM. CTA owns 64 output cols; weight slice
// W[64, K] resides in SMEM for the CTA's whole life. CTA iterates over MT
// row-tiles of 128, streaming A through a double-buffered cp.async pipeline
// that runs continuously across tile boundaries (register epilogue overlaps
// the next tile's loads). 8 warps = 4m x 2n, warp 32x32, acc 32 regs.
// SMEM: W chunks (K/64 x 64 x 144B) then A double buffer (2 x 128 x 144B).
// ---------------------------------------------------------------------------
#define WCHUNK 9216                    // 64 rows * 144 B
#define ABUF_BYTES 18432               // 128 rows * 144 B
#define WS_SMEM(K) (((K) >> 6) * WCHUNK + 2 * ABUF_BYTES)

template <int EPI>
__global__ void __launch_bounds__(256)
gemm_ws(const __half* __restrict__ A, int lda,
        const __half* __restrict__ Wt, int K,
        void* __restrict__ Cpv, int ldc,
        const float* __restrict__ p0, const float* __restrict__ p1,
        const float* __restrict__ p2, const float* __restrict__ p3,
        const float* __restrict__ Rs, int ldr, int MT) {
    extern __shared__ __align__(16) char smem[];
    const u32 sb = smem_u32(smem);
    const int tid = threadIdx.x, wid = tid >> 5, lane = tid & 31;
    const int wm = (wid >> 1) * 32, wn = (wid & 1) * 32;
    const int g = lane >> 2, t2 = lane & 3;
    const int col0 = blockIdx.y * 64;
    const int MC = gridDim.x;
    const int lrow = tid >> 3, lc8 = tid & 7;

    const int nch = K >> 6;
    const u32 AOFF = (u32)(nch * WCHUNK);
    const int total = MT * nch;

    // ---- load W slice once ----
    {
        const __half* Bg = Wt + (size_t)col0 * K;
        for (int c = 0; c < nch; c++) {
#pragma unroll
            for (int i = 0; i < 2; i++) {
                int r = i * 32 + lrow;
                cp16(sb + c * WCHUNK + r * 144 + lc8 * 16,
                     Bg + (size_t)r * K + c * 64 + lc8 * 8);
            }
        }
    }

    auto issueA = [&](int gg) {
        int m = gg / nch, c = gg - m * nch;
        int row0 = (m * MC + blockIdx.x) * 128;
        u32 ab = sb + AOFF + (u32)(gg & 1) * ABUF_BYTES;
        const __half* Ag = A + (size_t)row0 * lda + c * 64;
#pragma unroll
        for (int i = 0; i < 4; i++) {
            int r = i * 32 + lrow;
            cp16(ab + r * 144 + lc8 * 16, Ag + (size_t)r * lda + lc8 * 8);
        }
    };

    float acc[2][4][4];
#pragma unroll
    for (int i = 0; i < 2; i++)
#pragma unroll
        for (int j = 0; j < 4; j++)
#pragma unroll
            for (int q = 0; q < 4; q++) acc[i][j][q] = 0.f;

    issueA(0);
    asm volatile("cp.async.commit_group;");   // group: W + A0

    for (int gg = 0; gg < total; gg++) {
        const int c = gg % nch;
        const bool tileEnd = (c == nch - 1);
        const int m = gg / nch;
        const int row0 = (m * MC + blockIdx.x) * 128;

        if constexpr (EPI == EPI_NCHW) {
            // no prefetch across the smem-staging epilogue
            if (!tileEnd) {
                issueA(gg + 1);
                asm volatile("cp.async.commit_group;");
                asm volatile("cp.async.wait_group 1;");
            } else {
                asm volatile("cp.async.wait_group 0;");
            }
        } else {
            if (gg + 1 < total) {
                issueA(gg + 1);
                asm volatile("cp.async.commit_group;");
                asm volatile("cp.async.wait_group 1;");
            } else {
                asm volatile("cp.async.wait_group 0;");
            }
        }
        __syncthreads();

        u32 ab = sb + AOFF + (u32)(gg & 1) * ABUF_BYTES;
        u32 bb = sb + (u32)c * WCHUNK;
#pragma unroll
        for (int kb = 0; kb < 4; kb++) {
            u32 a[2][4], b[4][2];
#pragma unroll
            for (int mf = 0; mf < 2; mf++) {
                int r = wm + mf * 16 + (lane & 7) + ((lane >> 3) & 1) * 8;
                ldm_x4(a[mf][0], a[mf][1], a[mf][2], a[mf][3],
                       ab + r * 144 + kb * 32 + (lane >> 4) * 16);
            }
#pragma unroll
            for (int np = 0; np < 2; np++) {
                int r = wn + np * 16 + (lane & 7) + ((lane >> 4) & 1) * 8;
                ldm_x4(b[2*np][0], b[2*np][1], b[2*np+1][0], b[2*np+1][1],
                       bb + r * 144 + kb * 32 + ((lane >> 3) & 1) * 16);
            }
#pragma unroll
            for (int mf = 0; mf < 2; mf++)
#pragma unroll
                for (int nf = 0; nf < 4; nf++)
                    mma_fp16(acc[mf][nf], a[mf], b[nf]);
        }

        if (tileEnd) {
            if constexpr (EPI == EPI_NCHW) {
                __syncthreads();                 // all mma done; A bufs free
                float* stg = (float*)(smem + AOFF);   // 128 x 65 fp32
#pragma unroll
                for (int mf = 0; mf < 2; mf++)
#pragma unroll
                    for (int nf = 0; nf < 4; nf++) {
                        int r = wm + mf * 16 + g;
                        int cl = wn + nf * 8 + t2 * 2;
                        stg[r * 65 + cl]           = acc[mf][nf][0];
                        stg[r * 65 + cl + 1]       = acc[mf][nf][1];
                        stg[(r + 8) * 65 + cl]     = acc[mf][nf][2];
                        stg[(r + 8) * 65 + cl + 1] = acc[mf][nf][3];
                    }
                __syncthreads();
                float* Cp = (float*)Cpv;
                for (int it = 0; it < 32; it++) {
                    int idx  = it * 256 + tid;
                    int lcol = idx >> 7;
                    int r    = idx & 127;
                    int col  = col0 + lcol;
                    int row  = row0 + r;
                    float v  = stg[r * 65 + lcol];
                    float sc = p0[col] * rsqrtf(p3[col] + 1e-5f);
                    v = v * sc + (p1[col] - p2[col] * sc);
                    v = v / (1.f + __expf(-v));
                    Cp[(((size_t)(row >> 12)) * C2_ + col) * 4096 + (row & 4095)] = v;
                }
                if (gg + 1 < total) {
                    __syncthreads();             // writeout reads done
                    issueA(gg + 1);
                    asm volatile("cp.async.commit_group;");
                }
            } else {
                // register epilogue — overlaps next tile's in-flight loads
#pragma unroll
                for (int mf = 0; mf < 2; mf++) {
#pragma unroll
                    for (int nf = 0; nf < 4; nf++) {
                        int col = col0 + wn + nf * 8 + t2 * 2;
                        float e0 = p0[col], e1 = p0[col + 1];
#pragma unroll
                        for (int h = 0; h < 2; h++) {
                            int row = row0 + wm + mf * 16 + g + h * 8;
                            float v0 = acc[mf][nf][h * 2];
                            float v1 = acc[mf][nf][h * 2 + 1];
                            if constexpr (EPI == EPI_QKV) {
                                v0 += e0; v1 += e1;
                            } else if constexpr (EPI == EPI_GELU) {
                                v0 += e0; v1 += e1;
                                v0 = 0.5f * v0 * (1.f + erff(v0 * 0.70710678118654752f));
                                v1 = 0.5f * v1 * (1.f + erff(v1 * 0.70710678118654752f));
                            } else if constexpr (EPI == EPI_FFN2) {
                                float2 rs = *(const float2*)(Rs + (size_t)row * ldr + col);
                                v0 = v0 + e0 + rs.x;
                                v1 = v1 + e1 + rs.y;
                            }
                            *(__half2*)((__half*)Cpv + (size_t)row * ldc + col) =
                                __floats2half2_rn(v0, v1);
                        }
                    }
                }
            }
#pragma unroll
            for (int i = 0; i < 2; i++)
#pragma unroll
                for (int j = 0; j < 4; j++)
#pragma unroll
                    for (int q = 0; q < 4; q++) acc[i][j][q] = 0.f;
        }
        __syncthreads();
    }
}

// ---------------------------------------------------------------------------
// Tensor-core retention attention. One warp per (b, head, fixed line).
// ---------------------------------------------------------------------------
template <int PASS>
__global__ void __launch_bounds__(128)
attn_mma(const __half* __restrict__ qkv,
         float* __restrict__ partial,
         __half* __restrict__ out16) {
    __shared__ __half sQ[4][64 * 24];
    __shared__ __half sK[4][64 * 24];
    __shared__ __half sV[4][64 * 24];
    __shared__ float decrow[64];

    const int tid = threadIdx.x, wid = tid >> 5, lane = tid & 31;
    const int g = lane >> 2, t2 = lane & 3;
    const int fixed = blockIdx.x * 4 + wid;
    const int n = blockIdx.y, b = blockIdx.z;

    if (tid < 64) {
        float dec = logf(1.f - exp2f(-2.f - 0.5f * (float)n));
        decrow[tid] = 0.5f * __expf(dec * (float)tid);
    }

#pragma unroll
    for (int tt = 0; tt < 2; tt++) {
        int t = lane + tt * 32;
        size_t tok = (PASS == 0) ? ((size_t)(b * 64 + t) * 64 + fixed)
                                 : ((size_t)(b * 64 + fixed) * 64 + t);
        const uint4* src = (const uint4*)(qkv + tok * 384 + n * HD_);
        *(uint4*)&sQ[wid][t * 24]     = src[0];
        *(uint4*)&sQ[wid][t * 24 + 8] = src[1];
        *(uint4*)&sK[wid][t * 24]     = src[16];
        *(uint4*)&sK[wid][t * 24 + 8] = src[17];
        *(uint4*)&sV[wid][t * 24]     = src[32];
        *(uint4*)&sV[wid][t * 24 + 8] = src[33];
    }
    __syncthreads();

    const u32 qb = smem_u32(&sQ[wid][0]);
    const u32 kb = smem_u32(&sK[wid][0]);
    const u32 vb = smem_u32(&sV[wid][0]);

    u32 qa[4][4];
#pragma unroll
    for (int mf = 0; mf < 4; mf++) {
        int r = mf * 16 + (lane & 7) + ((lane >> 3) & 1) * 8;
        ldm_x4(qa[mf][0], qa[mf][1], qa[mf][2], qa[mf][3],
               qb + r * 48 + (lane >> 4) * 16);
    }

    float oacc[4][2][4];
#pragma unroll
    for (int i = 0; i < 4; i++)
#pragma unroll
        for (int j = 0; j < 2; j++)
#pragma unroll
            for (int q = 0; q < 4; q++) oacc[i][j][q] = 0.f;

#pragma unroll
    for (int jb = 0; jb < 4; jb++) {
        u32 kf[4];
        {
            int r = jb * 16 + (lane & 7) + ((lane >> 4) & 1) * 8;
            ldm_x4(kf[0], kf[1], kf[2], kf[3],
                   kb + r * 48 + ((lane >> 3) & 1) * 16);
        }
        float s[4][2][4];
#pragma unroll
        for (int mf = 0; mf < 4; mf++)
#pragma unroll
            for (int np = 0; np < 2; np++) {
#pragma unroll
                for (int q = 0; q < 4; q++) s[mf][np][q] = 0.f;
                u32 bfrag[2] = { kf[2 * np], kf[2 * np + 1] };
                mma_fp16(s[mf][np], qa[mf], bfrag);
            }
        u32 aP[4][4];
#pragma unroll
        for (int mf = 0; mf < 4; mf++) {
#pragma unroll
            for (int np = 0; np < 2; np++) {
                int i0 = mf * 16 + g;
                int j0 = jb * 16 + np * 8 + t2 * 2;
                int d00 = i0 - j0;       d00 = d00 < 0 ? -d00 : d00;
                int d01 = i0 - j0 - 1;   d01 = d01 < 0 ? -d01 : d01;
                int d10 = i0 + 8 - j0;   d10 = d10 < 0 ? -d10 : d10;
                int d11 = i0 + 7 - j0;   d11 = d11 < 0 ? -d11 : d11;
                s[mf][np][0] *= decrow[d00];
                s[mf][np][1] *= decrow[d01];
                s[mf][np][2] *= decrow[d10];
                s[mf][np][3] *= decrow[d11];
            }
            __half2 h;
            h = __floats2half2_rn(s[mf][0][0], s[mf][0][1]); aP[mf][0] = *(u32*)&h;
            h = __floats2half2_rn(s[mf][0][2], s[mf][0][3]); aP[mf][1] = *(u32*)&h;
            h = __floats2half2_rn(s[mf][1][0], s[mf][1][1]); aP[mf][2] = *(u32*)&h;
            h = __floats2half2_rn(s[mf][1][2], s[mf][1][3]); aP[mf][3] = *(u32*)&h;
        }
        u32 vf[4];
        {
            int r = jb * 16 + (lane & 7) + ((lane >> 3) & 1) * 8;
            ldm_x4t(vf[0], vf[1], vf[2], vf[3],
                    vb + r * 48 + (lane >> 4) * 16);
        }
#pragma unroll
        for (int mf = 0; mf < 4; mf++)
#pragma unroll
            for (int np = 0; np < 2; np++) {
                u32 bfrag[2] = { vf[2 * np], vf[2 * np + 1] };
                mma_fp16(oacc[mf][np], aP[mf], bfrag);
            }
    }

#pragma unroll
    for (int mf = 0; mf < 4; mf++)
#pragma unroll
        for (int np = 0; np < 2; np++) {
            int ch = n * HD_ + np * 8 + t2 * 2;
#pragma unroll
            for (int h = 0; h < 2; h++) {
                int i = mf * 16 + g + h * 8;
                size_t tok = (PASS == 0) ? ((size_t)(b * 64 + i) * 64 + fixed)
                                         : ((size_t)(b * 64 + fixed) * 64 + i);
                float v0 = oacc[mf][np][h * 2];
                float v1 = oacc[mf][np][h * 2 + 1];
                if (PASS == 0) {
                    *(float2*)(partial + tok * 128 + ch) = make_float2(v0, v1);
                } else {
                    float2 pr = *(const float2*)(partial + tok * 128 + ch);
                    *(__half2*)(out16 + tok * 128 + ch) =
                        __floats2half2_rn(pr.x + v0, pr.y + v1);
                }
            }
        }
}

// ---------------------------------------------------------------------------
extern "C" void kernel_launch(void* const* d_in, const int* in_sizes, int n_in,
                              void* d_out, int out_size) {
    const float* x      = (const float*)d_in[0];
    const float* cv1_w  = (const float*)d_in[1];
    const float* bn1_g  = (const float*)d_in[2];
    const float* bn1_b  = (const float*)d_in[3];
    const float* bn1_m  = (const float*)d_in[4];
    const float* bn1_v  = (const float*)d_in[5];
    const float* cv2_w  = (const float*)d_in[6];
    const float* bn2_g  = (const float*)d_in[7];
    const float* bn2_b  = (const float*)d_in[8];
    const float* bn2_m  = (const float*)d_in[9];
    const float* bn2_v  = (const float*)d_in[10];
    const float* ln1_g  = (const float*)d_in[11];
    const float* ln1_b  = (const float*)d_in[12];
    const float* qkv_w  = (const float*)d_in[13];
    const float* qkv_b  = (const float*)d_in[14];
    const float* proj_w = (const float*)d_in[15];
    const float* proj_b = (const float*)d_in[16];
    const float* gamma  = (const float*)d_in[17];
    const float* ln2_g  = (const float*)d_in[18];
    const float* ln2_b  = (const float*)d_in[19];
    const float* ffn_w1 = (const float*)d_in[20];
    const float* ffn_b1 = (const float*)d_in[21];
    const float* ffn_w2 = (const float*)d_in[22];
    const float* ffn_b2 = (const float*)d_in[23];
    float* out = (float*)d_out;

    __half *xt16, *cat16, *fn16, *qkv16, *attn16, *h116, *w16;
    float *y2f, *attnp, *f2;
    cudaGetSymbolAddress((void**)&xt16,   g_xt16);
    cudaGetSymbolAddress((void**)&cat16,  g_cat16);
    cudaGetSymbolAddress((void**)&y2f,    g_y2f);
    cudaGetSymbolAddress((void**)&fn16,   g_fn16);
    cudaGetSymbolAddress((void**)&qkv16,  g_qkv16);
    cudaGetSymbolAddress((void**)&attnp,  g_attnp);
    cudaGetSymbolAddress((void**)&attn16, g_attn16);
    cudaGetSymbolAddress((void**)&f2,     g_f2);
    cudaGetSymbolAddress((void**)&h116,   g_h116);
    cudaGetSymbolAddress((void**)&w16,    g_w16);

    __half* w_cv1  = w16;
    __half* w_qkv  = w_cv1 + 65536;
    __half* w_proj = w_qkv + 49152;
    __half* w_f1   = w_proj + 16384;
    __half* w_f2   = w_f1 + 32768;
    __half* w_cv2  = w_f2 + 32768;

    cudaFuncSetAttribute(gemm128<EPI_CV1>,  cudaFuncAttributeMaxDynamicSharedMemorySize, SM128_BYTES);
    cudaFuncSetAttribute(gemm128<EPI_PROJ>, cudaFuncAttributeMaxDynamicSharedMemorySize, SM128_BYTES);
    cudaFuncSetAttribute(gemm_ws<EPI_QKV>,  cudaFuncAttributeMaxDynamicSharedMemorySize, WS_SMEM(128));
    cudaFuncSetAttribute(gemm_ws<EPI_GELU>, cudaFuncAttributeMaxDynamicSharedMemorySize, WS_SMEM(128));
    cudaFuncSetAttribute(gemm_ws<EPI_FFN2>, cudaFuncAttributeMaxDynamicSharedMemorySize, WS_SMEM(256));
    cudaFuncSetAttribute(gemm_ws<EPI_NCHW>, cudaFuncAttributeMaxDynamicSharedMemorySize, WS_SMEM(384));

    // 0) weights -> fp16
    convert_w_all<<<dim3(192, 6), 256>>>(cv1_w, qkv_w, proj_w, ffn_w1, ffn_w2,
                                         cv2_w, w16);

    // 1) x NCHW -> xt16
    transpose_x_kernel<<<dim3(HW_/32, C1_/32, B_), dim3(32, 8)>>>(x, xt16);

    // 2) cv1 + BN + SiLU -> cat16[:,0:256] (+ y2f, + fused LN1 -> fn16)
    gemm128<EPI_CV1><<<dim3(TOKENS/128, 2), 256, SM128_BYTES>>>(
        xt16, 256, w_cv1, 256, cat16, 384, bn1_g, bn1_b, bn1_m, bn1_v,
        nullptr, 0, ln1_g, ln1_b, fn16);

    // 3) qkv  (ws: 64 CTAs x 6 cols, MT=8)
    gemm_ws<EPI_QKV><<<dim3(64, 6), 256, WS_SMEM(128)>>>(
        fn16, 128, w_qkv, 128, qkv16, 384, qkv_b, nullptr, nullptr, nullptr,
        nullptr, 0, 8);

    // 4) attention H then W
    attn_mma<0><<<dim3(16, NH_, B_), 128>>>(qkv16, attnp, attn16);
    attn_mma<1><<<dim3(16, NH_, B_), 128>>>(qkv16, attnp, attn16);

    // 5) proj (+res y2, *gamma) -> f2 (+ fused LN2 -> fn16)
    gemm128<EPI_PROJ><<<dim3(TOKENS/128, 1), 256, SM128_BYTES>>>(
        attn16, 128, w_proj, 128, f2, 128, proj_b, gamma, nullptr, nullptr,
        y2f, 128, ln2_g, ln2_b, fn16);

    // 6) ffn1 + GELU  (ws: 128 CTAs x 4 cols, MT=4)
    gemm_ws<EPI_GELU><<<dim3(128, 4), 256, WS_SMEM(128)>>>(
        fn16, 128, w_f1, 128, h116, 256, ffn_b1, nullptr, nullptr, nullptr,
        nullptr, 0, 4);

    // 7) ffn2 + bias + res f2 -> cat16[:,256:384]  (ws: 128 x 2, MT=4)
    gemm_ws<EPI_FFN2><<<dim3(128, 2), 256, WS_SMEM(256)>>>(
        h116, 256, w_f2, 256, cat16 + 256, 384, ffn_b2, nullptr, nullptr, nullptr,
        f2, 128, 4);

    // 8) cv2 + BN + SiLU -> NCHW out  (ws: 128 x 4, MT=4)
    gemm_ws<EPI_NCHW><<<dim3(128, 4), 256, WS_SMEM(384)>>>(
        cat16, 384, w_cv2, 384, out, 0, bn2_g, bn2_b, bn2_m, bn2_v,
        nullptr, 0, 4);
}

// round 8
// speedup vs baseline: 1.0682x; 1.0682x over previous
#include <cuda_runtime.h>
#include <cuda_fp16.h>
#include <math.h>

#define B_ 16
#define C1_ 256
#define C2_ 256
#define H_ 64
#define W_ 64
#define NH_ 8
#define C_ 128
#define HD_ 16
#define HW_ (H_*W_)
#define TOKENS (B_*HW_)

typedef unsigned int u32;

// -------- static scratch -----------
__device__ __half g_xt16  [(size_t)TOKENS*256];
__device__ __half g_cat16 [(size_t)TOKENS*384];
__device__ float  g_y2f   [(size_t)TOKENS*128];
__device__ __half g_fn16  [(size_t)TOKENS*128];
__device__ __half g_qkv16 [(size_t)TOKENS*384];
__device__ float  g_attnp [(size_t)TOKENS*128];
__device__ __half g_attn16[(size_t)TOKENS*128];
__device__ float  g_f2    [(size_t)TOKENS*128];
__device__ __half g_h116  [(size_t)TOKENS*256];
__device__ __half g_w16[65536+49152+16384+32768+32768+98304];

// ---------------------------------------------------------------------------
__device__ __forceinline__ u32 smem_u32(const void* p) {
    u32 a;
    asm("{ .reg .u64 t; cvta.to.shared.u64 t, %1; cvt.u32.u64 %0, t; }"
        : "=r"(a) : "l"(p));
    return a;
}
__device__ __forceinline__ void mma_fp16(float* c, const u32* a, const u32* b) {
    asm volatile(
        "mma.sync.aligned.m16n8k16.row.col.f32.f16.f16.f32 "
        "{%0,%1,%2,%3}, {%4,%5,%6,%7}, {%8,%9}, {%0,%1,%2,%3};"
        : "+f"(c[0]), "+f"(c[1]), "+f"(c[2]), "+f"(c[3])
        : "r"(a[0]), "r"(a[1]), "r"(a[2]), "r"(a[3]), "r"(b[0]), "r"(b[1]));
}
__device__ __forceinline__ void ldm_x4(u32& r0, u32& r1, u32& r2, u32& r3, u32 a) {
    asm volatile("ldmatrix.sync.aligned.m8n8.x4.shared.b16 {%0,%1,%2,%3}, [%4];"
        : "=r"(r0), "=r"(r1), "=r"(r2), "=r"(r3) : "r"(a));
}
__device__ __forceinline__ void ldm_x4t(u32& r0, u32& r1, u32& r2, u32& r3, u32 a) {
    asm volatile("ldmatrix.sync.aligned.m8n8.x4.trans.shared.b16 {%0,%1,%2,%3}, [%4];"
        : "=r"(r0), "=r"(r1), "=r"(r2), "=r"(r3) : "r"(a));
}
__device__ __forceinline__ void cp16(u32 dst, const void* src) {
    asm volatile("cp.async.cg.shared.global [%0], [%1], 16;" :: "r"(dst), "l"(src));
}

// ---------------------------------------------------------------------------
__global__ void convert_w_all(const float* __restrict__ s0, const float* __restrict__ s1,
                              const float* __restrict__ s2, const float* __restrict__ s3,
                              const float* __restrict__ s4, const float* __restrict__ s5,
                              __half* __restrict__ dst) {
    const int sizes[6] = {65536, 49152, 16384, 32768, 32768, 98304};
    const int offs [6] = {0, 65536, 114688, 131072, 163840, 196608};
    int t = blockIdx.y;
    const float* src = t == 0 ? s0 : t == 1 ? s1 : t == 2 ? s2 :
                       t == 3 ? s3 : t == 4 ? s4 : s5;
    int n2 = sizes[t] >> 1;
    int i = blockIdx.x * 256 + threadIdx.x;
    if (i < n2) {
        float2 v = *(const float2*)(src + 2 * i);
        *(__half2*)(dst + offs[t] + 2 * i) = __floats2half2_rn(v.x, v.y);
    }
}

__global__ void transpose_x_kernel(const float* __restrict__ x,
                                   __half* __restrict__ xt) {
    __shared__ float tile[32][33];
    int b  = blockIdx.z;
    int p0 = blockIdx.x * 32;
    int c0 = blockIdx.y * 32;
    const float* xb = x + (size_t)b * C1_ * HW_;
    __half*     xtb = xt + (size_t)b * HW_ * C1_;
#pragma unroll
    for (int i = 0; i < 32; i += 8)
        tile[threadIdx.y + i][threadIdx.x] =
            xb[(size_t)(c0 + threadIdx.y + i) * HW_ + p0 + threadIdx.x];
    __syncthreads();
#pragma unroll
    for (int i = 0; i < 32; i += 8)
        xtb[(size_t)(p0 + threadIdx.y + i) * C1_ + c0 + threadIdx.x] =
            __float2half_rn(tile[threadIdx.x][threadIdx.y + i]);
}

enum { EPI_CV1 = 0, EPI_QKV = 1, EPI_PROJ = 2, EPI_GELU = 3,
       EPI_FFN2 = 4, EPI_NCHW = 5 };

// ---------------------------------------------------------------------------
// gemm128: CTA 128x128, 8 warps (2m x 4n, warp 64x32). 3-stage cp.async,
// ONE barrier per chunk. For LN-fused GEMMs (cv1, proj).
// ---------------------------------------------------------------------------
#define STG128 36864
#define SM128_BYTES (3*STG128)      // 110592; staging 128*129*4=66048 fits

template <int EPI>
__global__ void __launch_bounds__(256)
gemm128(const __half* __restrict__ A, int lda,
        const __half* __restrict__ Wt, int K,
        void* __restrict__ Cpv, int ldc,
        const float* __restrict__ p0, const float* __restrict__ p1,
        const float* __restrict__ p2, const float* __restrict__ p3,
        const float* __restrict__ Rs, int ldr,
        const float* __restrict__ lng, const float* __restrict__ lnb,
        __half* __restrict__ fnout) {
    extern __shared__ __align__(16) char smem[];
    const u32 sb = smem_u32(smem);
    const int tid = threadIdx.x, wid = tid >> 5, lane = tid & 31;
    const int wm = (wid >> 2) * 64, wn = (wid & 3) * 32;
    const int g = lane >> 2, t2 = lane & 3;
    const int row0 = blockIdx.x * 128, col0 = blockIdx.y * 128;
    const int lrow = tid >> 3, lc8 = tid & 7;

    float acc[4][4][4];
#pragma unroll
    for (int i = 0; i < 4; i++)
#pragma unroll
        for (int j = 0; j < 4; j++)
#pragma unroll
            for (int q = 0; q < 4; q++) acc[i][j][q] = 0.f;

    const int nch = K >> 6;
    auto issue = [&](int c) {
        u32 ab = sb + (u32)(c % 3) * STG128;
        u32 bb = ab + 18432;
        const __half* Ag = A  + (size_t)row0 * lda + c * 64;
        const __half* Bg = Wt + (size_t)col0 * K   + c * 64;
#pragma unroll
        for (int i = 0; i < 4; i++) {
            int r = i * 32 + lrow;
            cp16(ab + r * 144 + lc8 * 16, Ag + (size_t)r * lda + lc8 * 8);
            cp16(bb + r * 144 + lc8 * 16, Bg + (size_t)r * K   + lc8 * 8);
        }
    };

    issue(0);
    asm volatile("cp.async.commit_group;");
    if (nch > 1) {
        issue(1);
        asm volatile("cp.async.commit_group;");
    }
    for (int c = 0; c < nch; c++) {
        if (c + 1 < nch) asm volatile("cp.async.wait_group 1;");
        else             asm volatile("cp.async.wait_group 0;");
        __syncthreads();
        u32 ab = sb + (u32)(c % 3) * STG128;
        u32 bb = ab + 18432;
#pragma unroll
        for (int kb = 0; kb < 4; kb++) {
            u32 a[4][4], b[4][2];
#pragma unroll
            for (int mf = 0; mf < 4; mf++) {
                int r = wm + mf * 16 + (lane & 7) + ((lane >> 3) & 1) * 8;
                ldm_x4(a[mf][0], a[mf][1], a[mf][2], a[mf][3],
                       ab + r * 144 + kb * 32 + (lane >> 4) * 16);
            }
#pragma unroll
            for (int np = 0; np < 2; np++) {
                int r = wn + np * 16 + (lane & 7) + ((lane >> 4) & 1) * 8;
                ldm_x4(b[2*np][0], b[2*np][1], b[2*np+1][0], b[2*np+1][1],
                       bb + r * 144 + kb * 32 + ((lane >> 3) & 1) * 16);
            }
#pragma unroll
            for (int mf = 0; mf < 4; mf++)
#pragma unroll
                for (int nf = 0; nf < 4; nf++)
                    mma_fp16(acc[mf][nf], a[mf], b[nf]);
        }
        if (c + 2 < nch) {
            issue(c + 2);
            asm volatile("cp.async.commit_group;");
        }
    }
    __syncthreads();   // all mma done before smem reuse (LN staging)

    float* stg = (float*)smem;
    const bool doLN = (EPI != EPI_CV1) || (blockIdx.y == 1);

#pragma unroll
    for (int mf = 0; mf < 4; mf++) {
#pragma unroll
        for (int nf = 0; nf < 4; nf++) {
            int lcol = wn + nf * 8 + t2 * 2;
            int col  = col0 + lcol;
            float e0 = 0.f, e1 = 0.f, f0 = 0.f, f1 = 0.f;
            if constexpr (EPI == EPI_CV1) {
                e0 = p0[col]     * rsqrtf(p3[col]     + 1e-5f);
                e1 = p0[col + 1] * rsqrtf(p3[col + 1] + 1e-5f);
                f0 = p1[col]     - p2[col]     * e0;
                f1 = p1[col + 1] - p2[col + 1] * e1;
            } else if constexpr (EPI == EPI_PROJ) {
                e0 = p0[col]; e1 = p0[col + 1];
                f0 = p1[col]; f1 = p1[col + 1];
            }
#pragma unroll
            for (int h = 0; h < 2; h++) {
                int r   = wm + mf * 16 + g + h * 8;
                int row = row0 + r;
                float v0 = acc[mf][nf][h * 2];
                float v1 = acc[mf][nf][h * 2 + 1];
                if constexpr (EPI == EPI_CV1) {
                    v0 = v0 * e0 + f0; v0 = v0 / (1.f + __expf(-v0));
                    v1 = v1 * e1 + f1; v1 = v1 / (1.f + __expf(-v1));
                    *(__half2*)((__half*)Cpv + (size_t)row * 384 + col) =
                        __floats2half2_rn(v0, v1);
                    if (col0 == 128)
                        *(float2*)(g_y2f + (size_t)row * 128 + lcol) =
                            make_float2(v0, v1);
                } else if constexpr (EPI == EPI_PROJ) {
                    float2 rs = *(const float2*)(Rs + (size_t)row * ldr + col);
                    v0 = rs.x + (v0 + e0) * f0;
                    v1 = rs.y + (v1 + e1) * f1;
                    *(float2*)((float*)Cpv + (size_t)row * ldc + col) =
                        make_float2(v0, v1);
                }
                if (doLN) {
                    stg[r * 129 + lcol]     = v0;
                    stg[r * 129 + lcol + 1] = v1;
                }
            }
        }
    }
    if (doLN) {
        __syncthreads();
#pragma unroll
        for (int rr = 0; rr < 16; rr++) {
            int r = wid * 16 + rr;
            float v[4];
            float s = 0.f;
#pragma unroll
            for (int i = 0; i < 4; i++) {
                v[i] = stg[r * 129 + lane + 32 * i];
                s += v[i];
            }
#pragma unroll
            for (int o = 16; o; o >>= 1) s += __shfl_xor_sync(~0u, s, o);
            float mu = s * (1.f / 128.f);
            float q = 0.f;
#pragma unroll
            for (int i = 0; i < 4; i++) { float d = v[i] - mu; q += d * d; }
#pragma unroll
            for (int o = 16; o; o >>= 1) q += __shfl_xor_sync(~0u, q, o);
            float rsd = rsqrtf(q * (1.f / 128.f) + 1e-5f);
#pragma unroll
            for (int i = 0; i < 4; i++) {
                int cc = lane + 32 * i;
                fnout[(size_t)(row0 + r) * 128 + cc] =
                    __float2half_rn((v[i] - mu) * rsd * lng[cc] + lnb[cc]);
            }
        }
    }
}

// ---------------------------------------------------------------------------
// gemm64: CTA 128x64, 8 warps (4m x 2n, warp 32x32). 3-stage cp.async,
// ONE barrier per chunk.
// ---------------------------------------------------------------------------
#define STG64 27648           // A 128*144 + B 64*144
#define SM64_BYTES (3*STG64)  // 82944 (>= 128*65*4 = 33280 NCHW staging)

template <int EPI>
__global__ void __launch_bounds__(256, 2)
gemm64(const __half* __restrict__ A, int lda,
       const __half* __restrict__ Wt, int K,
       void* __restrict__ Cpv, int ldc,
       const float* __restrict__ p0, const float* __restrict__ p1,
       const float* __restrict__ p2, const float* __restrict__ p3,
       const float* __restrict__ Rs, int ldr) {
    extern __shared__ __align__(16) char smem[];
    const u32 sb = smem_u32(smem);
    const int tid = threadIdx.x, wid = tid >> 5, lane = tid & 31;
    const int wm = (wid >> 1) * 32, wn = (wid & 1) * 32;
    const int g = lane >> 2, t2 = lane & 3;
    const int row0 = blockIdx.x * 128, col0 = blockIdx.y * 64;
    const int lrow = tid >> 3, lc8 = tid & 7;

    float acc[2][4][4];
#pragma unroll
    for (int i = 0; i < 2; i++)
#pragma unroll
        for (int j = 0; j < 4; j++)
#pragma unroll
            for (int q = 0; q < 4; q++) acc[i][j][q] = 0.f;

    const int nch = K >> 6;
    auto issue = [&](int c) {
        u32 ab = sb + (u32)(c % 3) * STG64;
        u32 bb = ab + 18432;
        const __half* Ag = A  + (size_t)row0 * lda + c * 64;
        const __half* Bg = Wt + (size_t)col0 * K   + c * 64;
#pragma unroll
        for (int i = 0; i < 4; i++) {
            int r = i * 32 + lrow;
            cp16(ab + r * 144 + lc8 * 16, Ag + (size_t)r * lda + lc8 * 8);
        }
#pragma unroll
        for (int i = 0; i < 2; i++) {
            int r = i * 32 + lrow;
            cp16(bb + r * 144 + lc8 * 16, Bg + (size_t)r * K + lc8 * 8);
        }
    };

    issue(0);
    asm volatile("cp.async.commit_group;");
    if (nch > 1) {
        issue(1);
        asm volatile("cp.async.commit_group;");
    }
    for (int c = 0; c < nch; c++) {
        if (c + 1 < nch) asm volatile("cp.async.wait_group 1;");
        else             asm volatile("cp.async.wait_group 0;");
        __syncthreads();
        u32 ab = sb + (u32)(c % 3) * STG64;
        u32 bb = ab + 18432;
#pragma unroll
        for (int kb = 0; kb < 4; kb++) {
            u32 a[2][4], b[4][2];
#pragma unroll
            for (int mf = 0; mf < 2; mf++) {
                int r = wm + mf * 16 + (lane & 7) + ((lane >> 3) & 1) * 8;
                ldm_x4(a[mf][0], a[mf][1], a[mf][2], a[mf][3],
                       ab + r * 144 + kb * 32 + (lane >> 4) * 16);
            }
#pragma unroll
            for (int np = 0; np < 2; np++) {
                int r = wn + np * 16 + (lane & 7) + ((lane >> 4) & 1) * 8;
                ldm_x4(b[2*np][0], b[2*np][1], b[2*np+1][0], b[2*np+1][1],
                       bb + r * 144 + kb * 32 + ((lane >> 3) & 1) * 16);
            }
#pragma unroll
            for (int mf = 0; mf < 2; mf++)
#pragma unroll
                for (int nf = 0; nf < 4; nf++)
                    mma_fp16(acc[mf][nf], a[mf], b[nf]);
        }
        if (c + 2 < nch) {
            issue(c + 2);
            asm volatile("cp.async.commit_group;");
        }
    }

    if constexpr (EPI == EPI_NCHW) {
        __syncthreads();                 // drain before smem reuse
        float* stg = (float*)smem;       // 128 x 65
#pragma unroll
        for (int mf = 0; mf < 2; mf++)
#pragma unroll
            for (int nf = 0; nf < 4; nf++) {
                int r = wm + mf * 16 + g;
                int cl = wn + nf * 8 + t2 * 2;
                stg[r * 65 + cl]           = acc[mf][nf][0];
                stg[r * 65 + cl + 1]       = acc[mf][nf][1];
                stg[(r + 8) * 65 + cl]     = acc[mf][nf][2];
                stg[(r + 8) * 65 + cl + 1] = acc[mf][nf][3];
            }
        __syncthreads();
        float* Cp = (float*)Cpv;
        for (int it = 0; it < 32; it++) {
            int idx  = it * 256 + tid;
            int lcol = idx >> 7;
            int r    = idx & 127;
            int col  = col0 + lcol;
            int row  = row0 + r;
            float v  = stg[r * 65 + lcol];
            float sc = p0[col] * rsqrtf(p3[col] + 1e-5f);
            v = v * sc + (p1[col] - p2[col] * sc);
            v = v / (1.f + __expf(-v));
            Cp[(((size_t)(row >> 12)) * C2_ + col) * 4096 + (row & 4095)] = v;
        }
    } else {
#pragma unroll
        for (int mf = 0; mf < 2; mf++) {
#pragma unroll
            for (int nf = 0; nf < 4; nf++) {
                int col = col0 + wn + nf * 8 + t2 * 2;
                float e0 = p0[col], e1 = p0[col + 1];
#pragma unroll
                for (int h = 0; h < 2; h++) {
                    int row = row0 + wm + mf * 16 + g + h * 8;
                    float v0 = acc[mf][nf][h * 2];
                    float v1 = acc[mf][nf][h * 2 + 1];
                    if constexpr (EPI == EPI_QKV) {
                        v0 += e0; v1 += e1;
                    } else if constexpr (EPI == EPI_GELU) {
                        v0 += e0; v1 += e1;
                        v0 = 0.5f * v0 * (1.f + erff(v0 * 0.70710678118654752f));
                        v1 = 0.5f * v1 * (1.f + erff(v1 * 0.70710678118654752f));
                    } else if constexpr (EPI == EPI_FFN2) {
                        float2 rs = *(const float2*)(Rs + (size_t)row * ldr + col);
                        v0 = v0 + e0 + rs.x;
                        v1 = v1 + e1 + rs.y;
                    }
                    *(__half2*)((__half*)Cpv + (size_t)row * ldc + col) =
                        __floats2half2_rn(v0, v1);
                }
            }
        }
    }
}

// ---------------------------------------------------------------------------
// Tensor-core retention attention. One warp per (b, head, fixed line).
// ---------------------------------------------------------------------------
template <int PASS>
__global__ void __launch_bounds__(128)
attn_mma(const __half* __restrict__ qkv,
         float* __restrict__ partial,
         __half* __restrict__ out16) {
    __shared__ __half sQ[4][64 * 24];
    __shared__ __half sK[4][64 * 24];
    __shared__ __half sV[4][64 * 24];
    __shared__ float decrow[64];

    const int tid = threadIdx.x, wid = tid >> 5, lane = tid & 31;
    const int g = lane >> 2, t2 = lane & 3;
    const int fixed = blockIdx.x * 4 + wid;
    const int n = blockIdx.y, b = blockIdx.z;

    if (tid < 64) {
        float dec = logf(1.f - exp2f(-2.f - 0.5f * (float)n));
        decrow[tid] = 0.5f * __expf(dec * (float)tid);
    }

#pragma unroll
    for (int tt = 0; tt < 2; tt++) {
        int t = lane + tt * 32;
        size_t tok = (PASS == 0) ? ((size_t)(b * 64 + t) * 64 + fixed)
                                 : ((size_t)(b * 64 + fixed) * 64 + t);
        const uint4* src = (const uint4*)(qkv + tok * 384 + n * HD_);
        *(uint4*)&sQ[wid][t * 24]     = src[0];
        *(uint4*)&sQ[wid][t * 24 + 8] = src[1];
        *(uint4*)&sK[wid][t * 24]     = src[16];
        *(uint4*)&sK[wid][t * 24 + 8] = src[17];
        *(uint4*)&sV[wid][t * 24]     = src[32];
        *(uint4*)&sV[wid][t * 24 + 8] = src[33];
    }
    __syncthreads();

    const u32 qb = smem_u32(&sQ[wid][0]);
    const u32 kb = smem_u32(&sK[wid][0]);
    const u32 vb = smem_u32(&sV[wid][0]);

    u32 qa[4][4];
#pragma unroll
    for (int mf = 0; mf < 4; mf++) {
        int r = mf * 16 + (lane & 7) + ((lane >> 3) & 1) * 8;
        ldm_x4(qa[mf][0], qa[mf][1], qa[mf][2], qa[mf][3],
               qb + r * 48 + (lane >> 4) * 16);
    }

    float oacc[4][2][4];
#pragma unroll
    for (int i = 0; i < 4; i++)
#pragma unroll
        for (int j = 0; j < 2; j++)
#pragma unroll
            for (int q = 0; q < 4; q++) oacc[i][j][q] = 0.f;

#pragma unroll
    for (int jb = 0; jb < 4; jb++) {
        u32 kf[4];
        {
            int r = jb * 16 + (lane & 7) + ((lane >> 4) & 1) * 8;
            ldm_x4(kf[0], kf[1], kf[2], kf[3],
                   kb + r * 48 + ((lane >> 3) & 1) * 16);
        }
        float s[4][2][4];
#pragma unroll
        for (int mf = 0; mf < 4; mf++)
#pragma unroll
            for (int np = 0; np < 2; np++) {
#pragma unroll
                for (int q = 0; q < 4; q++) s[mf][np][q] = 0.f;
                u32 bfrag[2] = { kf[2 * np], kf[2 * np + 1] };
                mma_fp16(s[mf][np], qa[mf], bfrag);
            }
        u32 aP[4][4];
#pragma unroll
        for (int mf = 0; mf < 4; mf++) {
#pragma unroll
            for (int np = 0; np < 2; np++) {
                int i0 = mf * 16 + g;
                int j0 = jb * 16 + np * 8 + t2 * 2;
                int d00 = i0 - j0;       d00 = d00 < 0 ? -d00 : d00;
                int d01 = i0 - j0 - 1;   d01 = d01 < 0 ? -d01 : d01;
                int d10 = i0 + 8 - j0;   d10 = d10 < 0 ? -d10 : d10;
                int d11 = i0 + 7 - j0;   d11 = d11 < 0 ? -d11 : d11;
                s[mf][np][0] *= decrow[d00];
                s[mf][np][1] *= decrow[d01];
                s[mf][np][2] *= decrow[d10];
                s[mf][np][3] *= decrow[d11];
            }
            __half2 h;
            h = __floats2half2_rn(s[mf][0][0], s[mf][0][1]); aP[mf][0] = *(u32*)&h;
            h = __floats2half2_rn(s[mf][0][2], s[mf][0][3]); aP[mf][1] = *(u32*)&h;
            h = __floats2half2_rn(s[mf][1][0], s[mf][1][1]); aP[mf][2] = *(u32*)&h;
            h = __floats2half2_rn(s[mf][1][2], s[mf][1][3]); aP[mf][3] = *(u32*)&h;
        }
        u32 vf[4];
        {
            int r = jb * 16 + (lane & 7) + ((lane >> 3) & 1) * 8;
            ldm_x4t(vf[0], vf[1], vf[2], vf[3],
                    vb + r * 48 + (lane >> 4) * 16);
        }
#pragma unroll
        for (int mf = 0; mf < 4; mf++)
#pragma unroll
            for (int np = 0; np < 2; np++) {
                u32 bfrag[2] = { vf[2 * np], vf[2 * np + 1] };
                mma_fp16(oacc[mf][np], aP[mf], bfrag);
            }
    }

#pragma unroll
    for (int mf = 0; mf < 4; mf++)
#pragma unroll
        for (int np = 0; np < 2; np++) {
            int ch = n * HD_ + np * 8 + t2 * 2;
#pragma unroll
            for (int h = 0; h < 2; h++) {
                int i = mf * 16 + g + h * 8;
                size_t tok = (PASS == 0) ? ((size_t)(b * 64 + i) * 64 + fixed)
                                         : ((size_t)(b * 64 + fixed) * 64 + i);
                float v0 = oacc[mf][np][h * 2];
                float v1 = oacc[mf][np][h * 2 + 1];
                if (PASS == 0) {
                    *(float2*)(partial + tok * 128 + ch) = make_float2(v0, v1);
                } else {
                    float2 pr = *(const float2*)(partial + tok * 128 + ch);
                    *(__half2*)(out16 + tok * 128 + ch) =
                        __floats2half2_rn(pr.x + v0, pr.y + v1);
                }
            }
        }
}

// ---------------------------------------------------------------------------
extern "C" void kernel_launch(void* const* d_in, const int* in_sizes, int n_in,
                              void* d_out, int out_size) {
    const float* x      = (const float*)d_in[0];
    const float* cv1_w  = (const float*)d_in[1];
    const float* bn1_g  = (const float*)d_in[2];
    const float* bn1_b  = (const float*)d_in[3];
    const float* bn1_m  = (const float*)d_in[4];
    const float* bn1_v  = (const float*)d_in[5];
    const float* cv2_w  = (const float*)d_in[6];
    const float* bn2_g  = (const float*)d_in[7];
    const float* bn2_b  = (const float*)d_in[8];
    const float* bn2_m  = (const float*)d_in[9];
    const float* bn2_v  = (const float*)d_in[10];
    const float* ln1_g  = (const float*)d_in[11];
    const float* ln1_b  = (const float*)d_in[12];
    const float* qkv_w  = (const float*)d_in[13];
    const float* qkv_b  = (const float*)d_in[14];
    const float* proj_w = (const float*)d_in[15];
    const float* proj_b = (const float*)d_in[16];
    const float* gamma  = (const float*)d_in[17];
    const float* ln2_g  = (const float*)d_in[18];
    const float* ln2_b  = (const float*)d_in[19];
    const float* ffn_w1 = (const float*)d_in[20];
    const float* ffn_b1 = (const float*)d_in[21];
    const float* ffn_w2 = (const float*)d_in[22];
    const float* ffn_b2 = (const float*)d_in[23];
    float* out = (float*)d_out;

    __half *xt16, *cat16, *fn16, *qkv16, *attn16, *h116, *w16;
    float *y2f, *attnp, *f2;
    cudaGetSymbolAddress((void**)&xt16,   g_xt16);
    cudaGetSymbolAddress((void**)&cat16,  g_cat16);
    cudaGetSymbolAddress((void**)&y2f,    g_y2f);
    cudaGetSymbolAddress((void**)&fn16,   g_fn16);
    cudaGetSymbolAddress((void**)&qkv16,  g_qkv16);
    cudaGetSymbolAddress((void**)&attnp,  g_attnp);
    cudaGetSymbolAddress((void**)&attn16, g_attn16);
    cudaGetSymbolAddress((void**)&f2,     g_f2);
    cudaGetSymbolAddress((void**)&h116,   g_h116);
    cudaGetSymbolAddress((void**)&w16,    g_w16);

    __half* w_cv1  = w16;
    __half* w_qkv  = w_cv1 + 65536;
    __half* w_proj = w_qkv + 49152;
    __half* w_f1   = w_proj + 16384;
    __half* w_f2   = w_f1 + 32768;
    __half* w_cv2  = w_f2 + 32768;

    cudaFuncSetAttribute(gemm128<EPI_CV1>,  cudaFuncAttributeMaxDynamicSharedMemorySize, SM128_BYTES);
    cudaFuncSetAttribute(gemm128<EPI_PROJ>, cudaFuncAttributeMaxDynamicSharedMemorySize, SM128_BYTES);
    cudaFuncSetAttribute(gemm64<EPI_QKV>,   cudaFuncAttributeMaxDynamicSharedMemorySize, SM64_BYTES);
    cudaFuncSetAttribute(gemm64<EPI_GELU>,  cudaFuncAttributeMaxDynamicSharedMemorySize, SM64_BYTES);
    cudaFuncSetAttribute(gemm64<EPI_FFN2>,  cudaFuncAttributeMaxDynamicSharedMemorySize, SM64_BYTES);
    cudaFuncSetAttribute(gemm64<EPI_NCHW>,  cudaFuncAttributeMaxDynamicSharedMemorySize, SM64_BYTES);

    // 0) weights -> fp16
    convert_w_all<<<dim3(192, 6), 256>>>(cv1_w, qkv_w, proj_w, ffn_w1, ffn_w2,
                                         cv2_w, w16);

    // 1) x NCHW -> xt16
    transpose_x_kernel<<<dim3(HW_/32, C1_/32, B_), dim3(32, 8)>>>(x, xt16);

    // 2) cv1 + BN + SiLU -> cat16[:,0:256] (+ y2f, + fused LN1 -> fn16)
    gemm128<EPI_CV1><<<dim3(TOKENS/128, 2), 256, SM128_BYTES>>>(
        xt16, 256, w_cv1, 256, cat16, 384, bn1_g, bn1_b, bn1_m, bn1_v,
        nullptr, 0, ln1_g, ln1_b, fn16);

    // 3) qkv
    gemm64<EPI_QKV><<<dim3(TOKENS/128, 6), 256, SM64_BYTES>>>(
        fn16, 128, w_qkv, 128, qkv16, 384, qkv_b, nullptr, nullptr, nullptr,
        nullptr, 0);

    // 4) attention H then W
    attn_mma<0><<<dim3(16, NH_, B_), 128>>>(qkv16, attnp, attn16);
    attn_mma<1><<<dim3(16, NH_, B_), 128>>>(qkv16, attnp, attn16);

    // 5) proj (+res y2, *gamma) -> f2 (+ fused LN2 -> fn16)
    gemm128<EPI_PROJ><<<dim3(TOKENS/128, 1), 256, SM128_BYTES>>>(
        attn16, 128, w_proj, 128, f2, 128, proj_b, gamma, nullptr, nullptr,
        y2f, 128, ln2_g, ln2_b, fn16);

    // 6) ffn1 + GELU
    gemm64<EPI_GELU><<<dim3(TOKENS/128, 4), 256, SM64_BYTES>>>(
        fn16, 128, w_f1, 128, h116, 256, ffn_b1, nullptr, nullptr, nullptr,
        nullptr, 0);

    // 7) ffn2 + bias + res f2 -> cat16[:,256:384]
    gemm64<EPI_FFN2><<<dim3(TOKENS/128, 2), 256, SM64_BYTES>>>(
        h116, 256, w_f2, 256, cat16 + 256, 384, ffn_b2, nullptr, nullptr, nullptr,
        f2, 128);

    // 8) cv2 + BN + SiLU -> NCHW out
    gemm64<EPI_NCHW><<<dim3(TOKENS/128, 4), 256, SM64_BYTES>>>(
        cat16, 384, w_cv2, 384, out, 0, bn2_g, bn2_b, bn2_m, bn2_v,
        nullptr, 0);
}

// round 9
// speedup vs baseline: 1.1382x; 1.0656x over previous
#include <cuda_runtime.h>
#include <cuda_fp16.h>
#include <math.h>

#define B_ 16
#define C1_ 256
#define C2_ 256
#define H_ 64
#define W_ 64
#define NH_ 8
#define C_ 128
#define HD_ 16
#define HW_ (H_*W_)
#define TOKENS (B_*HW_)

typedef unsigned int u32;

// -------- static scratch -----------
__device__ __half g_xt16  [(size_t)TOKENS*256];
__device__ __half g_cat16 [(size_t)TOKENS*384];
__device__ float  g_y2f   [(size_t)TOKENS*128];
__device__ __half g_fn16  [(size_t)TOKENS*128];
__device__ __half g_qkv16 [(size_t)TOKENS*384];
__device__ float  g_attnp [(size_t)TOKENS*128];
__device__ __half g_attn16[(size_t)TOKENS*128];
__device__ float  g_f2    [(size_t)TOKENS*128];
__device__ __half g_w16[65536+49152+16384+32768+32768+98304];

// ---------------------------------------------------------------------------
__device__ __forceinline__ u32 smem_u32(const void* p) {
    u32 a;
    asm("{ .reg .u64 t; cvta.to.shared.u64 t, %1; cvt.u32.u64 %0, t; }"
        : "=r"(a) : "l"(p));
    return a;
}
__device__ __forceinline__ void mma_fp16(float* c, const u32* a, const u32* b) {
    asm volatile(
        "mma.sync.aligned.m16n8k16.row.col.f32.f16.f16.f32 "
        "{%0,%1,%2,%3}, {%4,%5,%6,%7}, {%8,%9}, {%0,%1,%2,%3};"
        : "+f"(c[0]), "+f"(c[1]), "+f"(c[2]), "+f"(c[3])
        : "r"(a[0]), "r"(a[1]), "r"(a[2]), "r"(a[3]), "r"(b[0]), "r"(b[1]));
}
__device__ __forceinline__ void ldm_x4(u32& r0, u32& r1, u32& r2, u32& r3, u32 a) {
    asm volatile("ldmatrix.sync.aligned.m8n8.x4.shared.b16 {%0,%1,%2,%3}, [%4];"
        : "=r"(r0), "=r"(r1), "=r"(r2), "=r"(r3) : "r"(a));
}
__device__ __forceinline__ void ldm_x4t(u32& r0, u32& r1, u32& r2, u32& r3, u32 a) {
    asm volatile("ldmatrix.sync.aligned.m8n8.x4.trans.shared.b16 {%0,%1,%2,%3}, [%4];"
        : "=r"(r0), "=r"(r1), "=r"(r2), "=r"(r3) : "r"(a));
}
__device__ __forceinline__ void cp16(u32 dst, const void* src) {
    asm volatile("cp.async.cg.shared.global [%0], [%1], 16;" :: "r"(dst), "l"(src));
}

// ---------------------------------------------------------------------------
__global__ void convert_w_all(const float* __restrict__ s0, const float* __restrict__ s1,
                              const float* __restrict__ s2, const float* __restrict__ s3,
                              const float* __restrict__ s4, const float* __restrict__ s5,
                              __half* __restrict__ dst) {
    const int sizes[6] = {65536, 49152, 16384, 32768, 32768, 98304};
    const int offs [6] = {0, 65536, 114688, 131072, 163840, 196608};
    int t = blockIdx.y;
    const float* src = t == 0 ? s0 : t == 1 ? s1 : t == 2 ? s2 :
                       t == 3 ? s3 : t == 4 ? s4 : s5;
    int n2 = sizes[t] >> 1;
    int i = blockIdx.x * 256 + threadIdx.x;
    if (i < n2) {
        float2 v = *(const float2*)(src + 2 * i);
        *(__half2*)(dst + offs[t] + 2 * i) = __floats2half2_rn(v.x, v.y);
    }
}

__global__ void transpose_x_kernel(const float* __restrict__ x,
                                   __half* __restrict__ xt) {
    __shared__ float tile[32][33];
    int b  = blockIdx.z;
    int p0 = blockIdx.x * 32;
    int c0 = blockIdx.y * 32;
    const float* xb = x + (size_t)b * C1_ * HW_;
    __half*     xtb = xt + (size_t)b * HW_ * C1_;
#pragma unroll
    for (int i = 0; i < 32; i += 8)
        tile[threadIdx.y + i][threadIdx.x] =
            xb[(size_t)(c0 + threadIdx.y + i) * HW_ + p0 + threadIdx.x];
    __syncthreads();
#pragma unroll
    for (int i = 0; i < 32; i += 8)
        xtb[(size_t)(p0 + threadIdx.y + i) * C1_ + c0 + threadIdx.x] =
            __float2half_rn(tile[threadIdx.x][threadIdx.y + i]);
}

enum { EPI_CV1 = 0, EPI_QKV = 1, EPI_PROJ = 2, EPI_NCHW = 5 };

// ---------------------------------------------------------------------------
// gemm128: CTA 128x128, 8 warps (2m x 4n, warp 64x32). 2-stage (R6 config).
// ---------------------------------------------------------------------------
#define STG128 36864
#define SM128_BYTES (2*STG128)

template <int EPI>
__global__ void __launch_bounds__(256)
gemm128(const __half* __restrict__ A, int lda,
        const __half* __restrict__ Wt, int K,
        void* __restrict__ Cpv, int ldc,
        const float* __restrict__ p0, const float* __restrict__ p1,
        const float* __restrict__ p2, const float* __restrict__ p3,
        const float* __restrict__ Rs, int ldr,
        const float* __restrict__ lng, const float* __restrict__ lnb,
        __half* __restrict__ fnout) {
    extern __shared__ __align__(16) char smem[];
    const u32 sb = smem_u32(smem);
    const int tid = threadIdx.x, wid = tid >> 5, lane = tid & 31;
    const int wm = (wid >> 2) * 64, wn = (wid & 3) * 32;
    const int g = lane >> 2, t2 = lane & 3;
    const int row0 = blockIdx.x * 128, col0 = blockIdx.y * 128;
    const int lrow = tid >> 3, lc8 = tid & 7;

    float acc[4][4][4];
#pragma unroll
    for (int i = 0; i < 4; i++)
#pragma unroll
        for (int j = 0; j < 4; j++)
#pragma unroll
            for (int q = 0; q < 4; q++) acc[i][j][q] = 0.f;

    const int nch = K >> 6;
    auto issue = [&](int c) {
        u32 ab = sb + (c & 1) * STG128;
        u32 bb = ab + 18432;
        const __half* Ag = A  + (size_t)row0 * lda + c * 64;
        const __half* Bg = Wt + (size_t)col0 * K   + c * 64;
#pragma unroll
        for (int i = 0; i < 4; i++) {
            int r = i * 32 + lrow;
            cp16(ab + r * 144 + lc8 * 16, Ag + (size_t)r * lda + lc8 * 8);
            cp16(bb + r * 144 + lc8 * 16, Bg + (size_t)r * K   + lc8 * 8);
        }
    };

    issue(0);
    asm volatile("cp.async.commit_group;");
    for (int c = 0; c < nch; c++) {
        if (c + 1 < nch) {
            issue(c + 1);
            asm volatile("cp.async.commit_group;");
            asm volatile("cp.async.wait_group 1;");
        } else {
            asm volatile("cp.async.wait_group 0;");
        }
        __syncthreads();
        u32 ab = sb + (c & 1) * STG128;
        u32 bb = ab + 18432;
#pragma unroll
        for (int kb = 0; kb < 4; kb++) {
            u32 a[4][4], b[4][2];
#pragma unroll
            for (int mf = 0; mf < 4; mf++) {
                int r = wm + mf * 16 + (lane & 7) + ((lane >> 3) & 1) * 8;
                ldm_x4(a[mf][0], a[mf][1], a[mf][2], a[mf][3],
                       ab + r * 144 + kb * 32 + (lane >> 4) * 16);
            }
#pragma unroll
            for (int np = 0; np < 2; np++) {
                int r = wn + np * 16 + (lane & 7) + ((lane >> 4) & 1) * 8;
                ldm_x4(b[2*np][0], b[2*np][1], b[2*np+1][0], b[2*np+1][1],
                       bb + r * 144 + kb * 32 + ((lane >> 3) & 1) * 16);
            }
#pragma unroll
            for (int mf = 0; mf < 4; mf++)
#pragma unroll
                for (int nf = 0; nf < 4; nf++)
                    mma_fp16(acc[mf][nf], a[mf], b[nf]);
        }
        __syncthreads();
    }

    float* stg = (float*)smem;
    const bool doLN = (EPI != EPI_CV1) || (blockIdx.y == 1);

#pragma unroll
    for (int mf = 0; mf < 4; mf++) {
#pragma unroll
        for (int nf = 0; nf < 4; nf++) {
            int lcol = wn + nf * 8 + t2 * 2;
            int col  = col0 + lcol;
            float e0 = 0.f, e1 = 0.f, f0 = 0.f, f1 = 0.f;
            if constexpr (EPI == EPI_CV1) {
                e0 = p0[col]     * rsqrtf(p3[col]     + 1e-5f);
                e1 = p0[col + 1] * rsqrtf(p3[col + 1] + 1e-5f);
                f0 = p1[col]     - p2[col]     * e0;
                f1 = p1[col + 1] - p2[col + 1] * e1;
            } else if constexpr (EPI == EPI_PROJ) {
                e0 = p0[col]; e1 = p0[col + 1];
                f0 = p1[col]; f1 = p1[col + 1];
            }
#pragma unroll
            for (int h = 0; h < 2; h++) {
                int r   = wm + mf * 16 + g + h * 8;
                int row = row0 + r;
                float v0 = acc[mf][nf][h * 2];
                float v1 = acc[mf][nf][h * 2 + 1];
                if constexpr (EPI == EPI_CV1) {
                    v0 = v0 * e0 + f0; v0 = v0 / (1.f + __expf(-v0));
                    v1 = v1 * e1 + f1; v1 = v1 / (1.f + __expf(-v1));
                    *(__half2*)((__half*)Cpv + (size_t)row * 384 + col) =
                        __floats2half2_rn(v0, v1);
                    if (col0 == 128)
                        *(float2*)(g_y2f + (size_t)row * 128 + lcol) =
                            make_float2(v0, v1);
                } else if constexpr (EPI == EPI_PROJ) {
                    float2 rs = *(const float2*)(Rs + (size_t)row * ldr + col);
                    v0 = rs.x + (v0 + e0) * f0;
                    v1 = rs.y + (v1 + e1) * f1;
                    *(float2*)((float*)Cpv + (size_t)row * ldc + col) =
                        make_float2(v0, v1);
                }
                if (doLN) {
                    stg[r * 129 + lcol]     = v0;
                    stg[r * 129 + lcol + 1] = v1;
                }
            }
        }
    }
    if (doLN) {
        __syncthreads();
#pragma unroll
        for (int rr = 0; rr < 16; rr++) {
            int r = wid * 16 + rr;
            float v[4];
            float s = 0.f;
#pragma unroll
            for (int i = 0; i < 4; i++) {
                v[i] = stg[r * 129 + lane + 32 * i];
                s += v[i];
            }
#pragma unroll
            for (int o = 16; o; o >>= 1) s += __shfl_xor_sync(~0u, s, o);
            float mu = s * (1.f / 128.f);
            float q = 0.f;
#pragma unroll
            for (int i = 0; i < 4; i++) { float d = v[i] - mu; q += d * d; }
#pragma unroll
            for (int o = 16; o; o >>= 1) q += __shfl_xor_sync(~0u, q, o);
            float rsd = rsqrtf(q * (1.f / 128.f) + 1e-5f);
#pragma unroll
            for (int i = 0; i < 4; i++) {
                int cc = lane + 32 * i;
                fnout[(size_t)(row0 + r) * 128 + cc] =
                    __float2half_rn((v[i] - mu) * rsd * lng[cc] + lnb[cc]);
            }
        }
    }
}

// ---------------------------------------------------------------------------
// gemm64: CTA 128x64, 8 warps (4m x 2n, warp 32x32). 2-stage (R6 config).
// ---------------------------------------------------------------------------
#define STG64 27648
#define SM64_BYTES (2*STG64)

template <int EPI>
__global__ void __launch_bounds__(256, 3)
gemm64(const __half* __restrict__ A, int lda,
       const __half* __restrict__ Wt, int K,
       void* __restrict__ Cpv, int ldc,
       const float* __restrict__ p0, const float* __restrict__ p1,
       const float* __restrict__ p2, const float* __restrict__ p3,
       const float* __restrict__ Rs, int ldr) {
    extern __shared__ __align__(16) char smem[];
    const u32 sb = smem_u32(smem);
    const int tid = threadIdx.x, wid = tid >> 5, lane = tid & 31;
    const int wm = (wid >> 1) * 32, wn = (wid & 1) * 32;
    const int g = lane >> 2, t2 = lane & 3;
    const int row0 = blockIdx.x * 128, col0 = blockIdx.y * 64;
    const int lrow = tid >> 3, lc8 = tid & 7;

    float acc[2][4][4];
#pragma unroll
    for (int i = 0; i < 2; i++)
#pragma unroll
        for (int j = 0; j < 4; j++)
#pragma unroll
            for (int q = 0; q < 4; q++) acc[i][j][q] = 0.f;

    const int nch = K >> 6;
    auto issue = [&](int c) {
        u32 ab = sb + (c & 1) * STG64;
        u32 bb = ab + 18432;
        const __half* Ag = A  + (size_t)row0 * lda + c * 64;
        const __half* Bg = Wt + (size_t)col0 * K   + c * 64;
#pragma unroll
        for (int i = 0; i < 4; i++) {
            int r = i * 32 + lrow;
            cp16(ab + r * 144 + lc8 * 16, Ag + (size_t)r * lda + lc8 * 8);
        }
#pragma unroll
        for (int i = 0; i < 2; i++) {
            int r = i * 32 + lrow;
            cp16(bb + r * 144 + lc8 * 16, Bg + (size_t)r * K + lc8 * 8);
        }
    };

    issue(0);
    asm volatile("cp.async.commit_group;");
    for (int c = 0; c < nch; c++) {
        if (c + 1 < nch) {
            issue(c + 1);
            asm volatile("cp.async.commit_group;");
            asm volatile("cp.async.wait_group 1;");
        } else {
            asm volatile("cp.async.wait_group 0;");
        }
        __syncthreads();
        u32 ab = sb + (c & 1) * STG64;
        u32 bb = ab + 18432;
#pragma unroll
        for (int kb = 0; kb < 4; kb++) {
            u32 a[2][4], b[4][2];
#pragma unroll
            for (int mf = 0; mf < 2; mf++) {
                int r = wm + mf * 16 + (lane & 7) + ((lane >> 3) & 1) * 8;
                ldm_x4(a[mf][0], a[mf][1], a[mf][2], a[mf][3],
                       ab + r * 144 + kb * 32 + (lane >> 4) * 16);
            }
#pragma unroll
            for (int np = 0; np < 2; np++) {
                int r = wn + np * 16 + (lane & 7) + ((lane >> 4) & 1) * 8;
                ldm_x4(b[2*np][0], b[2*np][1], b[2*np+1][0], b[2*np+1][1],
                       bb + r * 144 + kb * 32 + ((lane >> 3) & 1) * 16);
            }
#pragma unroll
            for (int mf = 0; mf < 2; mf++)
#pragma unroll
                for (int nf = 0; nf < 4; nf++)
                    mma_fp16(acc[mf][nf], a[mf], b[nf]);
        }
        __syncthreads();
    }

    if constexpr (EPI == EPI_NCHW) {
        float* stg = (float*)smem;
#pragma unroll
        for (int mf = 0; mf < 2; mf++)
#pragma unroll
            for (int nf = 0; nf < 4; nf++) {
                int r = wm + mf * 16 + g;
                int cl = wn + nf * 8 + t2 * 2;
                stg[r * 65 + cl]           = acc[mf][nf][0];
                stg[r * 65 + cl + 1]       = acc[mf][nf][1];
                stg[(r + 8) * 65 + cl]     = acc[mf][nf][2];
                stg[(r + 8) * 65 + cl + 1] = acc[mf][nf][3];
            }
        __syncthreads();
        float* Cp = (float*)Cpv;
        for (int it = 0; it < 32; it++) {
            int idx  = it * 256 + tid;
            int lcol = idx >> 7;
            int r    = idx & 127;
            int col  = col0 + lcol;
            int row  = row0 + r;
            float v  = stg[r * 65 + lcol];
            float sc = p0[col] * rsqrtf(p3[col] + 1e-5f);
            v = v * sc + (p1[col] - p2[col] * sc);
            v = v / (1.f + __expf(-v));
            Cp[(((size_t)(row >> 12)) * C2_ + col) * 4096 + (row & 4095)] = v;
        }
    } else {
#pragma unroll
        for (int mf = 0; mf < 2; mf++) {
#pragma unroll
            for (int nf = 0; nf < 4; nf++) {
                int col = col0 + wn + nf * 8 + t2 * 2;
                float e0 = p0[col], e1 = p0[col + 1];
#pragma unroll
                for (int h = 0; h < 2; h++) {
                    int row = row0 + wm + mf * 16 + g + h * 8;
                    float v0 = acc[mf][nf][h * 2] + e0;
                    float v1 = acc[mf][nf][h * 2 + 1] + e1;
                    *(__half2*)((__half*)Cpv + (size_t)row * ldc + col) =
                        __floats2half2_rn(v0, v1);
                }
            }
        }
    }
}

// ---------------------------------------------------------------------------
// ffn_fused: per 64 token rows, compute h1 = GELU(fn @ W1^T + b1) into SMEM,
// then out = f2 + h1 @ W2^T + b2 -> cat16[:,256:384]. 8 warps = 2m(32) x 4n(16).
// SMEM: fn tile 64x272B | W region 2x17408 (w1 dbuf) / 33792 (w2) | h1 64x528B.
// ---------------------------------------------------------------------------
#define FF_AOFF  0
#define FF_WOFF  17408
#define FF_H1OFF 52224
#define FF_SMEM  86016

__global__ void __launch_bounds__(256, 2)
ffn_fused(const __half* __restrict__ fn, const __half* __restrict__ w1,
          const __half* __restrict__ w2, const float* __restrict__ b1,
          const float* __restrict__ b2, const float* __restrict__ f2res,
          __half* __restrict__ outc) {
    extern __shared__ __align__(16) char smem[];
    const u32 sb = smem_u32(smem);
    const int tid = threadIdx.x, wid = tid >> 5, lane = tid & 31;
    const int wm = (wid >> 2) * 32, wn = (wid & 3) * 16;
    const int g = lane >> 2, t2 = lane & 3;
    const int row0 = blockIdx.x * 64;

    // load fn A-tile [64 x 128] (272B rows)
#pragma unroll
    for (int i = 0; i < 4; i++) {
        int idx = tid + i * 256;
        int r = idx >> 4, c = idx & 15;
        cp16(sb + FF_AOFF + r * 272 + c * 16,
             fn + (size_t)(row0 + r) * 128 + c * 8);
    }
    auto issueW1 = [&](int nc) {
        u32 d = sb + FF_WOFF + (u32)(nc & 1) * 17408;
#pragma unroll
        for (int i = 0; i < 4; i++) {
            int idx = tid + i * 256;
            int r = idx >> 4, c = idx & 15;
            cp16(d + r * 272 + c * 16, w1 + (size_t)(nc * 64 + r) * 128 + c * 8);
        }
    };
    issueW1(0);
    asm volatile("cp.async.commit_group;");
    issueW1(1);
    asm volatile("cp.async.commit_group;");

    float acc[2][2][4];
    // ---------------- phase B: ffn1 + GELU -> h1 smem ----------------
    for (int nc = 0; nc < 4; nc++) {
        if (nc < 3) asm volatile("cp.async.wait_group 1;");
        else        asm volatile("cp.async.wait_group 0;");
        __syncthreads();
#pragma unroll
        for (int i = 0; i < 2; i++)
#pragma unroll
            for (int j = 0; j < 2; j++)
#pragma unroll
                for (int q = 0; q < 4; q++) acc[i][j][q] = 0.f;
        u32 ab = sb + FF_AOFF;
        u32 bb = sb + FF_WOFF + (u32)(nc & 1) * 17408;
#pragma unroll
        for (int kb = 0; kb < 8; kb++) {
            u32 a[2][4], b[2][2];
#pragma unroll
            for (int mf = 0; mf < 2; mf++) {
                int r = wm + mf * 16 + (lane & 7) + ((lane >> 3) & 1) * 8;
                ldm_x4(a[mf][0], a[mf][1], a[mf][2], a[mf][3],
                       ab + r * 272 + kb * 32 + (lane >> 4) * 16);
            }
            {
                int r = wn + (lane & 7) + ((lane >> 4) & 1) * 8;
                ldm_x4(b[0][0], b[0][1], b[1][0], b[1][1],
                       bb + r * 272 + kb * 32 + ((lane >> 3) & 1) * 16);
            }
#pragma unroll
            for (int mf = 0; mf < 2; mf++)
#pragma unroll
                for (int nf = 0; nf < 2; nf++)
                    mma_fp16(acc[mf][nf], a[mf], b[nf]);
        }
        // GELU epilogue into h1 smem (528B rows)
#pragma unroll
        for (int mf = 0; mf < 2; mf++)
#pragma unroll
            for (int nf = 0; nf < 2; nf++) {
                int col = nc * 64 + wn + nf * 8 + t2 * 2;
                float e0 = b1[col], e1 = b1[col + 1];
#pragma unroll
                for (int h = 0; h < 2; h++) {
                    int r = wm + mf * 16 + g + h * 8;
                    float v0 = acc[mf][nf][h * 2] + e0;
                    float v1 = acc[mf][nf][h * 2 + 1] + e1;
                    v0 = 0.5f * v0 * (1.f + erff(v0 * 0.70710678118654752f));
                    v1 = 0.5f * v1 * (1.f + erff(v1 * 0.70710678118654752f));
                    *(__half2*)(smem + FF_H1OFF + r * 528 + col * 2) =
                        __floats2half2_rn(v0, v1);
                }
            }
        __syncthreads();
        if (nc + 2 < 4) {
            issueW1(nc + 2);
            asm volatile("cp.async.commit_group;");
        }
    }
    // h1 complete & visible (trailing __syncthreads of nc=3)

    // ---------------- phase C: ffn2 + bias + residual ----------------
    for (int nc2 = 0; nc2 < 2; nc2++) {
#pragma unroll
        for (int i = 0; i < 8; i++) {
            int idx = tid + i * 256;
            int r = idx >> 5, c = idx & 31;
            cp16(sb + FF_WOFF + r * 528 + c * 16,
                 w2 + (size_t)(nc2 * 64 + r) * 256 + c * 8);
        }
        asm volatile("cp.async.commit_group;");
        asm volatile("cp.async.wait_group 0;");
        __syncthreads();
#pragma unroll
        for (int i = 0; i < 2; i++)
#pragma unroll
            for (int j = 0; j < 2; j++)
#pragma unroll
                for (int q = 0; q < 4; q++) acc[i][j][q] = 0.f;
        u32 ab = sb + FF_H1OFF;
        u32 bb = sb + FF_WOFF;
#pragma unroll
        for (int kb = 0; kb < 16; kb++) {
            u32 a[2][4], b[2][2];
#pragma unroll
            for (int mf = 0; mf < 2; mf++) {
                int r = wm + mf * 16 + (lane & 7) + ((lane >> 3) & 1) * 8;
                ldm_x4(a[mf][0], a[mf][1], a[mf][2], a[mf][3],
                       ab + r * 528 + kb * 32 + (lane >> 4) * 16);
            }
            {
                int r = wn + (lane & 7) + ((lane >> 4) & 1) * 8;
                ldm_x4(b[0][0], b[0][1], b[1][0], b[1][1],
                       bb + r * 528 + kb * 32 + ((lane >> 3) & 1) * 16);
            }
#pragma unroll
            for (int mf = 0; mf < 2; mf++)
#pragma unroll
                for (int nf = 0; nf < 2; nf++)
                    mma_fp16(acc[mf][nf], a[mf], b[nf]);
        }
        __syncthreads();   // all reads of w2 slot done before next load
#pragma unroll
        for (int mf = 0; mf < 2; mf++)
#pragma unroll
            for (int nf = 0; nf < 2; nf++) {
                int col = nc2 * 64 + wn + nf * 8 + t2 * 2;
                float e0 = b2[col], e1 = b2[col + 1];
#pragma unroll
                for (int h = 0; h < 2; h++) {
                    int row = row0 + wm + mf * 16 + g + h * 8;
                    float2 rs = *(const float2*)(f2res + (size_t)row * 128 + col);
                    float v0 = acc[mf][nf][h * 2] + e0 + rs.x;
                    float v1 = acc[mf][nf][h * 2 + 1] + e1 + rs.y;
                    *(__half2*)(outc + (size_t)row * 384 + 256 + col) =
                        __floats2half2_rn(v0, v1);
                }
            }
    }
}

// ---------------------------------------------------------------------------
// Tensor-core retention attention. One warp per (b, head, fixed line).
// ---------------------------------------------------------------------------
template <int PASS>
__global__ void __launch_bounds__(128)
attn_mma(const __half* __restrict__ qkv,
         float* __restrict__ partial,
         __half* __restrict__ out16) {
    __shared__ __half sQ[4][64 * 24];
    __shared__ __half sK[4][64 * 24];
    __shared__ __half sV[4][64 * 24];
    __shared__ float decrow[64];

    const int tid = threadIdx.x, wid = tid >> 5, lane = tid & 31;
    const int g = lane >> 2, t2 = lane & 3;
    const int fixed = blockIdx.x * 4 + wid;
    const int n = blockIdx.y, b = blockIdx.z;

    if (tid < 64) {
        float dec = logf(1.f - exp2f(-2.f - 0.5f * (float)n));
        decrow[tid] = 0.5f * __expf(dec * (float)tid);
    }

#pragma unroll
    for (int tt = 0; tt < 2; tt++) {
        int t = lane + tt * 32;
        size_t tok = (PASS == 0) ? ((size_t)(b * 64 + t) * 64 + fixed)
                                 : ((size_t)(b * 64 + fixed) * 64 + t);
        const uint4* src = (const uint4*)(qkv + tok * 384 + n * HD_);
        *(uint4*)&sQ[wid][t * 24]     = src[0];
        *(uint4*)&sQ[wid][t * 24 + 8] = src[1];
        *(uint4*)&sK[wid][t * 24]     = src[16];
        *(uint4*)&sK[wid][t * 24 + 8] = src[17];
        *(uint4*)&sV[wid][t * 24]     = src[32];
        *(uint4*)&sV[wid][t * 24 + 8] = src[33];
    }
    __syncthreads();

    const u32 qb = smem_u32(&sQ[wid][0]);
    const u32 kb = smem_u32(&sK[wid][0]);
    const u32 vb = smem_u32(&sV[wid][0]);

    u32 qa[4][4];
#pragma unroll
    for (int mf = 0; mf < 4; mf++) {
        int r = mf * 16 + (lane & 7) + ((lane >> 3) & 1) * 8;
        ldm_x4(qa[mf][0], qa[mf][1], qa[mf][2], qa[mf][3],
               qb + r * 48 + (lane >> 4) * 16);
    }

    float oacc[4][2][4];
#pragma unroll
    for (int i = 0; i < 4; i++)
#pragma unroll
        for (int j = 0; j < 2; j++)
#pragma unroll
            for (int q = 0; q < 4; q++) oacc[i][j][q] = 0.f;

#pragma unroll
    for (int jb = 0; jb < 4; jb++) {
        u32 kf[4];
        {
            int r = jb * 16 + (lane & 7) + ((lane >> 4) & 1) * 8;
            ldm_x4(kf[0], kf[1], kf[2], kf[3],
                   kb + r * 48 + ((lane >> 3) & 1) * 16);
        }
        float s[4][2][4];
#pragma unroll
        for (int mf = 0; mf < 4; mf++)
#pragma unroll
            for (int np = 0; np < 2; np++) {
#pragma unroll
                for (int q = 0; q < 4; q++) s[mf][np][q] = 0.f;
                u32 bfrag[2] = { kf[2 * np], kf[2 * np + 1] };
                mma_fp16(s[mf][np], qa[mf], bfrag);
            }
        u32 aP[4][4];
#pragma unroll
        for (int mf = 0; mf < 4; mf++) {
#pragma unroll
            for (int np = 0; np < 2; np++) {
                int i0 = mf * 16 + g;
                int j0 = jb * 16 + np * 8 + t2 * 2;
                int d00 = i0 - j0;       d00 = d00 < 0 ? -d00 : d00;
                int d01 = i0 - j0 - 1;   d01 = d01 < 0 ? -d01 : d01;
                int d10 = i0 + 8 - j0;   d10 = d10 < 0 ? -d10 : d10;
                int d11 = i0 + 7 - j0;   d11 = d11 < 0 ? -d11 : d11;
                s[mf][np][0] *= decrow[d00];
                s[mf][np][1] *= decrow[d01];
                s[mf][np][2] *= decrow[d10];
                s[mf][np][3] *= decrow[d11];
            }
            __half2 h;
            h = __floats2half2_rn(s[mf][0][0], s[mf][0][1]); aP[mf][0] = *(u32*)&h;
            h = __floats2half2_rn(s[mf][0][2], s[mf][0][3]); aP[mf][1] = *(u32*)&h;
            h = __floats2half2_rn(s[mf][1][0], s[mf][1][1]); aP[mf][2] = *(u32*)&h;
            h = __floats2half2_rn(s[mf][1][2], s[mf][1][3]); aP[mf][3] = *(u32*)&h;
        }
        u32 vf[4];
        {
            int r = jb * 16 + (lane & 7) + ((lane >> 3) & 1) * 8;
            ldm_x4t(vf[0], vf[1], vf[2], vf[3],
                    vb + r * 48 + (lane >> 4) * 16);
        }
#pragma unroll
        for (int mf = 0; mf < 4; mf++)
#pragma unroll
            for (int np = 0; np < 2; np++) {
                u32 bfrag[2] = { vf[2 * np], vf[2 * np + 1] };
                mma_fp16(oacc[mf][np], aP[mf], bfrag);
            }
    }

#pragma unroll
    for (int mf = 0; mf < 4; mf++)
#pragma unroll
        for (int np = 0; np < 2; np++) {
            int ch = n * HD_ + np * 8 + t2 * 2;
#pragma unroll
            for (int h = 0; h < 2; h++) {
                int i = mf * 16 + g + h * 8;
                size_t tok = (PASS == 0) ? ((size_t)(b * 64 + i) * 64 + fixed)
                                         : ((size_t)(b * 64 + fixed) * 64 + i);
                float v0 = oacc[mf][np][h * 2];
                float v1 = oacc[mf][np][h * 2 + 1];
                if (PASS == 0) {
                    *(float2*)(partial + tok * 128 + ch) = make_float2(v0, v1);
                } else {
                    float2 pr = *(const float2*)(partial + tok * 128 + ch);
                    *(__half2*)(out16 + tok * 128 + ch) =
                        __floats2half2_rn(pr.x + v0, pr.y + v1);
                }
            }
        }
}

// ---------------------------------------------------------------------------
extern "C" void kernel_launch(void* const* d_in, const int* in_sizes, int n_in,
                              void* d_out, int out_size) {
    const float* x      = (const float*)d_in[0];
    const float* cv1_w  = (const float*)d_in[1];
    const float* bn1_g  = (const float*)d_in[2];
    const float* bn1_b  = (const float*)d_in[3];
    const float* bn1_m  = (const float*)d_in[4];
    const float* bn1_v  = (const float*)d_in[5];
    const float* cv2_w  = (const float*)d_in[6];
    const float* bn2_g  = (const float*)d_in[7];
    const float* bn2_b  = (const float*)d_in[8];
    const float* bn2_m  = (const float*)d_in[9];
    const float* bn2_v  = (const float*)d_in[10];
    const float* ln1_g  = (const float*)d_in[11];
    const float* ln1_b  = (const float*)d_in[12];
    const float* qkv_w  = (const float*)d_in[13];
    const float* qkv_b  = (const float*)d_in[14];
    const float* proj_w = (const float*)d_in[15];
    const float* proj_b = (const float*)d_in[16];
    const float* gamma  = (const float*)d_in[17];
    const float* ln2_g  = (const float*)d_in[18];
    const float* ln2_b  = (const float*)d_in[19];
    const float* ffn_w1 = (const float*)d_in[20];
    const float* ffn_b1 = (const float*)d_in[21];
    const float* ffn_w2 = (const float*)d_in[22];
    const float* ffn_b2 = (const float*)d_in[23];
    float* out = (float*)d_out;

    __half *xt16, *cat16, *fn16, *qkv16, *attn16, *w16;
    float *y2f, *attnp, *f2;
    cudaGetSymbolAddress((void**)&xt16,   g_xt16);
    cudaGetSymbolAddress((void**)&cat16,  g_cat16);
    cudaGetSymbolAddress((void**)&y2f,    g_y2f);
    cudaGetSymbolAddress((void**)&fn16,   g_fn16);
    cudaGetSymbolAddress((void**)&qkv16,  g_qkv16);
    cudaGetSymbolAddress((void**)&attnp,  g_attnp);
    cudaGetSymbolAddress((void**)&attn16, g_attn16);
    cudaGetSymbolAddress((void**)&f2,     g_f2);
    cudaGetSymbolAddress((void**)&w16,    g_w16);

    __half* w_cv1  = w16;
    __half* w_qkv  = w_cv1 + 65536;
    __half* w_proj = w_qkv + 49152;
    __half* w_f1   = w_proj + 16384;
    __half* w_f2   = w_f1 + 32768;
    __half* w_cv2  = w_f2 + 32768;

    cudaFuncSetAttribute(gemm128<EPI_CV1>,  cudaFuncAttributeMaxDynamicSharedMemorySize, SM128_BYTES);
    cudaFuncSetAttribute(gemm128<EPI_PROJ>, cudaFuncAttributeMaxDynamicSharedMemorySize, SM128_BYTES);
    cudaFuncSetAttribute(gemm64<EPI_QKV>,   cudaFuncAttributeMaxDynamicSharedMemorySize, SM64_BYTES);
    cudaFuncSetAttribute(gemm64<EPI_NCHW>,  cudaFuncAttributeMaxDynamicSharedMemorySize, SM64_BYTES);
    cudaFuncSetAttribute(ffn_fused,         cudaFuncAttributeMaxDynamicSharedMemorySize, FF_SMEM);

    // 0) weights -> fp16
    convert_w_all<<<dim3(192, 6), 256>>>(cv1_w, qkv_w, proj_w, ffn_w1, ffn_w2,
                                         cv2_w, w16);

    // 1) x NCHW -> xt16
    transpose_x_kernel<<<dim3(HW_/32, C1_/32, B_), dim3(32, 8)>>>(x, xt16);

    // 2) cv1 + BN + SiLU -> cat16[:,0:256] (+ y2f, + fused LN1 -> fn16)
    gemm128<EPI_CV1><<<dim3(TOKENS/128, 2), 256, SM128_BYTES>>>(
        xt16, 256, w_cv1, 256, cat16, 384, bn1_g, bn1_b, bn1_m, bn1_v,
        nullptr, 0, ln1_g, ln1_b, fn16);

    // 3) qkv
    gemm64<EPI_QKV><<<dim3(TOKENS/128, 6), 256, SM64_BYTES>>>(
        fn16, 128, w_qkv, 128, qkv16, 384, qkv_b, nullptr, nullptr, nullptr,
        nullptr, 0);

    // 4) attention H then W
    attn_mma<0><<<dim3(16, NH_, B_), 128>>>(qkv16, attnp, attn16);
    attn_mma<1><<<dim3(16, NH_, B_), 128>>>(qkv16, attnp, attn16);

    // 5) proj (+res y2, *gamma) -> f2 (+ fused LN2 -> fn16)
    gemm128<EPI_PROJ><<<dim3(TOKENS/128, 1), 256, SM128_BYTES>>>(
        attn16, 128, w_proj, 128, f2, 128, proj_b, gamma, nullptr, nullptr,
        y2f, 128, ln2_g, ln2_b, fn16);

    // 6) fused ffn1(GELU)+ffn2 (+res f2) -> cat16[:,256:384]
    ffn_fused<<<TOKENS/64, 256, FF_SMEM>>>(
        fn16, w_f1, w_f2, ffn_b1, ffn_b2, f2, cat16);

    // 7) cv2 + BN + SiLU -> NCHW out
    gemm64<EPI_NCHW><<<dim3(TOKENS/128, 4), 256, SM64_BYTES>>>(
        cat16, 384, w_cv2, 384, out, 0, bn2_g, bn2_b, bn2_m, bn2_v,
        nullptr, 0);
}

// round 11
// speedup vs baseline: 1.1934x; 1.0486x over previous
#include <cuda_runtime.h>
#include <cuda_fp16.h>
#include <math.h>

#define B_ 16
#define C1_ 256
#define C2_ 256
#define H_ 64
#define W_ 64
#define NH_ 8
#define C_ 128
#define HD_ 16
#define HW_ (H_*W_)
#define TOKENS (B_*HW_)

typedef unsigned int u32;

// -------- static scratch -----------
__device__ __half g_xt16  [(size_t)TOKENS*256];
__device__ __half g_cat16 [(size_t)TOKENS*384];
__device__ float  g_y2f   [(size_t)TOKENS*128];
__device__ __half g_fn16  [(size_t)TOKENS*128];   // LN2 output only
__device__ __half g_qkv16 [(size_t)TOKENS*384];
__device__ float  g_attnp [(size_t)TOKENS*128];
__device__ __half g_attn16[(size_t)TOKENS*128];
__device__ float  g_f2    [(size_t)TOKENS*128];
__device__ __half g_w16[65536+49152+16384+32768+32768+98304];

// ---------------------------------------------------------------------------
__device__ __forceinline__ u32 smem_u32(const void* p) {
    u32 a;
    asm("{ .reg .u64 t; cvta.to.shared.u64 t, %1; cvt.u32.u64 %0, t; }"
        : "=r"(a) : "l"(p));
    return a;
}
__device__ __forceinline__ void mma_fp16(float* c, const u32* a, const u32* b) {
    asm volatile(
        "mma.sync.aligned.m16n8k16.row.col.f32.f16.f16.f32 "
        "{%0,%1,%2,%3}, {%4,%5,%6,%7}, {%8,%9}, {%0,%1,%2,%3};"
        : "+f"(c[0]), "+f"(c[1]), "+f"(c[2]), "+f"(c[3])
        : "r"(a[0]), "r"(a[1]), "r"(a[2]), "r"(a[3]), "r"(b[0]), "r"(b[1]));
}
__device__ __forceinline__ void ldm_x4(u32& r0, u32& r1, u32& r2, u32& r3, u32 a) {
    asm volatile("ldmatrix.sync.aligned.m8n8.x4.shared.b16 {%0,%1,%2,%3}, [%4];"
        : "=r"(r0), "=r"(r1), "=r"(r2), "=r"(r3) : "r"(a));
}
__device__ __forceinline__ void ldm_x4t(u32& r0, u32& r1, u32& r2, u32& r3, u32 a) {
    asm volatile("ldmatrix.sync.aligned.m8n8.x4.trans.shared.b16 {%0,%1,%2,%3}, [%4];"
        : "=r"(r0), "=r"(r1), "=r"(r2), "=r"(r3) : "r"(a));
}
__device__ __forceinline__ void cp16(u32 dst, const void* src) {
    asm volatile("cp.async.cg.shared.global [%0], [%1], 16;" :: "r"(dst), "l"(src));
}

// ---------------------------------------------------------------------------
__global__ void convert_w_all(const float* __restrict__ s0, const float* __restrict__ s1,
                              const float* __restrict__ s2, const float* __restrict__ s3,
                              const float* __restrict__ s4, const float* __restrict__ s5,
                              __half* __restrict__ dst) {
    const int sizes[6] = {65536, 49152, 16384, 32768, 32768, 98304};
    const int offs [6] = {0, 65536, 114688, 131072, 163840, 196608};
    int t = blockIdx.y;
    const float* src = t == 0 ? s0 : t == 1 ? s1 : t == 2 ? s2 :
                       t == 3 ? s3 : t == 4 ? s4 : s5;
    int n2 = sizes[t] >> 1;
    int i = blockIdx.x * 256 + threadIdx.x;
    if (i < n2) {
        float2 v = *(const float2*)(src + 2 * i);
        *(__half2*)(dst + offs[t] + 2 * i) = __floats2half2_rn(v.x, v.y);
    }
}

__global__ void transpose_x_kernel(const float* __restrict__ x,
                                   __half* __restrict__ xt) {
    __shared__ float tile[32][33];
    int b  = blockIdx.z;
    int p0 = blockIdx.x * 32;
    int c0 = blockIdx.y * 32;
    const float* xb = x + (size_t)b * C1_ * HW_;
    __half*     xtb = xt + (size_t)b * HW_ * C1_;
#pragma unroll
    for (int i = 0; i < 32; i += 8)
        tile[threadIdx.y + i][threadIdx.x] =
            xb[(size_t)(c0 + threadIdx.y + i) * HW_ + p0 + threadIdx.x];
    __syncthreads();
#pragma unroll
    for (int i = 0; i < 32; i += 8)
        xtb[(size_t)(p0 + threadIdx.y + i) * C1_ + c0 + threadIdx.x] =
            __float2half_rn(tile[threadIdx.x][threadIdx.y + i]);
}

enum { EPI_CV1 = 0, EPI_PROJ = 2, EPI_NCHW = 5 };

// ---------------------------------------------------------------------------
// gemm128: CTA 128x128, 8 warps (2m x 4n, warp 64x32). 2-stage cp.async.
// EPI_CV1 + blockIdx.y==1: fused register-LN1 + in-SMEM qkv GEMM (N=384).
// EPI_PROJ: smem-staged LN2 -> fnout.
// Fused-qkv smem layout (post-mainloop): partials 4096 | fnS 34816 | W dbuf 34816.
// ---------------------------------------------------------------------------
#define STG128 36864
#define SM128_BYTES (2*STG128)
#define FQ_FNS 4096
#define FQ_W   38912

template <int EPI>
__global__ void __launch_bounds__(256, 2)
gemm128(const __half* __restrict__ A, int lda,
        const __half* __restrict__ Wt, int K,
        void* __restrict__ Cpv, int ldc,
        const float* __restrict__ p0, const float* __restrict__ p1,
        const float* __restrict__ p2, const float* __restrict__ p3,
        const float* __restrict__ Rs, int ldr,
        const float* __restrict__ lng, const float* __restrict__ lnb,
        __half* __restrict__ fnout,
        const __half* __restrict__ Wq, const float* __restrict__ qbias,
        __half* __restrict__ qkvout) {
    extern __shared__ __align__(16) char smem[];
    const u32 sb = smem_u32(smem);
    const int tid = threadIdx.x, wid = tid >> 5, lane = tid & 31;
    const int wm = (wid >> 2) * 64, wn = (wid & 3) * 32;
    const int g = lane >> 2, t2 = lane & 3;
    const int row0 = blockIdx.x * 128, col0 = blockIdx.y * 128;
    const int lrow = tid >> 3, lc8 = tid & 7;

    float acc[4][4][4];
#pragma unroll
    for (int i = 0; i < 4; i++)
#pragma unroll
        for (int j = 0; j < 4; j++)
#pragma unroll
            for (int q = 0; q < 4; q++) acc[i][j][q] = 0.f;

    const int nch = K >> 6;
    auto issue = [&](int c) {
        u32 ab = sb + (c & 1) * STG128;
        u32 bb = ab + 18432;
        const __half* Ag = A  + (size_t)row0 * lda + c * 64;
        const __half* Bg = Wt + (size_t)col0 * K   + c * 64;
#pragma unroll
        for (int i = 0; i < 4; i++) {
            int r = i * 32 + lrow;
            cp16(ab + r * 144 + lc8 * 16, Ag + (size_t)r * lda + lc8 * 8);
            cp16(bb + r * 144 + lc8 * 16, Bg + (size_t)r * K   + lc8 * 8);
        }
    };

    issue(0);
    asm volatile("cp.async.commit_group;");
    for (int c = 0; c < nch; c++) {
        if (c + 1 < nch) {
            issue(c + 1);
            asm volatile("cp.async.commit_group;");
            asm volatile("cp.async.wait_group 1;");
        } else {
            asm volatile("cp.async.wait_group 0;");
        }
        __syncthreads();
        u32 ab = sb + (c & 1) * STG128;
        u32 bb = ab + 18432;
#pragma unroll
        for (int kb = 0; kb < 4; kb++) {
            u32 a[4][4], b[4][2];
#pragma unroll
            for (int mf = 0; mf < 4; mf++) {
                int r = wm + mf * 16 + (lane & 7) + ((lane >> 3) & 1) * 8;
                ldm_x4(a[mf][0], a[mf][1], a[mf][2], a[mf][3],
                       ab + r * 144 + kb * 32 + (lane >> 4) * 16);
            }
#pragma unroll
            for (int np = 0; np < 2; np++) {
                int r = wn + np * 16 + (lane & 7) + ((lane >> 4) & 1) * 8;
                ldm_x4(b[2*np][0], b[2*np][1], b[2*np+1][0], b[2*np+1][1],
                       bb + r * 144 + kb * 32 + ((lane >> 3) & 1) * 16);
            }
#pragma unroll
            for (int mf = 0; mf < 4; mf++)
#pragma unroll
                for (int nf = 0; nf < 4; nf++)
                    mma_fp16(acc[mf][nf], a[mf], b[nf]);
        }
        __syncthreads();
    }

    const bool fuseQ = (EPI == EPI_CV1) && (blockIdx.y == 1);

    auto issueWq = [&](int nc) {
        u32 d = sb + FQ_W + (u32)(nc & 1) * 17408;
#pragma unroll
        for (int i = 0; i < 4; i++) {
            int idx = tid + i * 256;
            int r = idx >> 4, c2 = idx & 15;
            cp16(d + r * 272 + c2 * 16, Wq + (size_t)(nc * 64 + r) * 128 + c2 * 8);
        }
    };
    if (fuseQ) {
        issueWq(0);
        asm volatile("cp.async.commit_group;");
        issueWq(1);
        asm volatile("cp.async.commit_group;");
    }

    if constexpr (EPI == EPI_CV1) {
        // BN + SiLU epilogue; keep post-activation values in acc for LN.
#pragma unroll
        for (int mf = 0; mf < 4; mf++) {
#pragma unroll
            for (int nf = 0; nf < 4; nf++) {
                int lcol = wn + nf * 8 + t2 * 2;
                int col  = col0 + lcol;
                float e0 = p0[col]     * rsqrtf(p3[col]     + 1e-5f);
                float e1 = p0[col + 1] * rsqrtf(p3[col + 1] + 1e-5f);
                float f0 = p1[col]     - p2[col]     * e0;
                float f1 = p1[col + 1] - p2[col + 1] * e1;
#pragma unroll
                for (int h = 0; h < 2; h++) {
                    int row = row0 + wm + mf * 16 + g + h * 8;
                    float v0 = acc[mf][nf][h * 2]     * e0 + f0;
                    float v1 = acc[mf][nf][h * 2 + 1] * e1 + f1;
                    v0 = v0 / (1.f + __expf(-v0));
                    v1 = v1 / (1.f + __expf(-v1));
                    *(__half2*)((__half*)Cpv + (size_t)row * 384 + col) =
                        __floats2half2_rn(v0, v1);
                    if (fuseQ)
                        *(float2*)(g_y2f + (size_t)row * 128 + lcol) =
                            make_float2(v0, v1);
                    acc[mf][nf][h * 2]     = v0;
                    acc[mf][nf][h * 2 + 1] = v1;
                }
            }
        }
        if (fuseQ) {
            // ---- register LayerNorm with 4KB smem partials ----
            float* part = (float*)smem;   // [128 rows][4 wn-groups][2]
#pragma unroll
            for (int mf = 0; mf < 4; mf++)
#pragma unroll
                for (int h = 0; h < 2; h++) {
                    float s = 0.f, qq = 0.f;
#pragma unroll
                    for (int nf = 0; nf < 4; nf++) {
                        float a0 = acc[mf][nf][h * 2];
                        float a1 = acc[mf][nf][h * 2 + 1];
                        s += a0 + a1;
                        qq += a0 * a0 + a1 * a1;
                    }
                    s  += __shfl_xor_sync(~0u, s, 1);
                    s  += __shfl_xor_sync(~0u, s, 2);
                    qq += __shfl_xor_sync(~0u, qq, 1);
                    qq += __shfl_xor_sync(~0u, qq, 2);
                    if (t2 == 0) {
                        int r = wm + mf * 16 + g + h * 8;
                        part[r * 8 + (wid & 3) * 2]     = s;
                        part[r * 8 + (wid & 3) * 2 + 1] = qq;
                    }
                }
            __syncthreads();
#pragma unroll
            for (int mf = 0; mf < 4; mf++)
#pragma unroll
                for (int h = 0; h < 2; h++) {
                    int r = wm + mf * 16 + g + h * 8;
                    float s  = part[r*8] + part[r*8+2] + part[r*8+4] + part[r*8+6];
                    float qq = part[r*8+1] + part[r*8+3] + part[r*8+5] + part[r*8+7];
                    float mu  = s * (1.f / 128.f);
                    float var = qq * (1.f / 128.f) - mu * mu;
                    float rsd = rsqrtf(var + 1e-5f);
#pragma unroll
                    for (int nf = 0; nf < 4; nf++) {
                        int lcol = wn + nf * 8 + t2 * 2;
                        float f0 = (acc[mf][nf][h*2]   - mu) * rsd * lng[lcol]   + lnb[lcol];
                        float f1 = (acc[mf][nf][h*2+1] - mu) * rsd * lng[lcol+1] + lnb[lcol+1];
                        *(__half2*)(smem + FQ_FNS + r * 272 + lcol * 2) =
                            __floats2half2_rn(f0, f1);
                    }
                }
            __syncthreads();   // fnS complete

            // ---- fused qkv GEMM: [128 x 384] = fnS[128x128] @ Wq^T ----
            const int wm2 = (wid >> 1) * 32, wn2 = (wid & 1) * 32;
            for (int nc = 0; nc < 6; nc++) {
                if (nc < 5) asm volatile("cp.async.wait_group 1;");
                else        asm volatile("cp.async.wait_group 0;");
                __syncthreads();
                float qa[2][4][4];
#pragma unroll
                for (int i = 0; i < 2; i++)
#pragma unroll
                    for (int j = 0; j < 4; j++)
#pragma unroll
                        for (int q = 0; q < 4; q++) qa[i][j][q] = 0.f;
                u32 ab2 = sb + FQ_FNS;
                u32 bb2 = sb + FQ_W + (u32)(nc & 1) * 17408;
#pragma unroll
                for (int kb = 0; kb < 8; kb++) {
                    u32 a[2][4], b[4][2];
#pragma unroll
                    for (int mf = 0; mf < 2; mf++) {
                        int r = wm2 + mf * 16 + (lane & 7) + ((lane >> 3) & 1) * 8;
                        ldm_x4(a[mf][0], a[mf][1], a[mf][2], a[mf][3],
                               ab2 + r * 272 + kb * 32 + (lane >> 4) * 16);
                    }
#pragma unroll
                    for (int np = 0; np < 2; np++) {
                        int r = wn2 + np * 16 + (lane & 7) + ((lane >> 4) & 1) * 8;
                        ldm_x4(b[2*np][0], b[2*np][1], b[2*np+1][0], b[2*np+1][1],
                               bb2 + r * 272 + kb * 32 + ((lane >> 3) & 1) * 16);
                    }
#pragma unroll
                    for (int mf = 0; mf < 2; mf++)
#pragma unroll
                        for (int nf = 0; nf < 4; nf++)
                            mma_fp16(qa[mf][nf], a[mf], b[nf]);
                }
#pragma unroll
                for (int mf = 0; mf < 2; mf++)
#pragma unroll
                    for (int nf = 0; nf < 4; nf++) {
                        int col = nc * 64 + wn2 + nf * 8 + t2 * 2;
                        float e0 = qbias[col], e1 = qbias[col + 1];
#pragma unroll
                        for (int h = 0; h < 2; h++) {
                            int row = row0 + wm2 + mf * 16 + g + h * 8;
                            *(__half2*)(qkvout + (size_t)row * 384 + col) =
                                __floats2half2_rn(qa[mf][nf][h*2] + e0,
                                                  qa[mf][nf][h*2+1] + e1);
                        }
                    }
                __syncthreads();
                if (nc + 2 < 6) {
                    issueWq(nc + 2);
                    asm volatile("cp.async.commit_group;");
                }
            }
        }
    } else {   // EPI_PROJ: epilogue + smem-staged LN2
        float* stg = (float*)smem;
#pragma unroll
        for (int mf = 0; mf < 4; mf++) {
#pragma unroll
            for (int nf = 0; nf < 4; nf++) {
                int lcol = wn + nf * 8 + t2 * 2;
                int col  = col0 + lcol;
                float e0 = p0[col], e1 = p0[col + 1];
                float f0 = p1[col], f1 = p1[col + 1];
#pragma unroll
                for (int h = 0; h < 2; h++) {
                    int r   = wm + mf * 16 + g + h * 8;
                    int row = row0 + r;
                    float2 rs = *(const float2*)(Rs + (size_t)row * ldr + col);
                    float v0 = rs.x + (acc[mf][nf][h*2]   + e0) * f0;
                    float v1 = rs.y + (acc[mf][nf][h*2+1] + e1) * f1;
                    *(float2*)((float*)Cpv + (size_t)row * ldc + col) =
                        make_float2(v0, v1);
                    stg[r * 129 + lcol]     = v0;
                    stg[r * 129 + lcol + 1] = v1;
                }
            }
        }
        __syncthreads();
#pragma unroll
        for (int rr = 0; rr < 16; rr++) {
            int r = wid * 16 + rr;
            float v[4];
            float s = 0.f;
#pragma unroll
            for (int i = 0; i < 4; i++) {
                v[i] = stg[r * 129 + lane + 32 * i];
                s += v[i];
            }
#pragma unroll
            for (int o = 16; o; o >>= 1) s += __shfl_xor_sync(~0u, s, o);
            float mu = s * (1.f / 128.f);
            float q = 0.f;
#pragma unroll
            for (int i = 0; i < 4; i++) { float d = v[i] - mu; q += d * d; }
#pragma unroll
            for (int o = 16; o; o >>= 1) q += __shfl_xor_sync(~0u, q, o);
            float rsd = rsqrtf(q * (1.f / 128.f) + 1e-5f);
#pragma unroll
            for (int i = 0; i < 4; i++) {
                int cc = lane + 32 * i;
                fnout[(size_t)(row0 + r) * 128 + cc] =
                    __float2half_rn((v[i] - mu) * rsd * lng[cc] + lnb[cc]);
            }
        }
    }
}

// ---------------------------------------------------------------------------
// gemm64: CTA 128x64, 8 warps (4m x 2n, warp 32x32). 2-stage. cv2-NCHW only.
// ---------------------------------------------------------------------------
#define STG64 27648
#define SM64_BYTES (2*STG64)

__global__ void __launch_bounds__(256, 3)
gemm64_nchw(const __half* __restrict__ A, int lda,
            const __half* __restrict__ Wt, int K,
            float* __restrict__ Cp,
            const float* __restrict__ p0, const float* __restrict__ p1,
            const float* __restrict__ p2, const float* __restrict__ p3) {
    extern __shared__ __align__(16) char smem[];
    const u32 sb = smem_u32(smem);
    const int tid = threadIdx.x, wid = tid >> 5, lane = tid & 31;
    const int wm = (wid >> 1) * 32, wn = (wid & 1) * 32;
    const int g = lane >> 2, t2 = lane & 3;
    const int row0 = blockIdx.x * 128, col0 = blockIdx.y * 64;
    const int lrow = tid >> 3, lc8 = tid & 7;

    float acc[2][4][4];
#pragma unroll
    for (int i = 0; i < 2; i++)
#pragma unroll
        for (int j = 0; j < 4; j++)
#pragma unroll
            for (int q = 0; q < 4; q++) acc[i][j][q] = 0.f;

    const int nch = K >> 6;
    auto issue = [&](int c) {
        u32 ab = sb + (c & 1) * STG64;
        u32 bb = ab + 18432;
        const __half* Ag = A  + (size_t)row0 * lda + c * 64;
        const __half* Bg = Wt + (size_t)col0 * K   + c * 64;
#pragma unroll
        for (int i = 0; i < 4; i++) {
            int r = i * 32 + lrow;
            cp16(ab + r * 144 + lc8 * 16, Ag + (size_t)r * lda + lc8 * 8);
        }
#pragma unroll
        for (int i = 0; i < 2; i++) {
            int r = i * 32 + lrow;
            cp16(bb + r * 144 + lc8 * 16, Bg + (size_t)r * K + lc8 * 8);
        }
    };

    issue(0);
    asm volatile("cp.async.commit_group;");
    for (int c = 0; c < nch; c++) {
        if (c + 1 < nch) {
            issue(c + 1);
            asm volatile("cp.async.commit_group;");
            asm volatile("cp.async.wait_group 1;");
        } else {
            asm volatile("cp.async.wait_group 0;");
        }
        __syncthreads();
        u32 ab = sb + (c & 1) * STG64;
        u32 bb = ab + 18432;
#pragma unroll
        for (int kb = 0; kb < 4; kb++) {
            u32 a[2][4], b[4][2];
#pragma unroll
            for (int mf = 0; mf < 2; mf++) {
                int r = wm + mf * 16 + (lane & 7) + ((lane >> 3) & 1) * 8;
                ldm_x4(a[mf][0], a[mf][1], a[mf][2], a[mf][3],
                       ab + r * 144 + kb * 32 + (lane >> 4) * 16);
            }
#pragma unroll
            for (int np = 0; np < 2; np++) {
                int r = wn + np * 16 + (lane & 7) + ((lane >> 4) & 1) * 8;
                ldm_x4(b[2*np][0], b[2*np][1], b[2*np+1][0], b[2*np+1][1],
                       bb + r * 144 + kb * 32 + ((lane >> 3) & 1) * 16);
            }
#pragma unroll
            for (int mf = 0; mf < 2; mf++)
#pragma unroll
                for (int nf = 0; nf < 4; nf++)
                    mma_fp16(acc[mf][nf], a[mf], b[nf]);
        }
        __syncthreads();
    }

    float* stg = (float*)smem;   // 128 x 65
#pragma unroll
    for (int mf = 0; mf < 2; mf++)
#pragma unroll
        for (int nf = 0; nf < 4; nf++) {
            int r = wm + mf * 16 + g;
            int cl = wn + nf * 8 + t2 * 2;
            stg[r * 65 + cl]           = acc[mf][nf][0];
            stg[r * 65 + cl + 1]       = acc[mf][nf][1];
            stg[(r + 8) * 65 + cl]     = acc[mf][nf][2];
            stg[(r + 8) * 65 + cl + 1] = acc[mf][nf][3];
        }
    __syncthreads();
    for (int it = 0; it < 32; it++) {
        int idx  = it * 256 + tid;
        int lcol = idx >> 7;
        int r    = idx & 127;
        int col  = col0 + lcol;
        int row  = row0 + r;
        float v  = stg[r * 65 + lcol];
        float sc = p0[col] * rsqrtf(p3[col] + 1e-5f);
        v = v * sc + (p1[col] - p2[col] * sc);
        v = v / (1.f + __expf(-v));
        Cp[(((size_t)(row >> 12)) * C2_ + col) * 4096 + (row & 4095)] = v;
    }
}

// ---------------------------------------------------------------------------
// ffn_fused (unchanged from R9)
// ---------------------------------------------------------------------------
#define FF_AOFF  0
#define FF_WOFF  17408
#define FF_H1OFF 52224
#define FF_SMEM  86016

__global__ void __launch_bounds__(256, 2)
ffn_fused(const __half* __restrict__ fn, const __half* __restrict__ w1,
          const __half* __restrict__ w2, const float* __restrict__ b1,
          const float* __restrict__ b2, const float* __restrict__ f2res,
          __half* __restrict__ outc) {
    extern __shared__ __align__(16) char smem[];
    const u32 sb = smem_u32(smem);
    const int tid = threadIdx.x, wid = tid >> 5, lane = tid & 31;
    const int wm = (wid >> 2) * 32, wn = (wid & 3) * 16;
    const int g = lane >> 2, t2 = lane & 3;
    const int row0 = blockIdx.x * 64;

#pragma unroll
    for (int i = 0; i < 4; i++) {
        int idx = tid + i * 256;
        int r = idx >> 4, c = idx & 15;
        cp16(sb + FF_AOFF + r * 272 + c * 16,
             fn + (size_t)(row0 + r) * 128 + c * 8);
    }
    auto issueW1 = [&](int nc) {
        u32 d = sb + FF_WOFF + (u32)(nc & 1) * 17408;
#pragma unroll
        for (int i = 0; i < 4; i++) {
            int idx = tid + i * 256;
            int r = idx >> 4, c = idx & 15;
            cp16(d + r * 272 + c * 16, w1 + (size_t)(nc * 64 + r) * 128 + c * 8);
        }
    };
    issueW1(0);
    asm volatile("cp.async.commit_group;");
    issueW1(1);
    asm volatile("cp.async.commit_group;");

    float acc[2][2][4];
    for (int nc = 0; nc < 4; nc++) {
        if (nc < 3) asm volatile("cp.async.wait_group 1;");
        else        asm volatile("cp.async.wait_group 0;");
        __syncthreads();
#pragma unroll
        for (int i = 0; i < 2; i++)
#pragma unroll
            for (int j = 0; j < 2; j++)
#pragma unroll
                for (int q = 0; q < 4; q++) acc[i][j][q] = 0.f;
        u32 ab = sb + FF_AOFF;
        u32 bb = sb + FF_WOFF + (u32)(nc & 1) * 17408;
#pragma unroll
        for (int kb = 0; kb < 8; kb++) {
            u32 a[2][4], b[2][2];
#pragma unroll
            for (int mf = 0; mf < 2; mf++) {
                int r = wm + mf * 16 + (lane & 7) + ((lane >> 3) & 1) * 8;
                ldm_x4(a[mf][0], a[mf][1], a[mf][2], a[mf][3],
                       ab + r * 272 + kb * 32 + (lane >> 4) * 16);
            }
            {
                int r = wn + (lane & 7) + ((lane >> 4) & 1) * 8;
                ldm_x4(b[0][0], b[0][1], b[1][0], b[1][1],
                       bb + r * 272 + kb * 32 + ((lane >> 3) & 1) * 16);
            }
#pragma unroll
            for (int mf = 0; mf < 2; mf++)
#pragma unroll
                for (int nf = 0; nf < 2; nf++)
                    mma_fp16(acc[mf][nf], a[mf], b[nf]);
        }
#pragma unroll
        for (int mf = 0; mf < 2; mf++)
#pragma unroll
            for (int nf = 0; nf < 2; nf++) {
                int col = nc * 64 + wn + nf * 8 + t2 * 2;
                float e0 = b1[col], e1 = b1[col + 1];
#pragma unroll
                for (int h = 0; h < 2; h++) {
                    int r = wm + mf * 16 + g + h * 8;
                    float v0 = acc[mf][nf][h * 2] + e0;
                    float v1 = acc[mf][nf][h * 2 + 1] + e1;
                    v0 = 0.5f * v0 * (1.f + erff(v0 * 0.70710678118654752f));
                    v1 = 0.5f * v1 * (1.f + erff(v1 * 0.70710678118654752f));
                    *(__half2*)(smem + FF_H1OFF + r * 528 + col * 2) =
                        __floats2half2_rn(v0, v1);
                }
            }
        __syncthreads();
        if (nc + 2 < 4) {
            issueW1(nc + 2);
            asm volatile("cp.async.commit_group;");
        }
    }

    for (int nc2 = 0; nc2 < 2; nc2++) {
#pragma unroll
        for (int i = 0; i < 8; i++) {
            int idx = tid + i * 256;
            int r = idx >> 5, c = idx & 31;
            cp16(sb + FF_WOFF + r * 528 + c * 16,
                 w2 + (size_t)(nc2 * 64 + r) * 256 + c * 8);
        }
        asm volatile("cp.async.commit_group;");
        asm volatile("cp.async.wait_group 0;");
        __syncthreads();
#pragma unroll
        for (int i = 0; i < 2; i++)
#pragma unroll
            for (int j = 0; j < 2; j++)
#pragma unroll
                for (int q = 0; q < 4; q++) acc[i][j][q] = 0.f;
        u32 ab = sb + FF_H1OFF;
        u32 bb = sb + FF_WOFF;
#pragma unroll
        for (int kb = 0; kb < 16; kb++) {
            u32 a[2][4], b[2][2];
#pragma unroll
            for (int mf = 0; mf < 2; mf++) {
                int r = wm + mf * 16 + (lane & 7) + ((lane >> 3) & 1) * 8;
                ldm_x4(a[mf][0], a[mf][1], a[mf][2], a[mf][3],
                       ab + r * 528 + kb * 32 + (lane >> 4) * 16);
            }
            {
                int r = wn + (lane & 7) + ((lane >> 4) & 1) * 8;
                ldm_x4(b[0][0], b[0][1], b[1][0], b[1][1],
                       bb + r * 528 + kb * 32 + ((lane >> 3) & 1) * 16);
            }
#pragma unroll
            for (int mf = 0; mf < 2; mf++)
#pragma unroll
                for (int nf = 0; nf < 2; nf++)
                    mma_fp16(acc[mf][nf], a[mf], b[nf]);
        }
        __syncthreads();
#pragma unroll
        for (int mf = 0; mf < 2; mf++)
#pragma unroll
            for (int nf = 0; nf < 2; nf++) {
                int col = nc2 * 64 + wn + nf * 8 + t2 * 2;
                float e0 = b2[col], e1 = b2[col + 1];
#pragma unroll
                for (int h = 0; h < 2; h++) {
                    int row = row0 + wm + mf * 16 + g + h * 8;
                    float2 rs = *(const float2*)(f2res + (size_t)row * 128 + col);
                    float v0 = acc[mf][nf][h * 2] + e0 + rs.x;
                    float v1 = acc[mf][nf][h * 2 + 1] + e1 + rs.y;
                    *(__half2*)(outc + (size_t)row * 384 + 256 + col) =
                        __floats2half2_rn(v0, v1);
                }
            }
    }
}

// ---------------------------------------------------------------------------
// Tensor-core retention attention (unchanged).
// ---------------------------------------------------------------------------
template <int PASS>
__global__ void __launch_bounds__(128)
attn_mma(const __half* __restrict__ qkv,
         float* __restrict__ partial,
         __half* __restrict__ out16) {
    __shared__ __half sQ[4][64 * 24];
    __shared__ __half sK[4][64 * 24];
    __shared__ __half sV[4][64 * 24];
    __shared__ float decrow[64];

    const int tid = threadIdx.x, wid = tid >> 5, lane = tid & 31;
    const int g = lane >> 2, t2 = lane & 3;
    const int fixed = blockIdx.x * 4 + wid;
    const int n = blockIdx.y, b = blockIdx.z;

    if (tid < 64) {
        float dec = logf(1.f - exp2f(-2.f - 0.5f * (float)n));
        decrow[tid] = 0.5f * __expf(dec * (float)tid);
    }

#pragma unroll
    for (int tt = 0; tt < 2; tt++) {
        int t = lane + tt * 32;
        size_t tok = (PASS == 0) ? ((size_t)(b * 64 + t) * 64 + fixed)
                                 : ((size_t)(b * 64 + fixed) * 64 + t);
        const uint4* src = (const uint4*)(qkv + tok * 384 + n * HD_);
        *(uint4*)&sQ[wid][t * 24]     = src[0];
        *(uint4*)&sQ[wid][t * 24 + 8] = src[1];
        *(uint4*)&sK[wid][t * 24]     = src[16];
        *(uint4*)&sK[wid][t * 24 + 8] = src[17];
        *(uint4*)&sV[wid][t * 24]     = src[32];
        *(uint4*)&sV[wid][t * 24 + 8] = src[33];
    }
    __syncthreads();

    const u32 qb = smem_u32(&sQ[wid][0]);
    const u32 kb = smem_u32(&sK[wid][0]);
    const u32 vb = smem_u32(&sV[wid][0]);

    u32 qa[4][4];
#pragma unroll
    for (int mf = 0; mf < 4; mf++) {
        int r = mf * 16 + (lane & 7) + ((lane >> 3) & 1) * 8;
        ldm_x4(qa[mf][0], qa[mf][1], qa[mf][2], qa[mf][3],
               qb + r * 48 + (lane >> 4) * 16);
    }

    float oacc[4][2][4];
#pragma unroll
    for (int i = 0; i < 4; i++)
#pragma unroll
        for (int j = 0; j < 2; j++)
#pragma unroll
            for (int q = 0; q < 4; q++) oacc[i][j][q] = 0.f;

#pragma unroll
    for (int jb = 0; jb < 4; jb++) {
        u32 kf[4];
        {
            int r = jb * 16 + (lane & 7) + ((lane >> 4) & 1) * 8;
            ldm_x4(kf[0], kf[1], kf[2], kf[3],
                   kb + r * 48 + ((lane >> 3) & 1) * 16);
        }
        float s[4][2][4];
#pragma unroll
        for (int mf = 0; mf < 4; mf++)
#pragma unroll
            for (int np = 0; np < 2; np++) {
#pragma unroll
                for (int q = 0; q < 4; q++) s[mf][np][q] = 0.f;
                u32 bfrag[2] = { kf[2 * np], kf[2 * np + 1] };
                mma_fp16(s[mf][np], qa[mf], bfrag);
            }
        u32 aP[4][4];
#pragma unroll
        for (int mf = 0; mf < 4; mf++) {
#pragma unroll
            for (int np = 0; np < 2; np++) {
                int i0 = mf * 16 + g;
                int j0 = jb * 16 + np * 8 + t2 * 2;
                int d00 = i0 - j0;       d00 = d00 < 0 ? -d00 : d00;
                int d01 = i0 - j0 - 1;   d01 = d01 < 0 ? -d01 : d01;
                int d10 = i0 + 8 - j0;   d10 = d10 < 0 ? -d10 : d10;
                int d11 = i0 + 7 - j0;   d11 = d11 < 0 ? -d11 : d11;
                s[mf][np][0] *= decrow[d00];
                s[mf][np][1] *= decrow[d01];
                s[mf][np][2] *= decrow[d10];
                s[mf][np][3] *= decrow[d11];
            }
            __half2 h;
            h = __floats2half2_rn(s[mf][0][0], s[mf][0][1]); aP[mf][0] = *(u32*)&h;
            h = __floats2half2_rn(s[mf][0][2], s[mf][0][3]); aP[mf][1] = *(u32*)&h;
            h = __floats2half2_rn(s[mf][1][0], s[mf][1][1]); aP[mf][2] = *(u32*)&h;
            h = __floats2half2_rn(s[mf][1][2], s[mf][1][3]); aP[mf][3] = *(u32*)&h;
        }
        u32 vf[4];
        {
            int r = jb * 16 + (lane & 7) + ((lane >> 3) & 1) * 8;
            ldm_x4t(vf[0], vf[1], vf[2], vf[3],
                    vb + r * 48 + (lane >> 4) * 16);
        }
#pragma unroll
        for (int mf = 0; mf < 4; mf++)
#pragma unroll
            for (int np = 0; np < 2; np++) {
                u32 bfrag[2] = { vf[2 * np], vf[2 * np + 1] };
                mma_fp16(oacc[mf][np], aP[mf], bfrag);
            }
    }

#pragma unroll
    for (int mf = 0; mf < 4; mf++)
#pragma unroll
        for (int np = 0; np < 2; np++) {
            int ch = n * HD_ + np * 8 + t2 * 2;
#pragma unroll
            for (int h = 0; h < 2; h++) {
                int i = mf * 16 + g + h * 8;
                size_t tok = (PASS == 0) ? ((size_t)(b * 64 + i) * 64 + fixed)
                                         : ((size_t)(b * 64 + fixed) * 64 + i);
                float v0 = oacc[mf][np][h * 2];
                float v1 = oacc[mf][np][h * 2 + 1];
                if (PASS == 0) {
                    *(float2*)(partial + tok * 128 + ch) = make_float2(v0, v1);
                } else {
                    float2 pr = *(const float2*)(partial + tok * 128 + ch);
                    *(__half2*)(out16 + tok * 128 + ch) =
                        __floats2half2_rn(pr.x + v0, pr.y + v1);
                }
            }
        }
}

// ---------------------------------------------------------------------------
extern "C" void kernel_launch(void* const* d_in, const int* in_sizes, int n_in,
                              void* d_out, int out_size) {
    const float* x      = (const float*)d_in[0];
    const float* cv1_w  = (const float*)d_in[1];
    const float* bn1_g  = (const float*)d_in[2];
    const float* bn1_b  = (const float*)d_in[3];
    const float* bn1_m  = (const float*)d_in[4];
    const float* bn1_v  = (const float*)d_in[5];
    const float* cv2_w  = (const float*)d_in[6];
    const float* bn2_g  = (const float*)d_in[7];
    const float* bn2_b  = (const float*)d_in[8];
    const float* bn2_m  = (const float*)d_in[9];
    const float* bn2_v  = (const float*)d_in[10];
    const float* ln1_g  = (const float*)d_in[11];
    const float* ln1_b  = (const float*)d_in[12];
    const float* qkv_w  = (const float*)d_in[13];
    const float* qkv_b  = (const float*)d_in[14];
    const float* proj_w = (const float*)d_in[15];
    const float* proj_b = (const float*)d_in[16];
    const float* gamma  = (const float*)d_in[17];
    const float* ln2_g  = (const float*)d_in[18];
    const float* ln2_b  = (const float*)d_in[19];
    const float* ffn_w1 = (const float*)d_in[20];
    const float* ffn_b1 = (const float*)d_in[21];
    const float* ffn_w2 = (const float*)d_in[22];
    const float* ffn_b2 = (const float*)d_in[23];
    float* out = (float*)d_out;

    __half *xt16, *cat16, *fn16, *qkv16, *attn16, *w16;
    float *y2f, *attnp, *f2;
    cudaGetSymbolAddress((void**)&xt16,   g_xt16);
    cudaGetSymbolAddress((void**)&cat16,  g_cat16);
    cudaGetSymbolAddress((void**)&y2f,    g_y2f);
    cudaGetSymbolAddress((void**)&fn16,   g_fn16);
    cudaGetSymbolAddress((void**)&qkv16,  g_qkv16);
    cudaGetSymbolAddress((void**)&attnp,  g_attnp);
    cudaGetSymbolAddress((void**)&attn16, g_attn16);
    cudaGetSymbolAddress((void**)&f2,     g_f2);
    cudaGetSymbolAddress((void**)&w16,    g_w16);

    __half* w_cv1  = w16;
    __half* w_qkv  = w_cv1 + 65536;
    __half* w_proj = w_qkv + 49152;
    __half* w_f1   = w_proj + 16384;
    __half* w_f2   = w_f1 + 32768;
    __half* w_cv2  = w_f2 + 32768;

    cudaFuncSetAttribute(gemm128<EPI_CV1>,  cudaFuncAttributeMaxDynamicSharedMemorySize, SM128_BYTES);
    cudaFuncSetAttribute(gemm128<EPI_PROJ>, cudaFuncAttributeMaxDynamicSharedMemorySize, SM128_BYTES);
    cudaFuncSetAttribute(gemm64_nchw,       cudaFuncAttributeMaxDynamicSharedMemorySize, SM64_BYTES);
    cudaFuncSetAttribute(ffn_fused,         cudaFuncAttributeMaxDynamicSharedMemorySize, FF_SMEM);

    // 0) weights -> fp16
    convert_w_all<<<dim3(192, 6), 256>>>(cv1_w, qkv_w, proj_w, ffn_w1, ffn_w2,
                                         cv2_w, w16);

    // 1) x NCHW -> xt16
    transpose_x_kernel<<<dim3(HW_/32, C1_/32, B_), dim3(32, 8)>>>(x, xt16);

    // 2) cv1 + BN + SiLU -> cat16[:,0:256] (+ y2f) + fused LN1 + fused qkv
    gemm128<EPI_CV1><<<dim3(TOKENS/128, 2), 256, SM128_BYTES>>>(
        xt16, 256, w_cv1, 256, cat16, 384, bn1_g, bn1_b, bn1_m, bn1_v,
        nullptr, 0, ln1_g, ln1_b, nullptr, w_qkv, qkv_b, qkv16);

    // 3) attention H then W
    attn_mma<0><<<dim3(16, NH_, B_), 128>>>(qkv16, attnp, attn16);
    attn_mma<1><<<dim3(16, NH_, B_), 128>>>(qkv16, attnp, attn16);

    // 4) proj (+res y2, *gamma) -> f2 (+ fused LN2 -> fn16)
    gemm128<EPI_PROJ><<<dim3(TOKENS/128, 1), 256, SM128_BYTES>>>(
        attn16, 128, w_proj, 128, f2, 128, proj_b, gamma, nullptr, nullptr,
        y2f, 128, ln2_g, ln2_b, fn16, nullptr, nullptr, nullptr);

    // 5) fused ffn1(GELU)+ffn2 (+res f2) -> cat16[:,256:384]
    ffn_fused<<<TOKENS/64, 256, FF_SMEM>>>(
        fn16, w_f1, w_f2, ffn_b1, ffn_b2, f2, cat16);

    // 6) cv2 + BN + SiLU -> NCHW out
    gemm64_nchw<<<dim3(TOKENS/128, 4), 256, SM64_BYTES>>>(
        cat16, 384, w_cv2, 384, out, bn2_g, bn2_b, bn2_m, bn2_v);
}

// round 12
// speedup vs baseline: 1.2663x; 1.0610x over previous
#include <cuda_runtime.h>
#include <cuda_fp16.h>
#include <math.h>

#define B_ 16
#define C1_ 256
#define C2_ 256
#define H_ 64
#define W_ 64
#define NH_ 8
#define C_ 128
#define HD_ 16
#define HW_ (H_*W_)
#define TOKENS (B_*HW_)

typedef unsigned int u32;

// -------- static scratch -----------
__device__ __half g_xt16  [(size_t)TOKENS*256];
__device__ __half g_cat16 [(size_t)TOKENS*384];
__device__ float  g_y2f   [(size_t)TOKENS*128];
__device__ __half g_fn16  [(size_t)TOKENS*128];   // LN2 output only
__device__ __half g_qkv16 [(size_t)TOKENS*384];
__device__ __half g_attnp16[(size_t)TOKENS*128];  // fp16 H-pass partial
__device__ __half g_attn16[(size_t)TOKENS*128];
__device__ float  g_f2    [(size_t)TOKENS*128];
__device__ __half g_w16[65536+49152+16384+32768+32768+98304];

// ---------------------------------------------------------------------------
__device__ __forceinline__ u32 smem_u32(const void* p) {
    u32 a;
    asm("{ .reg .u64 t; cvta.to.shared.u64 t, %1; cvt.u32.u64 %0, t; }"
        : "=r"(a) : "l"(p));
    return a;
}
__device__ __forceinline__ void mma_fp16(float* c, const u32* a, const u32* b) {
    asm volatile(
        "mma.sync.aligned.m16n8k16.row.col.f32.f16.f16.f32 "
        "{%0,%1,%2,%3}, {%4,%5,%6,%7}, {%8,%9}, {%0,%1,%2,%3};"
        : "+f"(c[0]), "+f"(c[1]), "+f"(c[2]), "+f"(c[3])
        : "r"(a[0]), "r"(a[1]), "r"(a[2]), "r"(a[3]), "r"(b[0]), "r"(b[1]));
}
__device__ __forceinline__ void ldm_x4(u32& r0, u32& r1, u32& r2, u32& r3, u32 a) {
    asm volatile("ldmatrix.sync.aligned.m8n8.x4.shared.b16 {%0,%1,%2,%3}, [%4];"
        : "=r"(r0), "=r"(r1), "=r"(r2), "=r"(r3) : "r"(a));
}
__device__ __forceinline__ void ldm_x4t(u32& r0, u32& r1, u32& r2, u32& r3, u32 a) {
    asm volatile("ldmatrix.sync.aligned.m8n8.x4.trans.shared.b16 {%0,%1,%2,%3}, [%4];"
        : "=r"(r0), "=r"(r1), "=r"(r2), "=r"(r3) : "r"(a));
}
__device__ __forceinline__ void cp16(u32 dst, const void* src) {
    asm volatile("cp.async.cg.shared.global [%0], [%1], 16;" :: "r"(dst), "l"(src));
}

// ---------------------------------------------------------------------------
__global__ void convert_w_all(const float* __restrict__ s0, const float* __restrict__ s1,
                              const float* __restrict__ s2, const float* __restrict__ s3,
                              const float* __restrict__ s4, const float* __restrict__ s5,
                              __half* __restrict__ dst) {
    const int sizes[6] = {65536, 49152, 16384, 32768, 32768, 98304};
    const int offs [6] = {0, 65536, 114688, 131072, 163840, 196608};
    int t = blockIdx.y;
    const float* src = t == 0 ? s0 : t == 1 ? s1 : t == 2 ? s2 :
                       t == 3 ? s3 : t == 4 ? s4 : s5;
    int n2 = sizes[t] >> 1;
    int i = blockIdx.x * 256 + threadIdx.x;
    if (i < n2) {
        float2 v = *(const float2*)(src + 2 * i);
        *(__half2*)(dst + offs[t] + 2 * i) = __floats2half2_rn(v.x, v.y);
    }
}

__global__ void transpose_x_kernel(const float* __restrict__ x,
                                   __half* __restrict__ xt) {
    __shared__ float tile[32][33];
    int b  = blockIdx.z;
    int p0 = blockIdx.x * 32;
    int c0 = blockIdx.y * 32;
    const float* xb = x + (size_t)b * C1_ * HW_;
    __half*     xtb = xt + (size_t)b * HW_ * C1_;
#pragma unroll
    for (int i = 0; i < 32; i += 8)
        tile[threadIdx.y + i][threadIdx.x] =
            xb[(size_t)(c0 + threadIdx.y + i) * HW_ + p0 + threadIdx.x];
    __syncthreads();
#pragma unroll
    for (int i = 0; i < 32; i += 8)
        xtb[(size_t)(p0 + threadIdx.y + i) * C1_ + c0 + threadIdx.x] =
            __float2half_rn(tile[threadIdx.x][threadIdx.y + i]);
}

enum { EPI_CV1 = 0, EPI_PROJ = 2 };

// ---------------------------------------------------------------------------
// gemm128: CTA 128x128, 8 warps (2m x 4n, warp 64x32). 2-stage cp.async.
// EPI_CV1 + blockIdx.y==1: fused register-LN1 + in-SMEM qkv GEMM (N=384).
// EPI_PROJ: smem-staged LN2 -> fnout.
// ---------------------------------------------------------------------------
#define STG128 36864
#define SM128_BYTES (2*STG128)
#define FQ_FNS 4096
#define FQ_W   38912

template <int EPI>
__global__ void __launch_bounds__(256, 2)
gemm128(const __half* __restrict__ A, int lda,
        const __half* __restrict__ Wt, int K,
        void* __restrict__ Cpv, int ldc,
        const float* __restrict__ p0, const float* __restrict__ p1,
        const float* __restrict__ p2, const float* __restrict__ p3,
        const float* __restrict__ Rs, int ldr,
        const float* __restrict__ lng, const float* __restrict__ lnb,
        __half* __restrict__ fnout,
        const __half* __restrict__ Wq, const float* __restrict__ qbias,
        __half* __restrict__ qkvout) {
    extern __shared__ __align__(16) char smem[];
    const u32 sb = smem_u32(smem);
    const int tid = threadIdx.x, wid = tid >> 5, lane = tid & 31;
    const int wm = (wid >> 2) * 64, wn = (wid & 3) * 32;
    const int g = lane >> 2, t2 = lane & 3;
    const int row0 = blockIdx.x * 128, col0 = blockIdx.y * 128;
    const int lrow = tid >> 3, lc8 = tid & 7;

    float acc[4][4][4];
#pragma unroll
    for (int i = 0; i < 4; i++)
#pragma unroll
        for (int j = 0; j < 4; j++)
#pragma unroll
            for (int q = 0; q < 4; q++) acc[i][j][q] = 0.f;

    const int nch = K >> 6;
    auto issue = [&](int c) {
        u32 ab = sb + (c & 1) * STG128;
        u32 bb = ab + 18432;
        const __half* Ag = A  + (size_t)row0 * lda + c * 64;
        const __half* Bg = Wt + (size_t)col0 * K   + c * 64;
#pragma unroll
        for (int i = 0; i < 4; i++) {
            int r = i * 32 + lrow;
            cp16(ab + r * 144 + lc8 * 16, Ag + (size_t)r * lda + lc8 * 8);
            cp16(bb + r * 144 + lc8 * 16, Bg + (size_t)r * K   + lc8 * 8);
        }
    };

    issue(0);
    asm volatile("cp.async.commit_group;");
    for (int c = 0; c < nch; c++) {
        if (c + 1 < nch) {
            issue(c + 1);
            asm volatile("cp.async.commit_group;");
            asm volatile("cp.async.wait_group 1;");
        } else {
            asm volatile("cp.async.wait_group 0;");
        }
        __syncthreads();
        u32 ab = sb + (c & 1) * STG128;
        u32 bb = ab + 18432;
#pragma unroll
        for (int kb = 0; kb < 4; kb++) {
            u32 a[4][4], b[4][2];
#pragma unroll
            for (int mf = 0; mf < 4; mf++) {
                int r = wm + mf * 16 + (lane & 7) + ((lane >> 3) & 1) * 8;
                ldm_x4(a[mf][0], a[mf][1], a[mf][2], a[mf][3],
                       ab + r * 144 + kb * 32 + (lane >> 4) * 16);
            }
#pragma unroll
            for (int np = 0; np < 2; np++) {
                int r = wn + np * 16 + (lane & 7) + ((lane >> 4) & 1) * 8;
                ldm_x4(b[2*np][0], b[2*np][1], b[2*np+1][0], b[2*np+1][1],
                       bb + r * 144 + kb * 32 + ((lane >> 3) & 1) * 16);
            }
#pragma unroll
            for (int mf = 0; mf < 4; mf++)
#pragma unroll
                for (int nf = 0; nf < 4; nf++)
                    mma_fp16(acc[mf][nf], a[mf], b[nf]);
        }
        __syncthreads();
    }

    const bool fuseQ = (EPI == EPI_CV1) && (blockIdx.y == 1);

    auto issueWq = [&](int nc) {
        u32 d = sb + FQ_W + (u32)(nc & 1) * 17408;
#pragma unroll
        for (int i = 0; i < 4; i++) {
            int idx = tid + i * 256;
            int r = idx >> 4, c2 = idx & 15;
            cp16(d + r * 272 + c2 * 16, Wq + (size_t)(nc * 64 + r) * 128 + c2 * 8);
        }
    };
    if (fuseQ) {
        issueWq(0);
        asm volatile("cp.async.commit_group;");
        issueWq(1);
        asm volatile("cp.async.commit_group;");
    }

    if constexpr (EPI == EPI_CV1) {
#pragma unroll
        for (int mf = 0; mf < 4; mf++) {
#pragma unroll
            for (int nf = 0; nf < 4; nf++) {
                int lcol = wn + nf * 8 + t2 * 2;
                int col  = col0 + lcol;
                float e0 = p0[col]     * rsqrtf(p3[col]     + 1e-5f);
                float e1 = p0[col + 1] * rsqrtf(p3[col + 1] + 1e-5f);
                float f0 = p1[col]     - p2[col]     * e0;
                float f1 = p1[col + 1] - p2[col + 1] * e1;
#pragma unroll
                for (int h = 0; h < 2; h++) {
                    int row = row0 + wm + mf * 16 + g + h * 8;
                    float v0 = acc[mf][nf][h * 2]     * e0 + f0;
                    float v1 = acc[mf][nf][h * 2 + 1] * e1 + f1;
                    v0 = v0 / (1.f + __expf(-v0));
                    v1 = v1 / (1.f + __expf(-v1));
                    *(__half2*)((__half*)Cpv + (size_t)row * 384 + col) =
                        __floats2half2_rn(v0, v1);
                    if (fuseQ)
                        *(float2*)(g_y2f + (size_t)row * 128 + lcol) =
                            make_float2(v0, v1);
                    acc[mf][nf][h * 2]     = v0;
                    acc[mf][nf][h * 2 + 1] = v1;
                }
            }
        }
        if (fuseQ) {
            float* part = (float*)smem;
#pragma unroll
            for (int mf = 0; mf < 4; mf++)
#pragma unroll
                for (int h = 0; h < 2; h++) {
                    float s = 0.f, qq = 0.f;
#pragma unroll
                    for (int nf = 0; nf < 4; nf++) {
                        float a0 = acc[mf][nf][h * 2];
                        float a1 = acc[mf][nf][h * 2 + 1];
                        s += a0 + a1;
                        qq += a0 * a0 + a1 * a1;
                    }
                    s  += __shfl_xor_sync(~0u, s, 1);
                    s  += __shfl_xor_sync(~0u, s, 2);
                    qq += __shfl_xor_sync(~0u, qq, 1);
                    qq += __shfl_xor_sync(~0u, qq, 2);
                    if (t2 == 0) {
                        int r = wm + mf * 16 + g + h * 8;
                        part[r * 8 + (wid & 3) * 2]     = s;
                        part[r * 8 + (wid & 3) * 2 + 1] = qq;
                    }
                }
            __syncthreads();
#pragma unroll
            for (int mf = 0; mf < 4; mf++)
#pragma unroll
                for (int h = 0; h < 2; h++) {
                    int r = wm + mf * 16 + g + h * 8;
                    float s  = part[r*8] + part[r*8+2] + part[r*8+4] + part[r*8+6];
                    float qq = part[r*8+1] + part[r*8+3] + part[r*8+5] + part[r*8+7];
                    float mu  = s * (1.f / 128.f);
                    float var = qq * (1.f / 128.f) - mu * mu;
                    float rsd = rsqrtf(var + 1e-5f);
#pragma unroll
                    for (int nf = 0; nf < 4; nf++) {
                        int lcol = wn + nf * 8 + t2 * 2;
                        float f0 = (acc[mf][nf][h*2]   - mu) * rsd * lng[lcol]   + lnb[lcol];
                        float f1 = (acc[mf][nf][h*2+1] - mu) * rsd * lng[lcol+1] + lnb[lcol+1];
                        *(__half2*)(smem + FQ_FNS + r * 272 + lcol * 2) =
                            __floats2half2_rn(f0, f1);
                    }
                }
            __syncthreads();

            const int wm2 = (wid >> 1) * 32, wn2 = (wid & 1) * 32;
            for (int nc = 0; nc < 6; nc++) {
                if (nc < 5) asm volatile("cp.async.wait_group 1;");
                else        asm volatile("cp.async.wait_group 0;");
                __syncthreads();
                float qa[2][4][4];
#pragma unroll
                for (int i = 0; i < 2; i++)
#pragma unroll
                    for (int j = 0; j < 4; j++)
#pragma unroll
                        for (int q = 0; q < 4; q++) qa[i][j][q] = 0.f;
                u32 ab2 = sb + FQ_FNS;
                u32 bb2 = sb + FQ_W + (u32)(nc & 1) * 17408;
#pragma unroll
                for (int kb = 0; kb < 8; kb++) {
                    u32 a[2][4], b[4][2];
#pragma unroll
                    for (int mf = 0; mf < 2; mf++) {
                        int r = wm2 + mf * 16 + (lane & 7) + ((lane >> 3) & 1) * 8;
                        ldm_x4(a[mf][0], a[mf][1], a[mf][2], a[mf][3],
                               ab2 + r * 272 + kb * 32 + (lane >> 4) * 16);
                    }
#pragma unroll
                    for (int np = 0; np < 2; np++) {
                        int r = wn2 + np * 16 + (lane & 7) + ((lane >> 4) & 1) * 8;
                        ldm_x4(b[2*np][0], b[2*np][1], b[2*np+1][0], b[2*np+1][1],
                               bb2 + r * 272 + kb * 32 + ((lane >> 3) & 1) * 16);
                    }
#pragma unroll
                    for (int mf = 0; mf < 2; mf++)
#pragma unroll
                        for (int nf = 0; nf < 4; nf++)
                            mma_fp16(qa[mf][nf], a[mf], b[nf]);
                }
#pragma unroll
                for (int mf = 0; mf < 2; mf++)
#pragma unroll
                    for (int nf = 0; nf < 4; nf++) {
                        int col = nc * 64 + wn2 + nf * 8 + t2 * 2;
                        float e0 = qbias[col], e1 = qbias[col + 1];
#pragma unroll
                        for (int h = 0; h < 2; h++) {
                            int row = row0 + wm2 + mf * 16 + g + h * 8;
                            *(__half2*)(qkvout + (size_t)row * 384 + col) =
                                __floats2half2_rn(qa[mf][nf][h*2] + e0,
                                                  qa[mf][nf][h*2+1] + e1);
                        }
                    }
                __syncthreads();
                if (nc + 2 < 6) {
                    issueWq(nc + 2);
                    asm volatile("cp.async.commit_group;");
                }
            }
        }
    } else {   // EPI_PROJ
        float* stg = (float*)smem;
#pragma unroll
        for (int mf = 0; mf < 4; mf++) {
#pragma unroll
            for (int nf = 0; nf < 4; nf++) {
                int lcol = wn + nf * 8 + t2 * 2;
                int col  = col0 + lcol;
                float e0 = p0[col], e1 = p0[col + 1];
                float f0 = p1[col], f1 = p1[col + 1];
#pragma unroll
                for (int h = 0; h < 2; h++) {
                    int r   = wm + mf * 16 + g + h * 8;
                    int row = row0 + r;
                    float2 rs = *(const float2*)(Rs + (size_t)row * ldr + col);
                    float v0 = rs.x + (acc[mf][nf][h*2]   + e0) * f0;
                    float v1 = rs.y + (acc[mf][nf][h*2+1] + e1) * f1;
                    *(float2*)((float*)Cpv + (size_t)row * ldc + col) =
                        make_float2(v0, v1);
                    stg[r * 129 + lcol]     = v0;
                    stg[r * 129 + lcol + 1] = v1;
                }
            }
        }
        __syncthreads();
#pragma unroll
        for (int rr = 0; rr < 16; rr++) {
            int r = wid * 16 + rr;
            float v[4];
            float s = 0.f;
#pragma unroll
            for (int i = 0; i < 4; i++) {
                v[i] = stg[r * 129 + lane + 32 * i];
                s += v[i];
            }
#pragma unroll
            for (int o = 16; o; o >>= 1) s += __shfl_xor_sync(~0u, s, o);
            float mu = s * (1.f / 128.f);
            float q = 0.f;
#pragma unroll
            for (int i = 0; i < 4; i++) { float d = v[i] - mu; q += d * d; }
#pragma unroll
            for (int o = 16; o; o >>= 1) q += __shfl_xor_sync(~0u, q, o);
            float rsd = rsqrtf(q * (1.f / 128.f) + 1e-5f);
#pragma unroll
            for (int i = 0; i < 4; i++) {
                int cc = lane + 32 * i;
                fnout[(size_t)(row0 + r) * 128 + cc] =
                    __float2half_rn((v[i] - mu) * rsd * lng[cc] + lnb[cc]);
            }
        }
    }
}

// ---------------------------------------------------------------------------
// gemm64_nchw (cv2 only, unchanged from R10)
// ---------------------------------------------------------------------------
#define STG64 27648
#define SM64_BYTES (2*STG64)

__global__ void __launch_bounds__(256, 3)
gemm64_nchw(const __half* __restrict__ A, int lda,
            const __half* __restrict__ Wt, int K,
            float* __restrict__ Cp,
            const float* __restrict__ p0, const float* __restrict__ p1,
            const float* __restrict__ p2, const float* __restrict__ p3) {
    extern __shared__ __align__(16) char smem[];
    const u32 sb = smem_u32(smem);
    const int tid = threadIdx.x, wid = tid >> 5, lane = tid & 31;
    const int wm = (wid >> 1) * 32, wn = (wid & 1) * 32;
    const int g = lane >> 2, t2 = lane & 3;
    const int row0 = blockIdx.x * 128, col0 = blockIdx.y * 64;
    const int lrow = tid >> 3, lc8 = tid & 7;

    float acc[2][4][4];
#pragma unroll
    for (int i = 0; i < 2; i++)
#pragma unroll
        for (int j = 0; j < 4; j++)
#pragma unroll
            for (int q = 0; q < 4; q++) acc[i][j][q] = 0.f;

    const int nch = K >> 6;
    auto issue = [&](int c) {
        u32 ab = sb + (c & 1) * STG64;
        u32 bb = ab + 18432;
        const __half* Ag = A  + (size_t)row0 * lda + c * 64;
        const __half* Bg = Wt + (size_t)col0 * K   + c * 64;
#pragma unroll
        for (int i = 0; i < 4; i++) {
            int r = i * 32 + lrow;
            cp16(ab + r * 144 + lc8 * 16, Ag + (size_t)r * lda + lc8 * 8);
        }
#pragma unroll
        for (int i = 0; i < 2; i++) {
            int r = i * 32 + lrow;
            cp16(bb + r * 144 + lc8 * 16, Bg + (size_t)r * K + lc8 * 8);
        }
    };

    issue(0);
    asm volatile("cp.async.commit_group;");
    for (int c = 0; c < nch; c++) {
        if (c + 1 < nch) {
            issue(c + 1);
            asm volatile("cp.async.commit_group;");
            asm volatile("cp.async.wait_group 1;");
        } else {
            asm volatile("cp.async.wait_group 0;");
        }
        __syncthreads();
        u32 ab = sb + (c & 1) * STG64;
        u32 bb = ab + 18432;
#pragma unroll
        for (int kb = 0; kb < 4; kb++) {
            u32 a[2][4], b[4][2];
#pragma unroll
            for (int mf = 0; mf < 2; mf++) {
                int r = wm + mf * 16 + (lane & 7) + ((lane >> 3) & 1) * 8;
                ldm_x4(a[mf][0], a[mf][1], a[mf][2], a[mf][3],
                       ab + r * 144 + kb * 32 + (lane >> 4) * 16);
            }
#pragma unroll
            for (int np = 0; np < 2; np++) {
                int r = wn + np * 16 + (lane & 7) + ((lane >> 4) & 1) * 8;
                ldm_x4(b[2*np][0], b[2*np][1], b[2*np+1][0], b[2*np+1][1],
                       bb + r * 144 + kb * 32 + ((lane >> 3) & 1) * 16);
            }
#pragma unroll
            for (int mf = 0; mf < 2; mf++)
#pragma unroll
                for (int nf = 0; nf < 4; nf++)
                    mma_fp16(acc[mf][nf], a[mf], b[nf]);
        }
        __syncthreads();
    }

    float* stg = (float*)smem;
#pragma unroll
    for (int mf = 0; mf < 2; mf++)
#pragma unroll
        for (int nf = 0; nf < 4; nf++) {
            int r = wm + mf * 16 + g;
            int cl = wn + nf * 8 + t2 * 2;
            stg[r * 65 + cl]           = acc[mf][nf][0];
            stg[r * 65 + cl + 1]       = acc[mf][nf][1];
            stg[(r + 8) * 65 + cl]     = acc[mf][nf][2];
            stg[(r + 8) * 65 + cl + 1] = acc[mf][nf][3];
        }
    __syncthreads();
    for (int it = 0; it < 32; it++) {
        int idx  = it * 256 + tid;
        int lcol = idx >> 7;
        int r    = idx & 127;
        int col  = col0 + lcol;
        int row  = row0 + r;
        float v  = stg[r * 65 + lcol];
        float sc = p0[col] * rsqrtf(p3[col] + 1e-5f);
        v = v * sc + (p1[col] - p2[col] * sc);
        v = v / (1.f + __expf(-v));
        Cp[(((size_t)(row >> 12)) * C2_ + col) * 4096 + (row & 4095)] = v;
    }
}

// ---------------------------------------------------------------------------
// ffn_fused (unchanged)
// ---------------------------------------------------------------------------
#define FF_AOFF  0
#define FF_WOFF  17408
#define FF_H1OFF 52224
#define FF_SMEM  86016

__global__ void __launch_bounds__(256, 2)
ffn_fused(const __half* __restrict__ fn, const __half* __restrict__ w1,
          const __half* __restrict__ w2, const float* __restrict__ b1,
          const float* __restrict__ b2, const float* __restrict__ f2res,
          __half* __restrict__ outc) {
    extern __shared__ __align__(16) char smem[];
    const u32 sb = smem_u32(smem);
    const int tid = threadIdx.x, wid = tid >> 5, lane = tid & 31;
    const int wm = (wid >> 2) * 32, wn = (wid & 3) * 16;
    const int g = lane >> 2, t2 = lane & 3;
    const int row0 = blockIdx.x * 64;

#pragma unroll
    for (int i = 0; i < 4; i++) {
        int idx = tid + i * 256;
        int r = idx >> 4, c = idx & 15;
        cp16(sb + FF_AOFF + r * 272 + c * 16,
             fn + (size_t)(row0 + r) * 128 + c * 8);
    }
    auto issueW1 = [&](int nc) {
        u32 d = sb + FF_WOFF + (u32)(nc & 1) * 17408;
#pragma unroll
        for (int i = 0; i < 4; i++) {
            int idx = tid + i * 256;
            int r = idx >> 4, c = idx & 15;
            cp16(d + r * 272 + c * 16, w1 + (size_t)(nc * 64 + r) * 128 + c * 8);
        }
    };
    issueW1(0);
    asm volatile("cp.async.commit_group;");
    issueW1(1);
    asm volatile("cp.async.commit_group;");

    float acc[2][2][4];
    for (int nc = 0; nc < 4; nc++) {
        if (nc < 3) asm volatile("cp.async.wait_group 1;");
        else        asm volatile("cp.async.wait_group 0;");
        __syncthreads();
#pragma unroll
        for (int i = 0; i < 2; i++)
#pragma unroll
            for (int j = 0; j < 2; j++)
#pragma unroll
                for (int q = 0; q < 4; q++) acc[i][j][q] = 0.f;
        u32 ab = sb + FF_AOFF;
        u32 bb = sb + FF_WOFF + (u32)(nc & 1) * 17408;
#pragma unroll
        for (int kb = 0; kb < 8; kb++) {
            u32 a[2][4], b[2][2];
#pragma unroll
            for (int mf = 0; mf < 2; mf++) {
                int r = wm + mf * 16 + (lane & 7) + ((lane >> 3) & 1) * 8;
                ldm_x4(a[mf][0], a[mf][1], a[mf][2], a[mf][3],
                       ab + r * 272 + kb * 32 + (lane >> 4) * 16);
            }
            {
                int r = wn + (lane & 7) + ((lane >> 4) & 1) * 8;
                ldm_x4(b[0][0], b[0][1], b[1][0], b[1][1],
                       bb + r * 272 + kb * 32 + ((lane >> 3) & 1) * 16);
            }
#pragma unroll
            for (int mf = 0; mf < 2; mf++)
#pragma unroll
                for (int nf = 0; nf < 2; nf++)
                    mma_fp16(acc[mf][nf], a[mf], b[nf]);
        }
#pragma unroll
        for (int mf = 0; mf < 2; mf++)
#pragma unroll
            for (int nf = 0; nf < 2; nf++) {
                int col = nc * 64 + wn + nf * 8 + t2 * 2;
                float e0 = b1[col], e1 = b1[col + 1];
#pragma unroll
                for (int h = 0; h < 2; h++) {
                    int r = wm + mf * 16 + g + h * 8;
                    float v0 = acc[mf][nf][h * 2] + e0;
                    float v1 = acc[mf][nf][h * 2 + 1] + e1;
                    v0 = 0.5f * v0 * (1.f + erff(v0 * 0.70710678118654752f));
                    v1 = 0.5f * v1 * (1.f + erff(v1 * 0.70710678118654752f));
                    *(__half2*)(smem + FF_H1OFF + r * 528 + col * 2) =
                        __floats2half2_rn(v0, v1);
                }
            }
        __syncthreads();
        if (nc + 2 < 4) {
            issueW1(nc + 2);
            asm volatile("cp.async.commit_group;");
        }
    }

    for (int nc2 = 0; nc2 < 2; nc2++) {
#pragma unroll
        for (int i = 0; i < 8; i++) {
            int idx = tid + i * 256;
            int r = idx >> 5, c = idx & 31;
            cp16(sb + FF_WOFF + r * 528 + c * 16,
                 w2 + (size_t)(nc2 * 64 + r) * 256 + c * 8);
        }
        asm volatile("cp.async.commit_group;");
        asm volatile("cp.async.wait_group 0;");
        __syncthreads();
#pragma unroll
        for (int i = 0; i < 2; i++)
#pragma unroll
            for (int j = 0; j < 2; j++)
#pragma unroll
                for (int q = 0; q < 4; q++) acc[i][j][q] = 0.f;
        u32 ab = sb + FF_H1OFF;
        u32 bb = sb + FF_WOFF;
#pragma unroll
        for (int kb = 0; kb < 16; kb++) {
            u32 a[2][4], b[2][2];
#pragma unroll
            for (int mf = 0; mf < 2; mf++) {
                int r = wm + mf * 16 + (lane & 7) + ((lane >> 3) & 1) * 8;
                ldm_x4(a[mf][0], a[mf][1], a[mf][2], a[mf][3],
                       ab + r * 528 + kb * 32 + (lane >> 4) * 16);
            }
            {
                int r = wn + (lane & 7) + ((lane >> 4) & 1) * 8;
                ldm_x4(b[0][0], b[0][1], b[1][0], b[1][1],
                       bb + r * 528 + kb * 32 + ((lane >> 3) & 1) * 16);
            }
#pragma unroll
            for (int mf = 0; mf < 2; mf++)
#pragma unroll
                for (int nf = 0; nf < 2; nf++)
                    mma_fp16(acc[mf][nf], a[mf], b[nf]);
        }
        __syncthreads();
#pragma unroll
        for (int mf = 0; mf < 2; mf++)
#pragma unroll
            for (int nf = 0; nf < 2; nf++) {
                int col = nc2 * 64 + wn + nf * 8 + t2 * 2;
                float e0 = b2[col], e1 = b2[col + 1];
#pragma unroll
                for (int h = 0; h < 2; h++) {
                    int row = row0 + wm + mf * 16 + g + h * 8;
                    float2 rs = *(const float2*)(f2res + (size_t)row * 128 + col);
                    float v0 = acc[mf][nf][h * 2] + e0 + rs.x;
                    float v1 = acc[mf][nf][h * 2 + 1] + e1 + rs.y;
                    *(__half2*)(outc + (size_t)row * 384 + 256 + col) =
                        __floats2half2_rn(v0, v1);
                }
            }
    }
}

// ---------------------------------------------------------------------------
// Attention: one 256-thread CTA per (b, line). Shared 64x384 qkv tile
// (784B rows, conflict-free), 8 warps = 8 heads. fp16 partial between passes.
// ---------------------------------------------------------------------------
#define AT_ROW  784
#define AT_DEC  50176
#define AT_SMEM (50176 + 2048)

template <int PASS>
__global__ void __launch_bounds__(256)
attn_mma(const __half* __restrict__ qkv,
         __half* __restrict__ partial,
         __half* __restrict__ out16) {
    extern __shared__ __align__(16) char smem[];
    const u32 sb = smem_u32(smem);
    const int tid = threadIdx.x, wid = tid >> 5, lane = tid & 31;
    const int g = lane >> 2, t2 = lane & 3;
    const int fixed = blockIdx.x;
    const int b = blockIdx.y;
    const int n = wid;            // head
    float* decrow = (float*)(smem + AT_DEC);

    {
        float dec = logf(1.f - exp2f(-2.f - 0.5f * (float)wid));
        decrow[wid * 64 + lane]      = 0.5f * __expf(dec * (float)lane);
        decrow[wid * 64 + lane + 32] = 0.5f * __expf(dec * (float)(lane + 32));
    }

    // coalesced bulk load: 64 tokens x 768B
#pragma unroll
    for (int i = 0; i < 12; i++) {
        int idx = i * 256 + tid;
        int r = idx / 48, c = idx - r * 48;
        size_t tok = (PASS == 0) ? ((size_t)(b * 64 + r) * 64 + fixed)
                                 : ((size_t)(b * 64 + fixed) * 64 + r);
        cp16(sb + r * AT_ROW + c * 16, qkv + tok * 384 + c * 8);
    }
    asm volatile("cp.async.commit_group;");
    asm volatile("cp.async.wait_group 0;");
    __syncthreads();

    const u32 qb = sb + n * 32;
    const u32 kb = sb + 256 + n * 32;
    const u32 vb = sb + 512 + n * 32;

    u32 qa[4][4];
#pragma unroll
    for (int mf = 0; mf < 4; mf++) {
        int r = mf * 16 + (lane & 7) + ((lane >> 3) & 1) * 8;
        ldm_x4(qa[mf][0], qa[mf][1], qa[mf][2], qa[mf][3],
               qb + r * AT_ROW + (lane >> 4) * 16);
    }

    float oacc[4][2][4];
#pragma unroll
    for (int i = 0; i < 4; i++)
#pragma unroll
        for (int j = 0; j < 2; j++)
#pragma unroll
            for (int q = 0; q < 4; q++) oacc[i][j][q] = 0.f;

#pragma unroll
    for (int jb = 0; jb < 4; jb++) {
        u32 kf[4];
        {
            int r = jb * 16 + (lane & 7) + ((lane >> 4) & 1) * 8;
            ldm_x4(kf[0], kf[1], kf[2], kf[3],
                   kb + r * AT_ROW + ((lane >> 3) & 1) * 16);
        }
        float s[4][2][4];
#pragma unroll
        for (int mf = 0; mf < 4; mf++)
#pragma unroll
            for (int np = 0; np < 2; np++) {
#pragma unroll
                for (int q = 0; q < 4; q++) s[mf][np][q] = 0.f;
                u32 bfrag[2] = { kf[2 * np], kf[2 * np + 1] };
                mma_fp16(s[mf][np], qa[mf], bfrag);
            }
        u32 aP[4][4];
#pragma unroll
        for (int mf = 0; mf < 4; mf++) {
#pragma unroll
            for (int np = 0; np < 2; np++) {
                int i0 = mf * 16 + g;
                int j0 = jb * 16 + np * 8 + t2 * 2;
                int d00 = i0 - j0;       d00 = d00 < 0 ? -d00 : d00;
                int d01 = i0 - j0 - 1;   d01 = d01 < 0 ? -d01 : d01;
                int d10 = i0 + 8 - j0;   d10 = d10 < 0 ? -d10 : d10;
                int d11 = i0 + 7 - j0;   d11 = d11 < 0 ? -d11 : d11;
                s[mf][np][0] *= decrow[n * 64 + d00];
                s[mf][np][1] *= decrow[n * 64 + d01];
                s[mf][np][2] *= decrow[n * 64 + d10];
                s[mf][np][3] *= decrow[n * 64 + d11];
            }
            __half2 h;
            h = __floats2half2_rn(s[mf][0][0], s[mf][0][1]); aP[mf][0] = *(u32*)&h;
            h = __floats2half2_rn(s[mf][0][2], s[mf][0][3]); aP[mf][1] = *(u32*)&h;
            h = __floats2half2_rn(s[mf][1][0], s[mf][1][1]); aP[mf][2] = *(u32*)&h;
            h = __floats2half2_rn(s[mf][1][2], s[mf][1][3]); aP[mf][3] = *(u32*)&h;
        }
        u32 vf[4];
        {
            int r = jb * 16 + (lane & 7) + ((lane >> 3) & 1) * 8;
            ldm_x4t(vf[0], vf[1], vf[2], vf[3],
                    vb + r * AT_ROW + (lane >> 4) * 16);
        }
#pragma unroll
        for (int mf = 0; mf < 4; mf++)
#pragma unroll
            for (int np = 0; np < 2; np++) {
                u32 bfrag[2] = { vf[2 * np], vf[2 * np + 1] };
                mma_fp16(oacc[mf][np], aP[mf], bfrag);
            }
    }

#pragma unroll
    for (int mf = 0; mf < 4; mf++)
#pragma unroll
        for (int np = 0; np < 2; np++) {
            int ch = n * HD_ + np * 8 + t2 * 2;
#pragma unroll
            for (int h = 0; h < 2; h++) {
                int i = mf * 16 + g + h * 8;
                size_t tok = (PASS == 0) ? ((size_t)(b * 64 + i) * 64 + fixed)
                                         : ((size_t)(b * 64 + fixed) * 64 + i);
                float v0 = oacc[mf][np][h * 2];
                float v1 = oacc[mf][np][h * 2 + 1];
                if (PASS == 0) {
                    *(__half2*)(partial + tok * 128 + ch) =
                        __floats2half2_rn(v0, v1);
                } else {
                    float2 pr = __half22float2(
                        *(const __half2*)(partial + tok * 128 + ch));
                    *(__half2*)(out16 + tok * 128 + ch) =
                        __floats2half2_rn(pr.x + v0, pr.y + v1);
                }
            }
        }
}

// ---------------------------------------------------------------------------
extern "C" void kernel_launch(void* const* d_in, const int* in_sizes, int n_in,
                              void* d_out, int out_size) {
    const float* x      = (const float*)d_in[0];
    const float* cv1_w  = (const float*)d_in[1];
    const float* bn1_g  = (const float*)d_in[2];
    const float* bn1_b  = (const float*)d_in[3];
    const float* bn1_m  = (const float*)d_in[4];
    const float* bn1_v  = (const float*)d_in[5];
    const float* cv2_w  = (const float*)d_in[6];
    const float* bn2_g  = (const float*)d_in[7];
    const float* bn2_b  = (const float*)d_in[8];
    const float* bn2_m  = (const float*)d_in[9];
    const float* bn2_v  = (const float*)d_in[10];
    const float* ln1_g  = (const float*)d_in[11];
    const float* ln1_b  = (const float*)d_in[12];
    const float* qkv_w  = (const float*)d_in[13];
    const float* qkv_b  = (const float*)d_in[14];
    const float* proj_w = (const float*)d_in[15];
    const float* proj_b = (const float*)d_in[16];
    const float* gamma  = (const float*)d_in[17];
    const float* ln2_g  = (const float*)d_in[18];
    const float* ln2_b  = (const float*)d_in[19];
    const float* ffn_w1 = (const float*)d_in[20];
    const float* ffn_b1 = (const float*)d_in[21];
    const float* ffn_w2 = (const float*)d_in[22];
    const float* ffn_b2 = (const float*)d_in[23];
    float* out = (float*)d_out;

    __half *xt16, *cat16, *fn16, *qkv16, *attnp16, *attn16, *w16;
    float *y2f, *f2;
    cudaGetSymbolAddress((void**)&xt16,    g_xt16);
    cudaGetSymbolAddress((void**)&cat16,   g_cat16);
    cudaGetSymbolAddress((void**)&y2f,     g_y2f);
    cudaGetSymbolAddress((void**)&fn16,    g_fn16);
    cudaGetSymbolAddress((void**)&qkv16,   g_qkv16);
    cudaGetSymbolAddress((void**)&attnp16, g_attnp16);
    cudaGetSymbolAddress((void**)&attn16,  g_attn16);
    cudaGetSymbolAddress((void**)&f2,      g_f2);
    cudaGetSymbolAddress((void**)&w16,     g_w16);

    __half* w_cv1  = w16;
    __half* w_qkv  = w_cv1 + 65536;
    __half* w_proj = w_qkv + 49152;
    __half* w_f1   = w_proj + 16384;
    __half* w_f2   = w_f1 + 32768;
    __half* w_cv2  = w_f2 + 32768;

    cudaFuncSetAttribute(gemm128<EPI_CV1>,  cudaFuncAttributeMaxDynamicSharedMemorySize, SM128_BYTES);
    cudaFuncSetAttribute(gemm128<EPI_PROJ>, cudaFuncAttributeMaxDynamicSharedMemorySize, SM128_BYTES);
    cudaFuncSetAttribute(gemm64_nchw,       cudaFuncAttributeMaxDynamicSharedMemorySize, SM64_BYTES);
    cudaFuncSetAttribute(ffn_fused,         cudaFuncAttributeMaxDynamicSharedMemorySize, FF_SMEM);
    cudaFuncSetAttribute(attn_mma<0>,       cudaFuncAttributeMaxDynamicSharedMemorySize, AT_SMEM);
    cudaFuncSetAttribute(attn_mma<1>,       cudaFuncAttributeMaxDynamicSharedMemorySize, AT_SMEM);

    // 0) weights -> fp16
    convert_w_all<<<dim3(192, 6), 256>>>(cv1_w, qkv_w, proj_w, ffn_w1, ffn_w2,
                                         cv2_w, w16);

    // 1) x NCHW -> xt16
    transpose_x_kernel<<<dim3(HW_/32, C1_/32, B_), dim3(32, 8)>>>(x, xt16);

    // 2) cv1 + BN + SiLU -> cat16[:,0:256] (+ y2f) + fused LN1 + fused qkv
    gemm128<EPI_CV1><<<dim3(TOKENS/128, 2), 256, SM128_BYTES>>>(
        xt16, 256, w_cv1, 256, cat16, 384, bn1_g, bn1_b, bn1_m, bn1_v,
        nullptr, 0, ln1_g, ln1_b, nullptr, w_qkv, qkv_b, qkv16);

    // 3) attention H then W (shared-tile CTAs, fp16 partial)
    attn_mma<0><<<dim3(64, B_), 256, AT_SMEM>>>(qkv16, attnp16, attn16);
    attn_mma<1><<<dim3(64, B_), 256, AT_SMEM>>>(qkv16, attnp16, attn16);

    // 4) proj (+res y2, *gamma) -> f2 (+ fused LN2 -> fn16)
    gemm128<EPI_PROJ><<<dim3(TOKENS/128, 1), 256, SM128_BYTES>>>(
        attn16, 128, w_proj, 128, f2, 128, proj_b, gamma, nullptr, nullptr,
        y2f, 128, ln2_g, ln2_b, fn16, nullptr, nullptr, nullptr);

    // 5) fused ffn1(GELU)+ffn2 (+res f2) -> cat16[:,256:384]
    ffn_fused<<<TOKENS/64, 256, FF_SMEM>>>(
        fn16, w_f1, w_f2, ffn_b1, ffn_b2, f2, cat16);

    // 6) cv2 + BN + SiLU -> NCHW out
    gemm64_nchw<<<dim3(TOKENS/128, 4), 256, SM64_BYTES>>>(
        cat16, 384, w_cv2, 384, out, bn2_g, bn2_b, bn2_m, bn2_v);
}

// round 17
// speedup vs baseline: 1.2841x; 1.0141x over previous
#include <cuda_runtime.h>
#include <cuda_fp16.h>
#include <math.h>

#define B_ 16
#define C1_ 256
#define C2_ 256
#define H_ 64
#define W_ 64
#define NH_ 8
#define C_ 128
#define HD_ 16
#define HW_ (H_*W_)
#define TOKENS (B_*HW_)

typedef unsigned int u32;

// -------- static scratch -----------
__device__ __half g_xt16  [(size_t)TOKENS*256];
__device__ __half g_cat16 [(size_t)TOKENS*384];
__device__ float  g_y2f   [(size_t)TOKENS*128];
__device__ __half g_fn16  [(size_t)TOKENS*128];
__device__ __half g_qkv16 [(size_t)TOKENS*384];
__device__ __half g_attnp16[(size_t)TOKENS*128];
__device__ float  g_f2    [(size_t)TOKENS*128];
__device__ __half g_w16[65536+49152+16384+32768+32768+98304];

// ---------------------------------------------------------------------------
__device__ __forceinline__ u32 smem_u32(const void* p) {
    u32 a;
    asm("{ .reg .u64 t; cvta.to.shared.u64 t, %1; cvt.u32.u64 %0, t; }"
        : "=r"(a) : "l"(p));
    return a;
}
__device__ __forceinline__ void mma_fp16(float* c, const u32* a, const u32* b) {
    asm volatile(
        "mma.sync.aligned.m16n8k16.row.col.f32.f16.f16.f32 "
        "{%0,%1,%2,%3}, {%4,%5,%6,%7}, {%8,%9}, {%0,%1,%2,%3};"
        : "+f"(c[0]), "+f"(c[1]), "+f"(c[2]), "+f"(c[3])
        : "r"(a[0]), "r"(a[1]), "r"(a[2]), "r"(a[3]), "r"(b[0]), "r"(b[1]));
}
__device__ __forceinline__ void ldm_x4(u32& r0, u32& r1, u32& r2, u32& r3, u32 a) {
    asm volatile("ldmatrix.sync.aligned.m8n8.x4.shared.b16 {%0,%1,%2,%3}, [%4];"
        : "=r"(r0), "=r"(r1), "=r"(r2), "=r"(r3) : "r"(a));
}
__device__ __forceinline__ void ldm_x4t(u32& r0, u32& r1, u32& r2, u32& r3, u32 a) {
    asm volatile("ldmatrix.sync.aligned.m8n8.x4.trans.shared.b16 {%0,%1,%2,%3}, [%4];"
        : "=r"(r0), "=r"(r1), "=r"(r2), "=r"(r3) : "r"(a));
}
__device__ __forceinline__ void cp16(u32 dst, const void* src) {
    asm volatile("cp.async.cg.shared.global [%0], [%1], 16;" :: "r"(dst), "l"(src));
}

// ---------------------------------------------------------------------------
__global__ void convert_w_all(const float* __restrict__ s0, const float* __restrict__ s1,
                              const float* __restrict__ s2, const float* __restrict__ s3,
                              const float* __restrict__ s4, const float* __restrict__ s5,
                              __half* __restrict__ dst) {
    const int sizes[6] = {65536, 49152, 16384, 32768, 32768, 98304};
    const int offs [6] = {0, 65536, 114688, 131072, 163840, 196608};
    int t = blockIdx.y;
    const float* src = t == 0 ? s0 : t == 1 ? s1 : t == 2 ? s2 :
                       t == 3 ? s3 : t == 4 ? s4 : s5;
    int n2 = sizes[t] >> 1;
    int i = blockIdx.x * 256 + threadIdx.x;
    if (i < n2) {
        float2 v = *(const float2*)(src + 2 * i);
        *(__half2*)(dst + offs[t] + 2 * i) = __floats2half2_rn(v.x, v.y);
    }
}

__global__ void transpose_x_kernel(const float* __restrict__ x,
                                   __half* __restrict__ xt) {
    __shared__ float tile[32][33];
    int b  = blockIdx.z;
    int p0 = blockIdx.x * 32;
    int c0 = blockIdx.y * 32;
    const float* xb = x + (size_t)b * C1_ * HW_;
    __half*     xtb = xt + (size_t)b * HW_ * C1_;
#pragma unroll
    for (int i = 0; i < 32; i += 8)
        tile[threadIdx.y + i][threadIdx.x] =
            xb[(size_t)(c0 + threadIdx.y + i) * HW_ + p0 + threadIdx.x];
    __syncthreads();
#pragma unroll
    for (int i = 0; i < 32; i += 8)
        xtb[(size_t)(p0 + threadIdx.y + i) * C1_ + c0 + threadIdx.x] =
            __float2half_rn(tile[threadIdx.x][threadIdx.y + i]);
}

// ---------------------------------------------------------------------------
// gemm128 (EPI_CV1 only): CTA 128x128, fused BN+SiLU; y==1 also register-LN1
// + in-SMEM qkv GEMM (unchanged from R11/R12 winner).
// ---------------------------------------------------------------------------
#define STG128 36864
#define SM128_BYTES (2*STG128)
#define FQ_FNS 4096
#define FQ_W   38912

__global__ void __launch_bounds__(256, 2)
gemm_cv1(const __half* __restrict__ A, int lda,
         const __half* __restrict__ Wt, int K,
         __half* __restrict__ Cpv,
         const float* __restrict__ p0, const float* __restrict__ p1,
         const float* __restrict__ p2, const float* __restrict__ p3,
         const float* __restrict__ lng, const float* __restrict__ lnb,
         const __half* __restrict__ Wq, const float* __restrict__ qbias,
         __half* __restrict__ qkvout) {
    extern __shared__ __align__(16) char smem[];
    const u32 sb = smem_u32(smem);
    const int tid = threadIdx.x, wid = tid >> 5, lane = tid & 31;
    const int wm = (wid >> 2) * 64, wn = (wid & 3) * 32;
    const int g = lane >> 2, t2 = lane & 3;
    const int row0 = blockIdx.x * 128, col0 = blockIdx.y * 128;
    const int lrow = tid >> 3, lc8 = tid & 7;

    float acc[4][4][4];
#pragma unroll
    for (int i = 0; i < 4; i++)
#pragma unroll
        for (int j = 0; j < 4; j++)
#pragma unroll
            for (int q = 0; q < 4; q++) acc[i][j][q] = 0.f;

    const int nch = K >> 6;
    auto issue = [&](int c) {
        u32 ab = sb + (c & 1) * STG128;
        u32 bb = ab + 18432;
        const __half* Ag = A  + (size_t)row0 * lda + c * 64;
        const __half* Bg = Wt + (size_t)col0 * K   + c * 64;
#pragma unroll
        for (int i = 0; i < 4; i++) {
            int r = i * 32 + lrow;
            cp16(ab + r * 144 + lc8 * 16, Ag + (size_t)r * lda + lc8 * 8);
            cp16(bb + r * 144 + lc8 * 16, Bg + (size_t)r * K   + lc8 * 8);
        }
    };

    issue(0);
    asm volatile("cp.async.commit_group;");
    for (int c = 0; c < nch; c++) {
        if (c + 1 < nch) {
            issue(c + 1);
            asm volatile("cp.async.commit_group;");
            asm volatile("cp.async.wait_group 1;");
        } else {
            asm volatile("cp.async.wait_group 0;");
        }
        __syncthreads();
        u32 ab = sb + (c & 1) * STG128;
        u32 bb = ab + 18432;
#pragma unroll
        for (int kb = 0; kb < 4; kb++) {
            u32 a[4][4], b[4][2];
#pragma unroll
            for (int mf = 0; mf < 4; mf++) {
                int r = wm + mf * 16 + (lane & 7) + ((lane >> 3) & 1) * 8;
                ldm_x4(a[mf][0], a[mf][1], a[mf][2], a[mf][3],
                       ab + r * 144 + kb * 32 + (lane >> 4) * 16);
            }
#pragma unroll
            for (int np = 0; np < 2; np++) {
                int r = wn + np * 16 + (lane & 7) + ((lane >> 4) & 1) * 8;
                ldm_x4(b[2*np][0], b[2*np][1], b[2*np+1][0], b[2*np+1][1],
                       bb + r * 144 + kb * 32 + ((lane >> 3) & 1) * 16);
            }
#pragma unroll
            for (int mf = 0; mf < 4; mf++)
#pragma unroll
                for (int nf = 0; nf < 4; nf++)
                    mma_fp16(acc[mf][nf], a[mf], b[nf]);
        }
        __syncthreads();
    }

    const bool fuseQ = (blockIdx.y == 1);
    auto issueWq = [&](int nc) {
        u32 d = sb + FQ_W + (u32)(nc & 1) * 17408;
#pragma unroll
        for (int i = 0; i < 4; i++) {
            int idx = tid + i * 256;
            int r = idx >> 4, c2 = idx & 15;
            cp16(d + r * 272 + c2 * 16, Wq + (size_t)(nc * 64 + r) * 128 + c2 * 8);
        }
    };
    if (fuseQ) {
        issueWq(0);
        asm volatile("cp.async.commit_group;");
        issueWq(1);
        asm volatile("cp.async.commit_group;");
    }

#pragma unroll
    for (int mf = 0; mf < 4; mf++) {
#pragma unroll
        for (int nf = 0; nf < 4; nf++) {
            int lcol = wn + nf * 8 + t2 * 2;
            int col  = col0 + lcol;
            float e0 = p0[col]     * rsqrtf(p3[col]     + 1e-5f);
            float e1 = p0[col + 1] * rsqrtf(p3[col + 1] + 1e-5f);
            float f0 = p1[col]     - p2[col]     * e0;
            float f1 = p1[col + 1] - p2[col + 1] * e1;
#pragma unroll
            for (int h = 0; h < 2; h++) {
                int row = row0 + wm + mf * 16 + g + h * 8;
                float v0 = acc[mf][nf][h * 2]     * e0 + f0;
                float v1 = acc[mf][nf][h * 2 + 1] * e1 + f1;
                v0 = v0 / (1.f + __expf(-v0));
                v1 = v1 / (1.f + __expf(-v1));
                *(__half2*)(Cpv + (size_t)row * 384 + col) =
                    __floats2half2_rn(v0, v1);
                if (fuseQ)
                    *(float2*)(g_y2f + (size_t)row * 128 + lcol) =
                        make_float2(v0, v1);
                acc[mf][nf][h * 2]     = v0;
                acc[mf][nf][h * 2 + 1] = v1;
            }
        }
    }
    if (fuseQ) {
        float* part = (float*)smem;
#pragma unroll
        for (int mf = 0; mf < 4; mf++)
#pragma unroll
            for (int h = 0; h < 2; h++) {
                float s = 0.f, qq = 0.f;
#pragma unroll
                for (int nf = 0; nf < 4; nf++) {
                    float a0 = acc[mf][nf][h * 2];
                    float a1 = acc[mf][nf][h * 2 + 1];
                    s += a0 + a1;
                    qq += a0 * a0 + a1 * a1;
                }
                s  += __shfl_xor_sync(~0u, s, 1);
                s  += __shfl_xor_sync(~0u, s, 2);
                qq += __shfl_xor_sync(~0u, qq, 1);
                qq += __shfl_xor_sync(~0u, qq, 2);
                if (t2 == 0) {
                    int r = wm + mf * 16 + g + h * 8;
                    part[r * 8 + (wid & 3) * 2]     = s;
                    part[r * 8 + (wid & 3) * 2 + 1] = qq;
                }
            }
        __syncthreads();
#pragma unroll
        for (int mf = 0; mf < 4; mf++)
#pragma unroll
            for (int h = 0; h < 2; h++) {
                int r = wm + mf * 16 + g + h * 8;
                float s  = part[r*8] + part[r*8+2] + part[r*8+4] + part[r*8+6];
                float qq = part[r*8+1] + part[r*8+3] + part[r*8+5] + part[r*8+7];
                float mu  = s * (1.f / 128.f);
                float var = qq * (1.f / 128.f) - mu * mu;
                float rsd = rsqrtf(var + 1e-5f);
#pragma unroll
                for (int nf = 0; nf < 4; nf++) {
                    int lcol = wn + nf * 8 + t2 * 2;
                    float f0 = (acc[mf][nf][h*2]   - mu) * rsd * lng[lcol]   + lnb[lcol];
                    float f1 = (acc[mf][nf][h*2+1] - mu) * rsd * lng[lcol+1] + lnb[lcol+1];
                    *(__half2*)(smem + FQ_FNS + r * 272 + lcol * 2) =
                        __floats2half2_rn(f0, f1);
                }
            }
        __syncthreads();

        const int wm2 = (wid >> 1) * 32, wn2 = (wid & 1) * 32;
        for (int nc = 0; nc < 6; nc++) {
            if (nc < 5) asm volatile("cp.async.wait_group 1;");
            else        asm volatile("cp.async.wait_group 0;");
            __syncthreads();
            float qa[2][4][4];
#pragma unroll
            for (int i = 0; i < 2; i++)
#pragma unroll
                for (int j = 0; j < 4; j++)
#pragma unroll
                    for (int q = 0; q < 4; q++) qa[i][j][q] = 0.f;
            u32 ab2 = sb + FQ_FNS;
            u32 bb2 = sb + FQ_W + (u32)(nc & 1) * 17408;
#pragma unroll
            for (int kb = 0; kb < 8; kb++) {
                u32 a[2][4], b[4][2];
#pragma unroll
                for (int mf = 0; mf < 2; mf++) {
                    int r = wm2 + mf * 16 + (lane & 7) + ((lane >> 3) & 1) * 8;
                    ldm_x4(a[mf][0], a[mf][1], a[mf][2], a[mf][3],
                           ab2 + r * 272 + kb * 32 + (lane >> 4) * 16);
                }
#pragma unroll
                for (int np = 0; np < 2; np++) {
                    int r = wn2 + np * 16 + (lane & 7) + ((lane >> 4) & 1) * 8;
                    ldm_x4(b[2*np][0], b[2*np][1], b[2*np+1][0], b[2*np+1][1],
                           bb2 + r * 272 + kb * 32 + ((lane >> 3) & 1) * 16);
                }
#pragma unroll
                for (int mf = 0; mf < 2; mf++)
#pragma unroll
                    for (int nf = 0; nf < 4; nf++)
                        mma_fp16(qa[mf][nf], a[mf], b[nf]);
            }
#pragma unroll
            for (int mf = 0; mf < 2; mf++)
#pragma unroll
                for (int nf = 0; nf < 4; nf++) {
                    int col = nc * 64 + wn2 + nf * 8 + t2 * 2;
                    float e0 = qbias[col], e1 = qbias[col + 1];
#pragma unroll
                    for (int h = 0; h < 2; h++) {
                        int row = row0 + wm2 + mf * 16 + g + h * 8;
                        *(__half2*)(qkvout + (size_t)row * 384 + col) =
                            __floats2half2_rn(qa[mf][nf][h*2] + e0,
                                              qa[mf][nf][h*2+1] + e1);
                    }
                }
            __syncthreads();
            if (nc + 2 < 6) {
                issueWq(nc + 2);
                asm volatile("cp.async.commit_group;");
            }
        }
    }
}

// ---------------------------------------------------------------------------
// gemm64_nchw (cv2 only, unchanged)
// ---------------------------------------------------------------------------
#define STG64 27648
#define SM64_BYTES (2*STG64)

__global__ void __launch_bounds__(256, 3)
gemm64_nchw(const __half* __restrict__ A, int lda,
            const __half* __restrict__ Wt, int K,
            float* __restrict__ Cp,
            const float* __restrict__ p0, const float* __restrict__ p1,
            const float* __restrict__ p2, const float* __restrict__ p3) {
    extern __shared__ __align__(16) char smem[];
    const u32 sb = smem_u32(smem);
    const int tid = threadIdx.x, wid = tid >> 5, lane = tid & 31;
    const int wm = (wid >> 1) * 32, wn = (wid & 1) * 32;
    const int g = lane >> 2, t2 = lane & 3;
    const int row0 = blockIdx.x * 128, col0 = blockIdx.y * 64;
    const int lrow = tid >> 3, lc8 = tid & 7;

    float acc[2][4][4];
#pragma unroll
    for (int i = 0; i < 2; i++)
#pragma unroll
        for (int j = 0; j < 4; j++)
#pragma unroll
            for (int q = 0; q < 4; q++) acc[i][j][q] = 0.f;

    const int nch = K >> 6;
    auto issue = [&](int c) {
        u32 ab = sb + (c & 1) * STG64;
        u32 bb = ab + 18432;
        const __half* Ag = A  + (size_t)row0 * lda + c * 64;
        const __half* Bg = Wt + (size_t)col0 * K   + c * 64;
#pragma unroll
        for (int i = 0; i < 4; i++) {
            int r = i * 32 + lrow;
            cp16(ab + r * 144 + lc8 * 16, Ag + (size_t)r * lda + lc8 * 8);
        }
#pragma unroll
        for (int i = 0; i < 2; i++) {
            int r = i * 32 + lrow;
            cp16(bb + r * 144 + lc8 * 16, Bg + (size_t)r * K + lc8 * 8);
        }
    };

    issue(0);
    asm volatile("cp.async.commit_group;");
    for (int c = 0; c < nch; c++) {
        if (c + 1 < nch) {
            issue(c + 1);
            asm volatile("cp.async.commit_group;");
            asm volatile("cp.async.wait_group 1;");
        } else {
            asm volatile("cp.async.wait_group 0;");
        }
        __syncthreads();
        u32 ab = sb + (c & 1) * STG64;
        u32 bb = ab + 18432;
#pragma unroll
        for (int kb = 0; kb < 4; kb++) {
            u32 a[2][4], b[4][2];
#pragma unroll
            for (int mf = 0; mf < 2; mf++) {
                int r = wm + mf * 16 + (lane & 7) + ((lane >> 3) & 1) * 8;
                ldm_x4(a[mf][0], a[mf][1], a[mf][2], a[mf][3],
                       ab + r * 144 + kb * 32 + (lane >> 4) * 16);
            }
#pragma unroll
            for (int np = 0; np < 2; np++) {
                int r = wn + np * 16 + (lane & 7) + ((lane >> 4) & 1) * 8;
                ldm_x4(b[2*np][0], b[2*np][1], b[2*np+1][0], b[2*np+1][1],
                       bb + r * 144 + kb * 32 + ((lane >> 3) & 1) * 16);
            }
#pragma unroll
            for (int mf = 0; mf < 2; mf++)
#pragma unroll
                for (int nf = 0; nf < 4; nf++)
                    mma_fp16(acc[mf][nf], a[mf], b[nf]);
        }
        __syncthreads();
    }

    float* stg = (float*)smem;
#pragma unroll
    for (int mf = 0; mf < 2; mf++)
#pragma unroll
        for (int nf = 0; nf < 4; nf++) {
            int r = wm + mf * 16 + g;
            int cl = wn + nf * 8 + t2 * 2;
            stg[r * 65 + cl]           = acc[mf][nf][0];
            stg[r * 65 + cl + 1]       = acc[mf][nf][1];
            stg[(r + 8) * 65 + cl]     = acc[mf][nf][2];
            stg[(r + 8) * 65 + cl + 1] = acc[mf][nf][3];
        }
    __syncthreads();
    for (int it = 0; it < 32; it++) {
        int idx  = it * 256 + tid;
        int lcol = idx >> 7;
        int r    = idx & 127;
        int col  = col0 + lcol;
        int row  = row0 + r;
        float v  = stg[r * 65 + lcol];
        float sc = p0[col] * rsqrtf(p3[col] + 1e-5f);
        v = v * sc + (p1[col] - p2[col] * sc);
        v = v / (1.f + __expf(-v));
        Cp[(((size_t)(row >> 12)) * C2_ + col) * 4096 + (row & 4095)] = v;
    }
}

// ---------------------------------------------------------------------------
// ffn_fused (unchanged)
// ---------------------------------------------------------------------------
#define FF_AOFF  0
#define FF_WOFF  17408
#define FF_H1OFF 52224
#define FF_SMEM  86016

__global__ void __launch_bounds__(256, 2)
ffn_fused(const __half* __restrict__ fn, const __half* __restrict__ w1,
          const __half* __restrict__ w2, const float* __restrict__ b1,
          const float* __restrict__ b2, const float* __restrict__ f2res,
          __half* __restrict__ outc) {
    extern __shared__ __align__(16) char smem[];
    const u32 sb = smem_u32(smem);
    const int tid = threadIdx.x, wid = tid >> 5, lane = tid & 31;
    const int wm = (wid >> 2) * 32, wn = (wid & 3) * 16;
    const int g = lane >> 2, t2 = lane & 3;
    const int row0 = blockIdx.x * 64;

#pragma unroll
    for (int i = 0; i < 4; i++) {
        int idx = tid + i * 256;
        int r = idx >> 4, c = idx & 15;
        cp16(sb + FF_AOFF + r * 272 + c * 16,
             fn + (size_t)(row0 + r) * 128 + c * 8);
    }
    auto issueW1 = [&](int nc) {
        u32 d = sb + FF_WOFF + (u32)(nc & 1) * 17408;
#pragma unroll
        for (int i = 0; i < 4; i++) {
            int idx = tid + i * 256;
            int r = idx >> 4, c = idx & 15;
            cp16(d + r * 272 + c * 16, w1 + (size_t)(nc * 64 + r) * 128 + c * 8);
        }
    };
    issueW1(0);
    asm volatile("cp.async.commit_group;");
    issueW1(1);
    asm volatile("cp.async.commit_group;");

    float acc[2][2][4];
    for (int nc = 0; nc < 4; nc++) {
        if (nc < 3) asm volatile("cp.async.wait_group 1;");
        else        asm volatile("cp.async.wait_group 0;");
        __syncthreads();
#pragma unroll
        for (int i = 0; i < 2; i++)
#pragma unroll
            for (int j = 0; j < 2; j++)
#pragma unroll
                for (int q = 0; q < 4; q++) acc[i][j][q] = 0.f;
        u32 ab = sb + FF_AOFF;
        u32 bb = sb + FF_WOFF + (u32)(nc & 1) * 17408;
#pragma unroll
        for (int kb = 0; kb < 8; kb++) {
            u32 a[2][4], b[2][2];
#pragma unroll
            for (int mf = 0; mf < 2; mf++) {
                int r = wm + mf * 16 + (lane & 7) + ((lane >> 3) & 1) * 8;
                ldm_x4(a[mf][0], a[mf][1], a[mf][2], a[mf][3],
                       ab + r * 272 + kb * 32 + (lane >> 4) * 16);
            }
            {
                int r = wn + (lane & 7) + ((lane >> 4) & 1) * 8;
                ldm_x4(b[0][0], b[0][1], b[1][0], b[1][1],
                       bb + r * 272 + kb * 32 + ((lane >> 3) & 1) * 16);
            }
#pragma unroll
            for (int mf = 0; mf < 2; mf++)
#pragma unroll
                for (int nf = 0; nf < 2; nf++)
                    mma_fp16(acc[mf][nf], a[mf], b[nf]);
        }
#pragma unroll
        for (int mf = 0; mf < 2; mf++)
#pragma unroll
            for (int nf = 0; nf < 2; nf++) {
                int col = nc * 64 + wn + nf * 8 + t2 * 2;
                float e0 = b1[col], e1 = b1[col + 1];
#pragma unroll
                for (int h = 0; h < 2; h++) {
                    int r = wm + mf * 16 + g + h * 8;
                    float v0 = acc[mf][nf][h * 2] + e0;
                    float v1 = acc[mf][nf][h * 2 + 1] + e1;
                    v0 = 0.5f * v0 * (1.f + erff(v0 * 0.70710678118654752f));
                    v1 = 0.5f * v1 * (1.f + erff(v1 * 0.70710678118654752f));
                    *(__half2*)(smem + FF_H1OFF + r * 528 + col * 2) =
                        __floats2half2_rn(v0, v1);
                }
            }
        __syncthreads();
        if (nc + 2 < 4) {
            issueW1(nc + 2);
            asm volatile("cp.async.commit_group;");
        }
    }

    for (int nc2 = 0; nc2 < 2; nc2++) {
#pragma unroll
        for (int i = 0; i < 8; i++) {
            int idx = tid + i * 256;
            int r = idx >> 5, c = idx & 31;
            cp16(sb + FF_WOFF + r * 528 + c * 16,
                 w2 + (size_t)(nc2 * 64 + r) * 256 + c * 8);
        }
        asm volatile("cp.async.commit_group;");
        asm volatile("cp.async.wait_group 0;");
        __syncthreads();
#pragma unroll
        for (int i = 0; i < 2; i++)
#pragma unroll
            for (int j = 0; j < 2; j++)
#pragma unroll
                for (int q = 0; q < 4; q++) acc[i][j][q] = 0.f;
        u32 ab = sb + FF_H1OFF;
        u32 bb = sb + FF_WOFF;
#pragma unroll
        for (int kb = 0; kb < 16; kb++) {
            u32 a[2][4], b[2][2];
#pragma unroll
            for (int mf = 0; mf < 2; mf++) {
                int r = wm + mf * 16 + (lane & 7) + ((lane >> 3) & 1) * 8;
                ldm_x4(a[mf][0], a[mf][1], a[mf][2], a[mf][3],
                       ab + r * 528 + kb * 32 + (lane >> 4) * 16);
            }
            {
                int r = wn + (lane & 7) + ((lane >> 4) & 1) * 8;
                ldm_x4(b[0][0], b[0][1], b[1][0], b[1][1],
                       bb + r * 528 + kb * 32 + ((lane >> 3) & 1) * 16);
            }
#pragma unroll
            for (int mf = 0; mf < 2; mf++)
#pragma unroll
                for (int nf = 0; nf < 2; nf++)
                    mma_fp16(acc[mf][nf], a[mf], b[nf]);
        }
        __syncthreads();
#pragma unroll
        for (int mf = 0; mf < 2; mf++)
#pragma unroll
            for (int nf = 0; nf < 2; nf++) {
                int col = nc2 * 64 + wn + nf * 8 + t2 * 2;
                float e0 = b2[col], e1 = b2[col + 1];
#pragma unroll
                for (int h = 0; h < 2; h++) {
                    int row = row0 + wm + mf * 16 + g + h * 8;
                    float2 rs = *(const float2*)(f2res + (size_t)row * 128 + col);
                    float v0 = acc[mf][nf][h * 2] + e0 + rs.x;
                    float v1 = acc[mf][nf][h * 2 + 1] + e1 + rs.y;
                    *(__half2*)(outc + (size_t)row * 384 + 256 + col) =
                        __floats2half2_rn(v0, v1);
                }
            }
    }
}

// ---------------------------------------------------------------------------
// Attention pass 0 (H): shared 64x384 qkv tile, 8 warps = 8 heads,
// writes fp16 partial (0.5 folded into decay).
// ---------------------------------------------------------------------------
#define AT_ROW  784
#define AT_DEC  50176
#define AT_SMEM0 (50176 + 2048)

__global__ void __launch_bounds__(256)
attn_pass0(const __half* __restrict__ qkv, __half* __restrict__ partial) {
    extern __shared__ __align__(16) char smem[];
    const u32 sb = smem_u32(smem);
    const int tid = threadIdx.x, wid = tid >> 5, lane = tid & 31;
    const int g = lane >> 2, t2 = lane & 3;
    const int fixed = blockIdx.x;
    const int b = blockIdx.y;
    const int n = wid;
    float* decrow = (float*)(smem + AT_DEC);

    {
        float dec = logf(1.f - exp2f(-2.f - 0.5f * (float)wid));
        decrow[wid * 64 + lane]      = 0.5f * __expf(dec * (float)lane);
        decrow[wid * 64 + lane + 32] = 0.5f * __expf(dec * (float)(lane + 32));
    }

#pragma unroll
    for (int i = 0; i < 12; i++) {
        int idx = i * 256 + tid;
        int r = idx / 48, c = idx - r * 48;
        size_t tok = (size_t)(b * 64 + r) * 64 + fixed;
        cp16(sb + r * AT_ROW + c * 16, qkv + tok * 384 + c * 8);
    }
    asm volatile("cp.async.commit_group;");
    asm volatile("cp.async.wait_group 0;");
    __syncthreads();

    const u32 qb = sb + n * 32;
    const u32 kb = sb + 256 + n * 32;
    const u32 vb = sb + 512 + n * 32;

    u32 qa[4][4];
#pragma unroll
    for (int mf = 0; mf < 4; mf++) {
        int r = mf * 16 + (lane & 7) + ((lane >> 3) & 1) * 8;
        ldm_x4(qa[mf][0], qa[mf][1], qa[mf][2], qa[mf][3],
               qb + r * AT_ROW + (lane >> 4) * 16);
    }

    float oacc[4][2][4];
#pragma unroll
    for (int i = 0; i < 4; i++)
#pragma unroll
        for (int j = 0; j < 2; j++)
#pragma unroll
            for (int q = 0; q < 4; q++) oacc[i][j][q] = 0.f;

#pragma unroll
    for (int jb = 0; jb < 4; jb++) {
        u32 kf[4];
        {
            int r = jb * 16 + (lane & 7) + ((lane >> 4) & 1) * 8;
            ldm_x4(kf[0], kf[1], kf[2], kf[3],
                   kb + r * AT_ROW + ((lane >> 3) & 1) * 16);
        }
        float s[4][2][4];
#pragma unroll
        for (int mf = 0; mf < 4; mf++)
#pragma unroll
            for (int np = 0; np < 2; np++) {
#pragma unroll
                for (int q = 0; q < 4; q++) s[mf][np][q] = 0.f;
                u32 bfrag[2] = { kf[2 * np], kf[2 * np + 1] };
                mma_fp16(s[mf][np], qa[mf], bfrag);
            }
        u32 aP[4][4];
#pragma unroll
        for (int mf = 0; mf < 4; mf++) {
#pragma unroll
            for (int np = 0; np < 2; np++) {
                int i0 = mf * 16 + g;
                int j0 = jb * 16 + np * 8 + t2 * 2;
                int d00 = i0 - j0;       d00 = d00 < 0 ? -d00 : d00;
                int d01 = i0 - j0 - 1;   d01 = d01 < 0 ? -d01 : d01;
                int d10 = i0 + 8 - j0;   d10 = d10 < 0 ? -d10 : d10;
                int d11 = i0 + 7 - j0;   d11 = d11 < 0 ? -d11 : d11;
                s[mf][np][0] *= decrow[n * 64 + d00];
                s[mf][np][1] *= decrow[n * 64 + d01];
                s[mf][np][2] *= decrow[n * 64 + d10];
                s[mf][np][3] *= decrow[n * 64 + d11];
            }
            __half2 h;
            h = __floats2half2_rn(s[mf][0][0], s[mf][0][1]); aP[mf][0] = *(u32*)&h;
            h = __floats2half2_rn(s[mf][0][2], s[mf][0][3]); aP[mf][1] = *(u32*)&h;
            h = __floats2half2_rn(s[mf][1][0], s[mf][1][1]); aP[mf][2] = *(u32*)&h;
            h = __floats2half2_rn(s[mf][1][2], s[mf][1][3]); aP[mf][3] = *(u32*)&h;
        }
        u32 vf[4];
        {
            int r = jb * 16 + (lane & 7) + ((lane >> 3) & 1) * 8;
            ldm_x4t(vf[0], vf[1], vf[2], vf[3],
                    vb + r * AT_ROW + (lane >> 4) * 16);
        }
#pragma unroll
        for (int mf = 0; mf < 4; mf++)
#pragma unroll
            for (int np = 0; np < 2; np++) {
                u32 bfrag[2] = { vf[2 * np], vf[2 * np + 1] };
                mma_fp16(oacc[mf][np], aP[mf], bfrag);
            }
    }

#pragma unroll
    for (int mf = 0; mf < 4; mf++)
#pragma unroll
        for (int np = 0; np < 2; np++) {
            int ch = n * HD_ + np * 8 + t2 * 2;
#pragma unroll
            for (int h = 0; h < 2; h++) {
                int i = mf * 16 + g + h * 8;
                size_t tok = (size_t)(b * 64 + i) * 64 + fixed;
                *(__half2*)(partial + tok * 128 + ch) =
                    __floats2half2_rn(oacc[mf][np][h * 2],
                                      oacc[mf][np][h * 2 + 1]);
            }
        }
}

// ---------------------------------------------------------------------------
// Attention pass 1 (W) + proj + residual*gamma + LN2, all in one CTA.
// CTA = (fixed h-row, b): 64 contiguous tokens. smem:
//   [0, 50176)  qkv tile (784B rows); reused as att tile (272B rows, 17408B)
//   [50176, 52224) decay
//   [52224, 87040) w_proj (272B rows, 34816B); reused as fp32 LN staging 33024B
// ---------------------------------------------------------------------------
#define AP_WP   52224
#define AP_SMEM 87040

__global__ void __launch_bounds__(256)
attn_proj_ln(const __half* __restrict__ qkv,
             const __half* __restrict__ partial,
             const __half* __restrict__ wp,
             const float* __restrict__ pbias, const float* __restrict__ gamma,
             const float* __restrict__ y2f,
             float* __restrict__ f2out,
             const float* __restrict__ lng, const float* __restrict__ lnb,
             __half* __restrict__ fnout) {
    extern __shared__ __align__(16) char smem[];
    const u32 sb = smem_u32(smem);
    const int tid = threadIdx.x, wid = tid >> 5, lane = tid & 31;
    const int g = lane >> 2, t2 = lane & 3;
    const int fixed = blockIdx.x;
    const int b = blockIdx.y;
    const int n = wid;
    const size_t base = (size_t)(b * 64 + fixed) * 64;   // first of 64 tokens
    float* decrow = (float*)(smem + AT_DEC);

    {
        float dec = logf(1.f - exp2f(-2.f - 0.5f * (float)wid));
        decrow[wid * 64 + lane]      = 0.5f * __expf(dec * (float)lane);
        decrow[wid * 64 + lane + 32] = 0.5f * __expf(dec * (float)(lane + 32));
    }

    // qkv tile (group A) then w_proj (group B)
#pragma unroll
    for (int i = 0; i < 12; i++) {
        int idx = i * 256 + tid;
        int r = idx / 48, c = idx - r * 48;
        cp16(sb + r * AT_ROW + c * 16, qkv + (base + r) * 384 + c * 8);
    }
    asm volatile("cp.async.commit_group;");
#pragma unroll
    for (int i = 0; i < 8; i++) {
        int idx = i * 256 + tid;
        int r = idx >> 4, c = idx & 15;
        cp16(sb + AP_WP + r * 272 + c * 16, wp + (size_t)r * 128 + c * 8);
    }
    asm volatile("cp.async.commit_group;");
    asm volatile("cp.async.wait_group 1;");   // qkv ready (wp may lag)
    __syncthreads();

    const u32 qb = sb + n * 32;
    const u32 kb = sb + 256 + n * 32;
    const u32 vb = sb + 512 + n * 32;

    u32 qa[4][4];
#pragma unroll
    for (int mf = 0; mf < 4; mf++) {
        int r = mf * 16 + (lane & 7) + ((lane >> 3) & 1) * 8;
        ldm_x4(qa[mf][0], qa[mf][1], qa[mf][2], qa[mf][3],
               qb + r * AT_ROW + (lane >> 4) * 16);
    }

    float oacc[4][2][4];
#pragma unroll
    for (int i = 0; i < 4; i++)
#pragma unroll
        for (int j = 0; j < 2; j++)
#pragma unroll
            for (int q = 0; q < 4; q++) oacc[i][j][q] = 0.f;

#pragma unroll
    for (int jb = 0; jb < 4; jb++) {
        u32 kf[4];
        {
            int r = jb * 16 + (lane & 7) + ((lane >> 4) & 1) * 8;
            ldm_x4(kf[0], kf[1], kf[2], kf[3],
                   kb + r * AT_ROW + ((lane >> 3) & 1) * 16);
        }
        float s[4][2][4];
#pragma unroll
        for (int mf = 0; mf < 4; mf++)
#pragma unroll
            for (int np = 0; np < 2; np++) {
#pragma unroll
                for (int q = 0; q < 4; q++) s[mf][np][q] = 0.f;
                u32 bfrag[2] = { kf[2 * np], kf[2 * np + 1] };
                mma_fp16(s[mf][np], qa[mf], bfrag);
            }
        u32 aP[4][4];
#pragma unroll
        for (int mf = 0; mf < 4; mf++) {
#pragma unroll
            for (int np = 0; np < 2; np++) {
                int i0 = mf * 16 + g;
                int j0 = jb * 16 + np * 8 + t2 * 2;
                int d00 = i0 - j0;       d00 = d00 < 0 ? -d00 : d00;
                int d01 = i0 - j0 - 1;   d01 = d01 < 0 ? -d01 : d01;
                int d10 = i0 + 8 - j0;   d10 = d10 < 0 ? -d10 : d10;
                int d11 = i0 + 7 - j0;   d11 = d11 < 0 ? -d11 : d11;
                s[mf][np][0] *= decrow[n * 64 + d00];
                s[mf][np][1] *= decrow[n * 64 + d01];
                s[mf][np][2] *= decrow[n * 64 + d10];
                s[mf][np][3] *= decrow[n * 64 + d11];
            }
            __half2 h;
            h = __floats2half2_rn(s[mf][0][0], s[mf][0][1]); aP[mf][0] = *(u32*)&h;
            h = __floats2half2_rn(s[mf][0][2], s[mf][0][3]); aP[mf][1] = *(u32*)&h;
            h = __floats2half2_rn(s[mf][1][0], s[mf][1][1]); aP[mf][2] = *(u32*)&h;
            h = __floats2half2_rn(s[mf][1][2], s[mf][1][3]); aP[mf][3] = *(u32*)&h;
        }
        u32 vf[4];
        {
            int r = jb * 16 + (lane & 7) + ((lane >> 3) & 1) * 8;
            ldm_x4t(vf[0], vf[1], vf[2], vf[3],
                    vb + r * AT_ROW + (lane >> 4) * 16);
        }
#pragma unroll
        for (int mf = 0; mf < 4; mf++)
#pragma unroll
            for (int np = 0; np < 2; np++) {
                u32 bfrag[2] = { vf[2 * np], vf[2 * np + 1] };
                mma_fp16(oacc[mf][np], aP[mf], bfrag);
            }
    }
    __syncthreads();   // all qkv reads done -> att tile may overwrite

    // combine with H-pass partial, store att tile fp16 (272B rows)
#pragma unroll
    for (int mf = 0; mf < 4; mf++)
#pragma unroll
        for (int np = 0; np < 2; np++) {
            int ch = n * HD_ + np * 8 + t2 * 2;
#pragma unroll
            for (int h = 0; h < 2; h++) {
                int r = mf * 16 + g + h * 8;
                float2 pr = __half22float2(
                    *(const __half2*)(partial + (base + r) * 128 + ch));
                *(__half2*)(smem + r * 272 + ch * 2) =
                    __floats2half2_rn(pr.x + oacc[mf][np][h * 2],
                                      pr.y + oacc[mf][np][h * 2 + 1]);
            }
        }
    asm volatile("cp.async.wait_group 0;");   // w_proj ready
    __syncthreads();

    // proj GEMM: [64 x 128] = att[64x128] @ wp^T. 8 warps = 2m x 4n (32x32).
    const int wm3 = (wid >> 2) * 32, wn3 = (wid & 3) * 32;
    float pa[2][4][4];
#pragma unroll
    for (int i = 0; i < 2; i++)
#pragma unroll
        for (int j = 0; j < 4; j++)
#pragma unroll
            for (int q = 0; q < 4; q++) pa[i][j][q] = 0.f;
#pragma unroll
    for (int kb2 = 0; kb2 < 8; kb2++) {
        u32 a[2][4], bfr[4][2];
#pragma unroll
        for (int mf = 0; mf < 2; mf++) {
            int r = wm3 + mf * 16 + (lane & 7) + ((lane >> 3) & 1) * 8;
            ldm_x4(a[mf][0], a[mf][1], a[mf][2], a[mf][3],
                   sb + r * 272 + kb2 * 32 + (lane >> 4) * 16);
        }
#pragma unroll
        for (int np = 0; np < 2; np++) {
            int r = wn3 + np * 16 + (lane & 7) + ((lane >> 4) & 1) * 8;
            ldm_x4(bfr[2*np][0], bfr[2*np][1], bfr[2*np+1][0], bfr[2*np+1][1],
                   sb + AP_WP + r * 272 + kb2 * 32 + ((lane >> 3) & 1) * 16);
        }
#pragma unroll
        for (int mf = 0; mf < 2; mf++)
#pragma unroll
            for (int nf = 0; nf < 4; nf++)
                mma_fp16(pa[mf][nf], a[mf], bfr[nf]);
    }
    __syncthreads();   // proj reads done -> stg may overwrite wp region

    // epilogue: f2 = y2 + (pa + bias)*gamma ; write f2 + stage for LN2
    float* stg = (float*)(smem + AP_WP);   // 64 x 129 fp32
#pragma unroll
    for (int mf = 0; mf < 2; mf++)
#pragma unroll
        for (int nf = 0; nf < 4; nf++) {
            int col = wn3 + nf * 8 + t2 * 2;
            float e0 = pbias[col], e1 = pbias[col + 1];
            float f0 = gamma[col], f1 = gamma[col + 1];
#pragma unroll
            for (int h = 0; h < 2; h++) {
                int r = wm3 + mf * 16 + g + h * 8;
                float2 rs = *(const float2*)(y2f + (base + r) * 128 + col);
                float v0 = rs.x + (pa[mf][nf][h * 2]     + e0) * f0;
                float v1 = rs.y + (pa[mf][nf][h * 2 + 1] + e1) * f1;
                *(float2*)(f2out + (base + r) * 128 + col) = make_float2(v0, v1);
                stg[r * 129 + col]     = v0;
                stg[r * 129 + col + 1] = v1;
            }
        }
    __syncthreads();

    // LN2: 8 warps x 8 rows
#pragma unroll
    for (int rr = 0; rr < 8; rr++) {
        int r = wid * 8 + rr;
        float v[4];
        float s = 0.f;
#pragma unroll
        for (int i = 0; i < 4; i++) {
            v[i] = stg[r * 129 + lane + 32 * i];
            s += v[i];
        }
#pragma unroll
        for (int o = 16; o; o >>= 1) s += __shfl_xor_sync(~0u, s, o);
        float mu = s * (1.f / 128.f);
        float q = 0.f;
#pragma unroll
        for (int i = 0; i < 4; i++) { float d = v[i] - mu; q += d * d; }
#pragma unroll
        for (int o = 16; o; o >>= 1) q += __shfl_xor_sync(~0u, q, o);
        float rsd = rsqrtf(q * (1.f / 128.f) + 1e-5f);
#pragma unroll
        for (int i = 0; i < 4; i++) {
            int cc = lane + 32 * i;
            fnout[(base + r) * 128 + cc] =
                __float2half_rn((v[i] - mu) * rsd * lng[cc] + lnb[cc]);
        }
    }
}

// ---------------------------------------------------------------------------
extern "C" void kernel_launch(void* const* d_in, const int* in_sizes, int n_in,
                              void* d_out, int out_size) {
    const float* x      = (const float*)d_in[0];
    const float* cv1_w  = (const float*)d_in[1];
    const float* bn1_g  = (const float*)d_in[2];
    const float* bn1_b  = (const float*)d_in[3];
    const float* bn1_m  = (const float*)d_in[4];
    const float* bn1_v  = (const float*)d_in[5];
    const float* cv2_w  = (const float*)d_in[6];
    const float* bn2_g  = (const float*)d_in[7];
    const float* bn2_b  = (const float*)d_in[8];
    const float* bn2_m  = (const float*)d_in[9];
    const float* bn2_v  = (const float*)d_in[10];
    const float* ln1_g  = (const float*)d_in[11];
    const float* ln1_b  = (const float*)d_in[12];
    const float* qkv_w  = (const float*)d_in[13];
    const float* qkv_b  = (const float*)d_in[14];
    const float* proj_w = (const float*)d_in[15];
    const float* proj_b = (const float*)d_in[16];
    const float* gamma  = (const float*)d_in[17];
    const float* ln2_g  = (const float*)d_in[18];
    const float* ln2_b  = (const float*)d_in[19];
    const float* ffn_w1 = (const float*)d_in[20];
    const float* ffn_b1 = (const float*)d_in[21];
    const float* ffn_w2 = (const float*)d_in[22];
    const float* ffn_b2 = (const float*)d_in[23];
    float* out = (float*)d_out;

    __half *xt16, *cat16, *fn16, *qkv16, *attnp16, *w16;
    float *y2f, *f2;
    cudaGetSymbolAddress((void**)&xt16,    g_xt16);
    cudaGetSymbolAddress((void**)&cat16,   g_cat16);
    cudaGetSymbolAddress((void**)&y2f,     g_y2f);
    cudaGetSymbolAddress((void**)&fn16,    g_fn16);
    cudaGetSymbolAddress((void**)&qkv16,   g_qkv16);
    cudaGetSymbolAddress((void**)&attnp16, g_attnp16);
    cudaGetSymbolAddress((void**)&f2,      g_f2);
    cudaGetSymbolAddress((void**)&w16,     g_w16);

    __half* w_cv1  = w16;
    __half* w_qkv  = w_cv1 + 65536;
    __half* w_proj = w_qkv + 49152;
    __half* w_f1   = w_proj + 16384;
    __half* w_f2   = w_f1 + 32768;
    __half* w_cv2  = w_f2 + 32768;

    cudaFuncSetAttribute(gemm_cv1,    cudaFuncAttributeMaxDynamicSharedMemorySize, SM128_BYTES);
    cudaFuncSetAttribute(gemm64_nchw, cudaFuncAttributeMaxDynamicSharedMemorySize, SM64_BYTES);
    cudaFuncSetAttribute(ffn_fused,   cudaFuncAttributeMaxDynamicSharedMemorySize, FF_SMEM);
    cudaFuncSetAttribute(attn_pass0,  cudaFuncAttributeMaxDynamicSharedMemorySize, AT_SMEM0);
    cudaFuncSetAttribute(attn_proj_ln,cudaFuncAttributeMaxDynamicSharedMemorySize, AP_SMEM);

    // 0) weights -> fp16
    convert_w_all<<<dim3(192, 6), 256>>>(cv1_w, qkv_w, proj_w, ffn_w1, ffn_w2,
                                         cv2_w, w16);

    // 1) x NCHW -> xt16
    transpose_x_kernel<<<dim3(HW_/32, C1_/32, B_), dim3(32, 8)>>>(x, xt16);

    // 2) cv1 + BN + SiLU (+y2f) + fused LN1 + fused qkv
    gemm_cv1<<<dim3(TOKENS/128, 2), 256, SM128_BYTES>>>(
        xt16, 256, w_cv1, 256, cat16, bn1_g, bn1_b, bn1_m, bn1_v,
        ln1_g, ln1_b, w_qkv, qkv_b, qkv16);

    // 3) attention H pass -> fp16 partial
    attn_pass0<<<dim3(64, B_), 256, AT_SMEM0>>>(qkv16, attnp16);

    // 4) attention W pass + proj + residual*gamma + LN2 (writes f2, fn16)
    attn_proj_ln<<<dim3(64, B_), 256, AP_SMEM>>>(
        qkv16, attnp16, w_proj, proj_b, gamma, y2f, f2, ln2_g, ln2_b, fn16);

    // 5) fused ffn1(GELU)+ffn2 (+res f2) -> cat16[:,256:384]
    ffn_fused<<<TOKENS/64, 256, FF_SMEM>>>(
        fn16, w_f1, w_f2, ffn_b1, ffn_b2, f2, cat16);

    // 6) cv2 + BN + SiLU -> NCHW out
    gemm64_nchw<<<dim3(TOKENS/128, 4), 256, SM64_BYTES>>>(
        cat16, 384, w_cv2, 384, out, bn2_g, bn2_b, bn2_m, bn2_v);
}